// round 11
// baseline (speedup 1.0000x reference)
#include <cuda_runtime.h>
#include <cuda_bf16.h>
#include <math.h>
#include <stdint.h>

// ---------------------------------------------------------------------------
// Problem constants (CoconBlock: B=2, S=1024, Sc=256, D=768, H=12, dh=64)
// ---------------------------------------------------------------------------
constexpr int cD   = 768;
constexpr int cH   = 12;
constexpr int cDH  = 64;
constexpr int cB   = 2;
constexpr int cS   = 1024;
constexpr int cSC  = 256;
constexpr int cND  = cS + 1;          // 1025 queries per batch (sos + seq)
constexpr int cNS  = cSC + cND;       // 1281 keys per batch
constexpr int cM   = cB * cND;        // 2050 rows in main activation
constexpr int cMC  = cB * cSC;        // 512 context rows
constexpr int cBH  = cB * cH;         // 24 (batch, head) pairs
constexpr int cMPAD = 2176;           // 17 * 128 (padded row count for MMA tiles)

// attention padded dims
constexpr int NDP  = 1152;            // 9 * 128 padded queries
constexpr int NSP  = 1408;            // 11 * 128 padded keys
constexpr int K3Q  = 192;             // 3 * dh (split)
constexpr int K3AV = 3 * NSP;         // 4224 (split keys for AV)

// ---------------------------------------------------------------------------
// Scratch (static __device__ arrays, zero-initialized; padding regions are
// never written so they stay zero across graph replays)
// ---------------------------------------------------------------------------
__device__ float g_H  [(size_t)cM * cD];
__device__ float g_HL [(size_t)cM * cD];
__device__ float g_QKV[(size_t)cM * 3 * cD];
__device__ float g_CKV[(size_t)cMC * 2 * cD];
__device__ float g_A  [(size_t)cM * cD];
__device__ float g_H2 [(size_t)cM * cD];
__device__ float g_HL2[(size_t)cM * cD];
__device__ float g_FC [(size_t)cM * 4 * cD];
__device__ float g_Pp [3200000];                              // split-K partials
// bf16 split operands (reused per GEMM, sequential)
__device__ __nv_bfloat16 g_As[(size_t)cMPAD * 3 * 3072];     // A' [Mpad, 3K]
__device__ __nv_bfloat16 g_Bs[(size_t)3072 * 2304];          // B' [N, 3K]
// attention buffers
__device__ __nv_bfloat16 g_Qs [(size_t)cBH * NDP * K3Q];
__device__ __nv_bfloat16 g_Ks [(size_t)cBH * NSP * K3Q];
__device__ __nv_bfloat16 g_Vts[(size_t)cBH * cDH * K3AV];
__device__ float         g_Sp [(size_t)cBH * NDP * NSP];
__device__ __nv_bfloat16 g_Ps [(size_t)cBH * NDP * K3AV];

// ---------------------------------------------------------------------------
// Small helpers
// ---------------------------------------------------------------------------
__device__ __forceinline__ float gelu_new(float x) {
    float x3 = x * x * x;
    return 0.5f * x * (1.0f + tanhf(0.7978845608028654f * (x + 0.044715f * x3)));
}
__device__ __forceinline__ uint32_t smem_u32(const void* p) {
    uint32_t a;
    asm("{ .reg .u64 t; cvta.to.shared.u64 t, %1; cvt.u32.u64 %0, t; }" : "=r"(a) : "l"(p));
    return a;
}
__device__ __forceinline__ void cp16(uint32_t s, const void* g) {
    asm volatile("cp.async.cg.shared.global [%0], [%1], 16;\n"
                 :: "r"(s), "l"(__cvta_generic_to_global(g)) : "memory");
}
__device__ __forceinline__ void ldsm_x4(uint32_t& r0, uint32_t& r1, uint32_t& r2,
                                        uint32_t& r3, uint32_t addr) {
    asm volatile("ldmatrix.sync.aligned.m8n8.x4.shared.b16 {%0,%1,%2,%3}, [%4];"
                 : "=r"(r0), "=r"(r1), "=r"(r2), "=r"(r3) : "r"(addr));
}
__device__ __forceinline__ void mma16816(float* c, const uint32_t* a, const uint32_t* b) {
    asm volatile(
        "mma.sync.aligned.m16n8k16.row.col.f32.bf16.bf16.f32 "
        "{%0,%1,%2,%3}, {%4,%5,%6,%7}, {%8,%9}, {%0,%1,%2,%3};"
        : "+f"(c[0]), "+f"(c[1]), "+f"(c[2]), "+f"(c[3])
        : "r"(a[0]), "r"(a[1]), "r"(a[2]), "r"(a[3]), "r"(b[0]), "r"(b[1]));
}

// ---------------------------------------------------------------------------
// Split conversion kernels  (A'=[hi,lo,hi], B'=[hi,hi,lo] per k)
// ---------------------------------------------------------------------------
__global__ __launch_bounds__(256) void act_split(
    const float* __restrict__ X, __nv_bfloat16* __restrict__ Y, int MK, int K)
{
    int i4 = (blockIdx.x * 256 + threadIdx.x) * 4;
    if (i4 >= MK) return;
    int m = i4 / K, k = i4 % K;              // K % 4 == 0 -> same row
    float4 x = *(const float4*)(X + i4);
    __nv_bfloat16* Yo = Y + (size_t)m * (3 * K) + 3 * k;
    float xv[4] = {x.x, x.y, x.z, x.w};
    #pragma unroll
    for (int j = 0; j < 4; j++) {
        __nv_bfloat16 hi = __float2bfloat16(xv[j]);
        __nv_bfloat16 lo = __float2bfloat16(xv[j] - __bfloat162float(hi));
        Yo[3 * j] = hi; Yo[3 * j + 1] = lo; Yo[3 * j + 2] = hi;
    }
}

__global__ __launch_bounds__(256) void w_split(
    const float* __restrict__ W, __nv_bfloat16* __restrict__ Y, int K, int N)
{
    __shared__ float t[32][33];
    int k0 = blockIdx.y * 32, n0 = blockIdx.x * 32;
    int tid = threadIdx.x;
    #pragma unroll
    for (int p = 0; p < 4; p++) {
        int idx = p * 256 + tid;
        int kk = idx >> 5, nn = idx & 31;
        t[kk][nn] = W[(size_t)(k0 + kk) * N + n0 + nn];
    }
    __syncthreads();
    #pragma unroll
    for (int p = 0; p < 4; p++) {
        int idx = p * 256 + tid;
        int nn = idx >> 5, kk = idx & 31;
        float x = t[kk][nn];
        __nv_bfloat16 hi = __float2bfloat16(x);
        __nv_bfloat16 lo = __float2bfloat16(x - __bfloat162float(hi));
        size_t o = (size_t)(n0 + nn) * (3 * (size_t)K) + 3 * (size_t)(k0 + kk);
        Y[o] = hi; Y[o + 1] = hi; Y[o + 2] = lo;
    }
}

// ---------------------------------------------------------------------------
// HMMA GEMM: C[M,N] = A'[M,K3] x B'[N,K3]^T.  128x128 tile, 8 warps (2x4),
// BK=64, 3-stage cp.async ring with ONE __syncthreads per chunk.
// blockIdx.z splits K into gridDim.z sections (split-K).
// mode: 0 +bias, 1 +bias+gelu, 2 +bias+R, 3 +bias+R & drop-sos write,
//       4 raw partial -> C + z*M*N (no bias).
// ---------------------------------------------------------------------------
constexpr int TG_PITCH = 144;
constexpr int TG_STG   = 128 * TG_PITCH;            // 18432
constexpr int TG_SMEM  = 6 * TG_STG + 128;          // 3 stages A + 3 stages B

__global__ __launch_bounds__(256, 1) void tgemm(
    const __nv_bfloat16* __restrict__ A3, const __nv_bfloat16* __restrict__ B3,
    const float* __restrict__ bias, const float* __restrict__ R,
    float* __restrict__ C, int M, int N, int K3, int mode)
{
    extern __shared__ char dynraw[];
    char* sb = (char*)(((uintptr_t)dynraw + 127) & ~(uintptr_t)127);
    const uint32_t sA0 = smem_u32(sb);
    const uint32_t sB0 = sA0 + 3 * TG_STG;

    const int tid  = threadIdx.x;
    const int wid  = tid >> 5;
    const int lane = tid & 31;
    const int g    = lane >> 2;
    const int tg   = lane & 3;
    const int wm   = wid >> 2;
    const int wn   = wid & 3;
    const int row0 = blockIdx.y * 128;
    const int col0 = blockIdx.x * 128;
    const int zsec = K3 / gridDim.z;                 // per-split K length
    const int kbase = blockIdx.z * zsec;
    const int nch  = zsec >> 6;

    uint32_t soff[4];
    const __nv_bfloat16 *Ag[4], *Bg[4];
    #pragma unroll
    for (int p = 0; p < 4; p++) {
        int idx = p * 256 + tid;
        int row = idx >> 3, seg = idx & 7;
        soff[p] = (uint32_t)(row * TG_PITCH + seg * 16);
        Ag[p] = A3 + (size_t)(row0 + row) * K3 + kbase + seg * 8;
        Bg[p] = B3 + (size_t)(col0 + row) * K3 + kbase + seg * 8;
    }

    const uint32_t aoff  = (uint32_t)((wm * 64 + (lane & 15)) * TG_PITCH + (lane >> 4) * 16);
    const uint32_t boff4 = (uint32_t)((wn * 32 + (lane & 7)) * TG_PITCH + ((lane >> 3) & 3) * 16);

    float c[4][4][4];
    #pragma unroll
    for (int mi = 0; mi < 4; mi++)
        #pragma unroll
        for (int ni = 0; ni < 4; ni++)
            #pragma unroll
            for (int e = 0; e < 4; e++) c[mi][ni][e] = 0.f;

    // Prologue: stages 0,1
    const int pre = (nch < 2) ? nch : 2;
    for (int s = 0; s < pre; s++) {
        #pragma unroll
        for (int p = 0; p < 4; p++) {
            cp16(sA0 + s * TG_STG + soff[p], Ag[p] + s * 64);
            cp16(sB0 + s * TG_STG + soff[p], Bg[p] + s * 64);
        }
        asm volatile("cp.async.commit_group;" ::: "memory");
    }

    for (int i = 0; i < nch; i++) {
        if (i < nch - 1) asm volatile("cp.async.wait_group 1;" ::: "memory");
        else             asm volatile("cp.async.wait_group 0;" ::: "memory");
        __syncthreads();
        if (i + 2 < nch) {
            const int s2 = (i + 2) % 3;
            const int ko = (i + 2) * 64;
            #pragma unroll
            for (int p = 0; p < 4; p++) {
                cp16(sA0 + s2 * TG_STG + soff[p], Ag[p] + ko);
                cp16(sB0 + s2 * TG_STG + soff[p], Bg[p] + ko);
            }
            asm volatile("cp.async.commit_group;" ::: "memory");
        }
        const int s = i % 3;
        const uint32_t sa  = sA0 + s * TG_STG + aoff;
        const uint32_t sbb = sB0 + s * TG_STG + boff4;
        #pragma unroll
        for (int ks2 = 0; ks2 < 2; ks2++) {
            uint32_t b4[4][4];
            #pragma unroll
            for (int ni = 0; ni < 4; ni++)
                ldsm_x4(b4[ni][0], b4[ni][1], b4[ni][2], b4[ni][3],
                        sbb + (uint32_t)(ni * 8 * TG_PITCH + ks2 * 64));
            #pragma unroll
            for (int ko = 0; ko < 2; ko++) {
                const int ks = ks2 * 2 + ko;
                uint32_t a[4][4];
                #pragma unroll
                for (int mi = 0; mi < 4; mi++)
                    ldsm_x4(a[mi][0], a[mi][1], a[mi][2], a[mi][3],
                            sa + (uint32_t)(mi * 16 * TG_PITCH + ks * 32));
                #pragma unroll
                for (int mi = 0; mi < 4; mi++)
                    #pragma unroll
                    for (int ni = 0; ni < 4; ni++)
                        mma16816(c[mi][ni], a[mi], &b4[ni][ko * 2]);
            }
        }
    }

    #pragma unroll
    for (int mi = 0; mi < 4; mi++) {
        #pragma unroll
        for (int half = 0; half < 2; half++) {
            int rg = row0 + wm * 64 + mi * 16 + g + half * 8;
            if (rg >= M) continue;
            if (mode == 4) {
                float* crow = C + (size_t)blockIdx.z * M * N + (size_t)rg * N;
                #pragma unroll
                for (int ni = 0; ni < 4; ni++) {
                    int cg = col0 + wn * 32 + ni * 8 + 2 * tg;
                    *(float2*)(crow + cg) =
                        make_float2(c[mi][ni][half * 2 + 0], c[mi][ni][half * 2 + 1]);
                }
                continue;
            }
            float* crow;
            if (mode == 3) {
                int t = rg % cND;
                if (t == 0) continue;
                crow = C + ((size_t)((rg / cND) * cS + (t - 1))) * N;
            } else {
                crow = C + (size_t)rg * N;
            }
            #pragma unroll
            for (int ni = 0; ni < 4; ni++) {
                int cg = col0 + wn * 32 + ni * 8 + 2 * tg;
                float v0 = c[mi][ni][half * 2 + 0] + __ldg(&bias[cg]);
                float v1 = c[mi][ni][half * 2 + 1] + __ldg(&bias[cg + 1]);
                if (mode == 1) { v0 = gelu_new(v0); v1 = gelu_new(v1); }
                else if (mode >= 2) {
                    v0 += R[(size_t)rg * N + cg];
                    v1 += R[(size_t)rg * N + cg + 1];
                }
                *(float2*)(crow + cg) = make_float2(v0, v1);
            }
        }
    }
}

// ---------------------------------------------------------------------------
// combine: C = sum_s P[s] + bias (+R / gelu / sos-drop).  float4 vectorized.
// mode: 0 bias only, 1 +gelu, 2 +R, 3 +R & drop sos row.
// ---------------------------------------------------------------------------
__global__ __launch_bounds__(256) void combine(
    const float* __restrict__ P, const float* __restrict__ bias,
    const float* __restrict__ R, float* __restrict__ C,
    int M, int N, int nsplit, int mode)
{
    int i4 = (blockIdx.x * 256 + threadIdx.x) * 4;
    if (i4 >= M * N) return;
    int r = i4 / N, cc = i4 % N;
    float4 v = *(const float4*)(P + i4);
    for (int s = 1; s < nsplit; s++) {
        float4 u = *(const float4*)(P + (size_t)s * M * N + i4);
        v.x += u.x; v.y += u.y; v.z += u.z; v.w += u.w;
    }
    float4 bb = *(const float4*)(bias + cc);
    v.x += bb.x; v.y += bb.y; v.z += bb.z; v.w += bb.w;
    if (mode == 1) {
        v.x = gelu_new(v.x); v.y = gelu_new(v.y);
        v.z = gelu_new(v.z); v.w = gelu_new(v.w);
    } else if (mode >= 2) {
        float4 rr = *(const float4*)(R + i4);
        v.x += rr.x; v.y += rr.y; v.z += rr.z; v.w += rr.w;
    }
    if (mode == 3) {
        int t = r % cND;
        if (t == 0) return;
        *(float4*)(C + ((size_t)((r / cND) * cS + (t - 1))) * N + cc) = v;
    } else {
        *(float4*)(C + i4) = v;
    }
}

// ---------------------------------------------------------------------------
// scores_mma: S[bh, m, n] (padded NDP x NSP) = Qs x Ks^T, mask epilogue.
// 3-stage ring, nch = 3.
// ---------------------------------------------------------------------------
__global__ __launch_bounds__(256, 1) void scores_mma(
    const __nv_bfloat16* __restrict__ Qs, const __nv_bfloat16* __restrict__ Ks,
    float* __restrict__ S)
{
    extern __shared__ char dynraw[];
    char* sb = (char*)(((uintptr_t)dynraw + 127) & ~(uintptr_t)127);
    const uint32_t sA0 = smem_u32(sb);
    const uint32_t sB0 = sA0 + 3 * TG_STG;

    const int tid  = threadIdx.x;
    const int wid  = tid >> 5;
    const int lane = tid & 31;
    const int g    = lane >> 2;
    const int tg   = lane & 3;
    const int wm   = wid >> 2;
    const int wn   = wid & 3;
    const int bh   = blockIdx.z;
    const int row0 = blockIdx.y * 128;
    const int col0 = blockIdx.x * 128;

    const __nv_bfloat16* A3 = Qs + (size_t)bh * NDP * K3Q;
    const __nv_bfloat16* B3 = Ks + (size_t)bh * NSP * K3Q;

    uint32_t soff[4];
    const __nv_bfloat16 *Ag[4], *Bg[4];
    #pragma unroll
    for (int p = 0; p < 4; p++) {
        int idx = p * 256 + tid;
        int row = idx >> 3, seg = idx & 7;
        soff[p] = (uint32_t)(row * TG_PITCH + seg * 16);
        Ag[p] = A3 + (size_t)(row0 + row) * K3Q + seg * 8;
        Bg[p] = B3 + (size_t)(col0 + row) * K3Q + seg * 8;
    }
    const uint32_t aoff  = (uint32_t)((wm * 64 + (lane & 15)) * TG_PITCH + (lane >> 4) * 16);
    const uint32_t boff4 = (uint32_t)((wn * 32 + (lane & 7)) * TG_PITCH + ((lane >> 3) & 3) * 16);

    float c[4][4][4];
    #pragma unroll
    for (int mi = 0; mi < 4; mi++)
        #pragma unroll
        for (int ni = 0; ni < 4; ni++)
            #pragma unroll
            for (int e = 0; e < 4; e++) c[mi][ni][e] = 0.f;

    #pragma unroll
    for (int s = 0; s < 2; s++) {
        #pragma unroll
        for (int p = 0; p < 4; p++) {
            cp16(sA0 + s * TG_STG + soff[p], Ag[p] + s * 64);
            cp16(sB0 + s * TG_STG + soff[p], Bg[p] + s * 64);
        }
        asm volatile("cp.async.commit_group;" ::: "memory");
    }

    #pragma unroll
    for (int i = 0; i < 3; i++) {
        if (i < 2) asm volatile("cp.async.wait_group 1;" ::: "memory");
        else       asm volatile("cp.async.wait_group 0;" ::: "memory");
        __syncthreads();
        if (i == 0) {
            #pragma unroll
            for (int p = 0; p < 4; p++) {
                cp16(sA0 + 2 * TG_STG + soff[p], Ag[p] + 128);
                cp16(sB0 + 2 * TG_STG + soff[p], Bg[p] + 128);
            }
            asm volatile("cp.async.commit_group;" ::: "memory");
        }
        const uint32_t sa  = sA0 + i * TG_STG + aoff;
        const uint32_t sbb = sB0 + i * TG_STG + boff4;
        #pragma unroll
        for (int ks2 = 0; ks2 < 2; ks2++) {
            uint32_t b4[4][4];
            #pragma unroll
            for (int ni = 0; ni < 4; ni++)
                ldsm_x4(b4[ni][0], b4[ni][1], b4[ni][2], b4[ni][3],
                        sbb + (uint32_t)(ni * 8 * TG_PITCH + ks2 * 64));
            #pragma unroll
            for (int ko = 0; ko < 2; ko++) {
                const int ks = ks2 * 2 + ko;
                uint32_t a[4][4];
                #pragma unroll
                for (int mi = 0; mi < 4; mi++)
                    ldsm_x4(a[mi][0], a[mi][1], a[mi][2], a[mi][3],
                            sa + (uint32_t)(mi * 16 * TG_PITCH + ks * 32));
                #pragma unroll
                for (int mi = 0; mi < 4; mi++)
                    #pragma unroll
                    for (int ni = 0; ni < 4; ni++)
                        mma16816(c[mi][ni], a[mi], &b4[ni][ko * 2]);
            }
        }
    }

    float* Sb = S + (size_t)bh * NDP * NSP;
    const float scale = 0.125f;   // 1/sqrt(64)
    #pragma unroll
    for (int mi = 0; mi < 4; mi++) {
        #pragma unroll
        for (int half = 0; half < 2; half++) {
            int rg = row0 + wm * 64 + mi * 16 + g + half * 8;
            float* Sr = Sb + (size_t)rg * NSP;
            #pragma unroll
            for (int ni = 0; ni < 4; ni++) {
                int cg = col0 + wn * 32 + ni * 8 + 2 * tg;
                float v0 = (cg     <= rg + cSC) ? c[mi][ni][half * 2 + 0] * scale : -10000.0f;
                float v1 = (cg + 1 <= rg + cSC) ? c[mi][ni][half * 2 + 1] * scale : -10000.0f;
                *(float2*)(Sr + cg) = make_float2(v0, v1);
            }
        }
    }
}

// ---------------------------------------------------------------------------
// av_mma: A_merged = P' x Vt'^T.  128x64 tile, 8 warps 4x2, K3 = 4224,
// 3-stage ring, one sync per chunk.
// ---------------------------------------------------------------------------
constexpr int AV_BSTG = 64 * TG_PITCH;                       // 9216
constexpr int AV_SMEM = 3 * TG_STG + 3 * AV_BSTG + 128;

__global__ __launch_bounds__(256, 1) void av_mma(
    const __nv_bfloat16* __restrict__ P3, const __nv_bfloat16* __restrict__ V3,
    float* __restrict__ A)
{
    extern __shared__ char dynraw[];
    char* sb = (char*)(((uintptr_t)dynraw + 127) & ~(uintptr_t)127);
    const uint32_t sA0 = smem_u32(sb);
    const uint32_t sB0 = sA0 + 3 * TG_STG;

    const int tid  = threadIdx.x;
    const int wid  = tid >> 5;
    const int lane = tid & 31;
    const int g    = lane >> 2;
    const int tg   = lane & 3;
    const int wm   = wid >> 1;
    const int wn   = wid & 1;
    const int bh   = blockIdx.y;
    const int row0 = blockIdx.x * 128;

    const __nv_bfloat16* A3 = P3 + (size_t)bh * NDP * K3AV;
    const __nv_bfloat16* B3 = V3 + (size_t)bh * cDH * K3AV;

    uint32_t soffA[4];
    const __nv_bfloat16* Ag[4];
    #pragma unroll
    for (int p = 0; p < 4; p++) {
        int idx = p * 256 + tid;
        int row = idx >> 3, seg = idx & 7;
        soffA[p] = (uint32_t)(row * TG_PITCH + seg * 16);
        Ag[p] = A3 + (size_t)(row0 + row) * K3AV + seg * 8;
    }
    uint32_t soffB[2];
    const __nv_bfloat16* Bg[2];
    #pragma unroll
    for (int p = 0; p < 2; p++) {
        int idx = p * 256 + tid;
        int row = idx >> 3, seg = idx & 7;
        soffB[p] = (uint32_t)(row * TG_PITCH + seg * 16);
        Bg[p] = B3 + (size_t)row * K3AV + seg * 8;
    }

    const uint32_t aoff  = (uint32_t)((wm * 32 + (lane & 15)) * TG_PITCH + (lane >> 4) * 16);
    const uint32_t boff4 = (uint32_t)((wn * 32 + (lane & 7)) * TG_PITCH + ((lane >> 3) & 3) * 16);

    float c[2][4][4];
    #pragma unroll
    for (int mi = 0; mi < 2; mi++)
        #pragma unroll
        for (int ni = 0; ni < 4; ni++)
            #pragma unroll
            for (int e = 0; e < 4; e++) c[mi][ni][e] = 0.f;

    const int nch = K3AV >> 6;   // 66

    #pragma unroll
    for (int s = 0; s < 2; s++) {
        #pragma unroll
        for (int p = 0; p < 4; p++) cp16(sA0 + s * TG_STG + soffA[p], Ag[p] + s * 64);
        #pragma unroll
        for (int p = 0; p < 2; p++) cp16(sB0 + s * AV_BSTG + soffB[p], Bg[p] + s * 64);
        asm volatile("cp.async.commit_group;" ::: "memory");
    }

    for (int i = 0; i < nch; i++) {
        if (i < nch - 1) asm volatile("cp.async.wait_group 1;" ::: "memory");
        else             asm volatile("cp.async.wait_group 0;" ::: "memory");
        __syncthreads();
        if (i + 2 < nch) {
            const int s2 = (i + 2) % 3;
            const int ko = (i + 2) * 64;
            #pragma unroll
            for (int p = 0; p < 4; p++) cp16(sA0 + s2 * TG_STG + soffA[p], Ag[p] + ko);
            #pragma unroll
            for (int p = 0; p < 2; p++) cp16(sB0 + s2 * AV_BSTG + soffB[p], Bg[p] + ko);
            asm volatile("cp.async.commit_group;" ::: "memory");
        }
        const int s = i % 3;
        const uint32_t sa  = sA0 + s * TG_STG + aoff;
        const uint32_t sbb = sB0 + s * AV_BSTG + boff4;
        #pragma unroll
        for (int ks2 = 0; ks2 < 2; ks2++) {
            uint32_t b4[4][4];
            #pragma unroll
            for (int ni = 0; ni < 4; ni++)
                ldsm_x4(b4[ni][0], b4[ni][1], b4[ni][2], b4[ni][3],
                        sbb + (uint32_t)(ni * 8 * TG_PITCH + ks2 * 64));
            #pragma unroll
            for (int ko = 0; ko < 2; ko++) {
                const int ks = ks2 * 2 + ko;
                uint32_t a[2][4];
                #pragma unroll
                for (int mi = 0; mi < 2; mi++)
                    ldsm_x4(a[mi][0], a[mi][1], a[mi][2], a[mi][3],
                            sa + (uint32_t)(mi * 16 * TG_PITCH + ks * 32));
                #pragma unroll
                for (int mi = 0; mi < 2; mi++)
                    #pragma unroll
                    for (int ni = 0; ni < 4; ni++)
                        mma16816(c[mi][ni], a[mi], &b4[ni][ko * 2]);
            }
        }
    }

    const int b_ = bh / cH, h = bh % cH;
    #pragma unroll
    for (int mi = 0; mi < 2; mi++) {
        #pragma unroll
        for (int half = 0; half < 2; half++) {
            int rg = row0 + wm * 32 + mi * 16 + g + half * 8;
            if (rg >= cND) continue;
            float* Ar = A + ((size_t)(b_ * cND + rg)) * cD + h * cDH;
            #pragma unroll
            for (int ni = 0; ni < 4; ni++) {
                int cg = wn * 32 + ni * 8 + 2 * tg;
                *(float2*)(Ar + cg) =
                    make_float2(c[mi][ni][half * 2 + 0], c[mi][ni][half * 2 + 1]);
            }
        }
    }
}

// ---------------------------------------------------------------------------
// LayerNorm (optionally fused with sos-concat gather)
// ---------------------------------------------------------------------------
__global__ __launch_bounds__(256) void ln_kernel(
    const float* __restrict__ in, const float* __restrict__ sos,
    const float* __restrict__ gamma, const float* __restrict__ beta,
    float* __restrict__ Hout, float* __restrict__ HLout, int concat)
{
    int r   = blockIdx.x;
    int tid = threadIdx.x;
    const float* src;
    if (concat) {
        int b = r / cND, t = r % cND;
        src = (t == 0) ? sos : in + ((size_t)b * cS + (t - 1)) * cD;
    } else {
        src = in + (size_t)r * cD;
    }
    float v0 = src[tid], v1 = src[tid + 256], v2 = src[tid + 512];
    float s  = v0 + v1 + v2;
    float ss = v0 * v0 + v1 * v1 + v2 * v2;

    __shared__ float sb[8], sb2[8];
    #pragma unroll
    for (int o = 16; o; o >>= 1) {
        s  += __shfl_xor_sync(0xffffffffu, s,  o);
        ss += __shfl_xor_sync(0xffffffffu, ss, o);
    }
    int lane = tid & 31, w = tid >> 5;
    if (lane == 0) { sb[w] = s; sb2[w] = ss; }
    __syncthreads();
    if (tid == 0) {
        float a = 0.f, c = 0.f;
        #pragma unroll
        for (int i = 0; i < 8; i++) { a += sb[i]; c += sb2[i]; }
        sb[0] = a; sb2[0] = c;
    }
    __syncthreads();
    float mean = sb[0] * (1.0f / 768.0f);
    float var  = sb2[0] * (1.0f / 768.0f) - mean * mean;
    float inv  = rsqrtf(var + 1e-5f);

    if (concat) {
        float* hr = Hout + (size_t)r * cD;
        hr[tid] = v0; hr[tid + 256] = v1; hr[tid + 512] = v2;
    }
    float* hlr = HLout + (size_t)r * cD;
    hlr[tid      ] = (v0 - mean) * inv * gamma[tid      ] + beta[tid      ];
    hlr[tid + 256] = (v1 - mean) * inv * gamma[tid + 256] + beta[tid + 256];
    hlr[tid + 512] = (v2 - mean) * inv * gamma[tid + 512] + beta[tid + 512];
}

// ---------------------------------------------------------------------------
// Split gathers for attention
// ---------------------------------------------------------------------------
__global__ void gather_q_split(const float* __restrict__ QKV, __nv_bfloat16* __restrict__ Qs)
{
    int idx = blockIdx.x * blockDim.x + threadIdx.x;
    if (idx >= cBH * cND * cDH) return;
    int d    = idx & (cDH - 1);
    int rest = idx >> 6;
    int t    = rest % cND;
    int bh   = rest / cND;
    int b = bh / cH, h = bh % cH;
    float x = QKV[((size_t)(b * cND + t)) * (3 * cD) + h * cDH + d];
    __nv_bfloat16 hi = __float2bfloat16(x);
    __nv_bfloat16 lo = __float2bfloat16(x - __bfloat162float(hi));
    size_t o = ((size_t)bh * NDP + t) * K3Q + 3 * d;
    Qs[o] = hi; Qs[o + 1] = lo; Qs[o + 2] = hi;
}

__global__ void gather_k_split(const float* __restrict__ QKV, const float* __restrict__ CKV,
                               __nv_bfloat16* __restrict__ Ks)
{
    int idx = blockIdx.x * blockDim.x + threadIdx.x;
    if (idx >= cBH * cNS * cDH) return;
    int d    = idx & (cDH - 1);
    int rest = idx >> 6;
    int j    = rest % cNS;
    int bh   = rest / cNS;
    int b = bh / cH, h = bh % cH;
    float kv;
    if (j < cSC)
        kv = CKV[((size_t)(b * cSC + j)) * (2 * cD) + h * cDH + d];
    else
        kv = QKV[((size_t)(b * cND + (j - cSC))) * (3 * cD) + cD + h * cDH + d];
    __nv_bfloat16 hi = __float2bfloat16(kv);
    __nv_bfloat16 lo = __float2bfloat16(kv - __bfloat162float(hi));
    size_t o = ((size_t)bh * NSP + j) * K3Q + 3 * d;
    Ks[o] = hi; Ks[o + 1] = hi; Ks[o + 2] = lo;
}

__global__ void gather_vt_split(const float* __restrict__ QKV, const float* __restrict__ CKV,
                                __nv_bfloat16* __restrict__ Vts)
{
    int idx = blockIdx.x * blockDim.x + threadIdx.x;
    if (idx >= cBH * cDH * cNS) return;
    int j    = idx % cNS;
    int rest = idx / cNS;
    int d    = rest & (cDH - 1);
    int bh   = rest >> 6;
    int b = bh / cH, h = bh % cH;
    float vv;
    if (j < cSC)
        vv = CKV[((size_t)(b * cSC + j)) * (2 * cD) + cD + h * cDH + d];
    else
        vv = QKV[((size_t)(b * cND + (j - cSC))) * (3 * cD) + 2 * cD + h * cDH + d];
    __nv_bfloat16 hi = __float2bfloat16(vv);
    __nv_bfloat16 lo = __float2bfloat16(vv - __bfloat162float(hi));
    size_t o = ((size_t)bh * cDH + d) * K3AV + 3 * j;
    Vts[o] = hi; Vts[o + 1] = hi; Vts[o + 2] = lo;
}

// ---------------------------------------------------------------------------
// Softmax over padded rows; writes split-bf16 probs [hi,lo,hi] + zero padding
// ---------------------------------------------------------------------------
__global__ __launch_bounds__(256) void softmax_split(
    const float* __restrict__ S, __nv_bfloat16* __restrict__ Ps)
{
    int r  = blockIdx.x;
    int bh = r / cND, m = r % cND;
    const float* p = S + ((size_t)bh * NDP + m) * NSP;
    __nv_bfloat16* out = Ps + ((size_t)bh * NDP + m) * K3AV;
    int tid = threadIdx.x;

    float vals[6];
    float mx = -3.4e38f;
    #pragma unroll
    for (int it = 0; it < 6; it++) {
        int i = tid + it * 256;
        float v = (i < cNS) ? p[i] : -3.4e38f;
        vals[it] = v;
        mx = fmaxf(mx, v);
    }
    __shared__ float sb[8];
    #pragma unroll
    for (int o = 16; o; o >>= 1) mx = fmaxf(mx, __shfl_xor_sync(0xffffffffu, mx, o));
    if ((tid & 31) == 0) sb[tid >> 5] = mx;
    __syncthreads();
    if (tid < 32) {
        float m2 = (tid < 8) ? sb[tid] : -3.4e38f;
        #pragma unroll
        for (int o = 4; o; o >>= 1) m2 = fmaxf(m2, __shfl_xor_sync(0xffffffffu, m2, o));
        if (tid == 0) sb[0] = m2;
    }
    __syncthreads();
    float bmax = sb[0];
    __syncthreads();

    float s = 0.f;
    #pragma unroll
    for (int it = 0; it < 6; it++) {
        int i = tid + it * 256;
        if (i < cNS) {
            float e = __expf(vals[it] - bmax);
            vals[it] = e;
            s += e;
        }
    }
    #pragma unroll
    for (int o = 16; o; o >>= 1) s += __shfl_xor_sync(0xffffffffu, s, o);
    if ((tid & 31) == 0) sb[tid >> 5] = s;
    __syncthreads();
    if (tid < 32) {
        float s2 = (tid < 8) ? sb[tid] : 0.f;
        #pragma unroll
        for (int o = 4; o; o >>= 1) s2 += __shfl_xor_sync(0xffffffffu, s2, o);
        if (tid == 0) sb[0] = s2;
    }
    __syncthreads();
    float inv = 1.0f / sb[0];
    #pragma unroll
    for (int it = 0; it < 6; it++) {
        int i = tid + it * 256;
        if (i >= NSP) continue;
        float v = (i < cNS) ? vals[it] * inv : 0.f;
        __nv_bfloat16 hi = __float2bfloat16(v);
        __nv_bfloat16 lo = __float2bfloat16(v - __bfloat162float(hi));
        out[3 * i] = hi; out[3 * i + 1] = lo; out[3 * i + 2] = hi;
    }
}

// ---------------------------------------------------------------------------
// Launch sequence
// ---------------------------------------------------------------------------
extern "C" void kernel_launch(void* const* d_in, const int* in_sizes, int n_in,
                              void* d_out, int out_size)
{
    (void)in_sizes; (void)n_in; (void)out_size;
    const float* x       = (const float*)d_in[0];
    const float* ctx     = (const float*)d_in[1];
    const float* sos     = (const float*)d_in[2];
    const float* ln1_g   = (const float*)d_in[3];
    const float* ln1_b   = (const float*)d_in[4];
    const float* W_attn  = (const float*)d_in[5];
    const float* b_attn  = (const float*)d_in[6];
    const float* W_ref   = (const float*)d_in[7];
    const float* b_ref   = (const float*)d_in[8];
    const float* W_proj  = (const float*)d_in[9];
    const float* b_proj  = (const float*)d_in[10];
    const float* ln2_g   = (const float*)d_in[11];
    const float* ln2_b   = (const float*)d_in[12];
    const float* W_fc    = (const float*)d_in[13];
    const float* b_fc    = (const float*)d_in[14];
    const float* W_mproj = (const float*)d_in[15];
    const float* b_mproj = (const float*)d_in[16];
    float* out = (float*)d_out;

    float *H, *HL, *QKV, *CKV, *A, *H2, *HL2, *FC, *Sp, *Pp;
    __nv_bfloat16 *As, *Bs, *Qs, *Ks, *Vts, *Ps;
    cudaGetSymbolAddress((void**)&H,   g_H);
    cudaGetSymbolAddress((void**)&HL,  g_HL);
    cudaGetSymbolAddress((void**)&QKV, g_QKV);
    cudaGetSymbolAddress((void**)&CKV, g_CKV);
    cudaGetSymbolAddress((void**)&A,   g_A);
    cudaGetSymbolAddress((void**)&H2,  g_H2);
    cudaGetSymbolAddress((void**)&HL2, g_HL2);
    cudaGetSymbolAddress((void**)&FC,  g_FC);
    cudaGetSymbolAddress((void**)&Sp,  g_Sp);
    cudaGetSymbolAddress((void**)&Pp,  g_Pp);
    cudaGetSymbolAddress((void**)&As,  g_As);
    cudaGetSymbolAddress((void**)&Bs,  g_Bs);
    cudaGetSymbolAddress((void**)&Qs,  g_Qs);
    cudaGetSymbolAddress((void**)&Ks,  g_Ks);
    cudaGetSymbolAddress((void**)&Vts, g_Vts);
    cudaGetSymbolAddress((void**)&Ps,  g_Ps);

    cudaFuncSetAttribute(tgemm,      cudaFuncAttributeMaxDynamicSharedMemorySize, TG_SMEM);
    cudaFuncSetAttribute(scores_mma, cudaFuncAttributeMaxDynamicSharedMemorySize, TG_SMEM);
    cudaFuncSetAttribute(av_mma,     cudaFuncAttributeMaxDynamicSharedMemorySize, AV_SMEM);

    // 1. concat(sos, x) + LN1
    ln_kernel<<<cM, 256>>>(x, sos, ln1_g, ln1_b, H, HL, 1);

    // 2. qkv = ln1(h) @ W_attn + b_attn   (306 CTAs, no split)
    act_split<<<(cM * cD / 4 + 255) / 256, 256>>>(HL, As, cM * cD, cD);
    w_split<<<dim3(3 * cD / 32, cD / 32), 256>>>(W_attn, Bs, cD, 3 * cD);
    tgemm<<<dim3(3 * cD / 128, 17, 1), 256, TG_SMEM>>>(As, Bs, b_attn, nullptr, QKV,
                                                       cM, 3 * cD, 3 * cD, 0);

    // 3. ckv = context @ W_ref + b_ref    (split-K x3: 144 CTAs)
    act_split<<<(cMC * cD / 4 + 255) / 256, 256>>>(ctx, As, cMC * cD, cD);
    w_split<<<dim3(2 * cD / 32, cD / 32), 256>>>(W_ref, Bs, cD, 2 * cD);
    tgemm<<<dim3(2 * cD / 128, 4, 3), 256, TG_SMEM>>>(As, Bs, b_ref, nullptr, Pp,
                                                      cMC, 2 * cD, 3 * cD, 4);
    combine<<<(cMC * 2 * cD / 4 + 255) / 256, 256>>>(Pp, b_ref, nullptr, CKV,
                                                     cMC, 2 * cD, 3, 0);

    // 4. split gathers for attention
    gather_q_split<<<(cBH * cND * cDH + 255) / 256, 256>>>(QKV, Qs);
    gather_k_split<<<(cBH * cNS * cDH + 255) / 256, 256>>>(QKV, CKV, Ks);
    gather_vt_split<<<(cBH * cDH * cNS + 255) / 256, 256>>>(QKV, CKV, Vts);

    // 5. attention on tensor pipe
    scores_mma<<<dim3(NSP / 128, NDP / 128, cBH), 256, TG_SMEM>>>(Qs, Ks, Sp);
    softmax_split<<<cBH * cND, 256>>>(Sp, Ps);
    av_mma<<<dim3(NDP / 128, cBH), 256, AV_SMEM>>>(Ps, Vts, A);

    // 6. h2 = h + attn @ W_proj + b_proj  (split-K x2: 204 CTAs)
    act_split<<<(cM * cD / 4 + 255) / 256, 256>>>(A, As, cM * cD, cD);
    w_split<<<dim3(cD / 32, cD / 32), 256>>>(W_proj, Bs, cD, cD);
    tgemm<<<dim3(cD / 128, 17, 2), 256, TG_SMEM>>>(As, Bs, b_proj, nullptr, Pp,
                                                   cM, cD, 3 * cD, 4);
    combine<<<(cM * cD / 4 + 255) / 256, 256>>>(Pp, b_proj, H, H2, cM, cD, 2, 2);

    // 7. LN2
    ln_kernel<<<cM, 256>>>(H2, nullptr, ln2_g, ln2_b, nullptr, HL2, 0);

    // 8. fc = gelu(ln2(h2) @ W_fc + b_fc) (408 CTAs, no split)
    act_split<<<(cM * cD / 4 + 255) / 256, 256>>>(HL2, As, cM * cD, cD);
    w_split<<<dim3(4 * cD / 32, cD / 32), 256>>>(W_fc, Bs, cD, 4 * cD);
    tgemm<<<dim3(4 * cD / 128, 17, 1), 256, TG_SMEM>>>(As, Bs, b_fc, nullptr, FC,
                                                       cM, 4 * cD, 3 * cD, 1);

    // 9. out = (h2 + fc @ W_mproj + b_mproj)[:, 1:, :]  (split-K x2: 204 CTAs)
    act_split<<<(cM * 4 * cD / 4 + 255) / 256, 256>>>(FC, As, cM * 4 * cD, 4 * cD);
    w_split<<<dim3(cD / 32, 4 * cD / 32), 256>>>(W_mproj, Bs, 4 * cD, cD);
    tgemm<<<dim3(cD / 128, 17, 2), 256, TG_SMEM>>>(As, Bs, b_mproj, nullptr, Pp,
                                                   cM, cD, 12 * cD, 4);
    combine<<<(cM * cD / 4 + 255) / 256, 256>>>(Pp, b_mproj, H2, out, cM, cD, 2, 3);
}

// round 12
// speedup vs baseline: 1.1183x; 1.1183x over previous
#include <cuda_runtime.h>
#include <cuda_bf16.h>
#include <math.h>
#include <stdint.h>

// ---------------------------------------------------------------------------
// Problem constants (CoconBlock: B=2, S=1024, Sc=256, D=768, H=12, dh=64)
// ---------------------------------------------------------------------------
constexpr int cD   = 768;
constexpr int cH   = 12;
constexpr int cDH  = 64;
constexpr int cB   = 2;
constexpr int cS   = 1024;
constexpr int cSC  = 256;
constexpr int cND  = cS + 1;          // 1025 queries per batch (sos + seq)
constexpr int cNS  = cSC + cND;       // 1281 keys per batch
constexpr int cM   = cB * cND;        // 2050 rows in main activation
constexpr int cMC  = cB * cSC;        // 512 context rows
constexpr int cBH  = cB * cH;         // 24 (batch, head) pairs
constexpr int cMPAD = 2176;           // 17 * 128

// attention padded dims
constexpr int NDP  = 1152;            // 9 * 128 padded queries
constexpr int NSP  = 1408;            // 11 * 128 padded keys
constexpr int K3Q  = 192;             // 3 * dh (split)
constexpr int K3AV = 3 * NSP;         // 4224

// ---------------------------------------------------------------------------
// Scratch (static __device__ arrays, zero-initialized; padding regions are
// never written so they stay zero across graph replays)
// ---------------------------------------------------------------------------
__device__ float g_H  [(size_t)cM * cD];
__device__ float g_HL [(size_t)cM * cD];
__device__ float g_QKV[(size_t)cM * 3 * cD];
__device__ float g_CKV[(size_t)cMC * 2 * cD];
__device__ float g_A  [(size_t)cM * cD];
__device__ float g_H2 [(size_t)cM * cD];
__device__ float g_HL2[(size_t)cM * cD];
__device__ float g_FC [(size_t)cM * 4 * cD];
__device__ float g_Pp [3400000];                              // split-K partials
__device__ __nv_bfloat16 g_As[(size_t)cMPAD * 3 * 3072];
__device__ __nv_bfloat16 g_Bs[(size_t)3072 * 2304];
__device__ __nv_bfloat16 g_Qs [(size_t)cBH * NDP * K3Q];
__device__ __nv_bfloat16 g_Ks [(size_t)cBH * NSP * K3Q];
__device__ __nv_bfloat16 g_Vts[(size_t)cBH * cDH * K3AV];
__device__ float         g_Sp [(size_t)cBH * NDP * NSP];
__device__ __nv_bfloat16 g_Ps [(size_t)cBH * NDP * K3AV];

// ---------------------------------------------------------------------------
// Small helpers
// ---------------------------------------------------------------------------
__device__ __forceinline__ float gelu_new(float x) {
    float x3 = x * x * x;
    return 0.5f * x * (1.0f + tanhf(0.7978845608028654f * (x + 0.044715f * x3)));
}
__device__ __forceinline__ uint32_t smem_u32(const void* p) {
    uint32_t a;
    asm("{ .reg .u64 t; cvta.to.shared.u64 t, %1; cvt.u32.u64 %0, t; }" : "=r"(a) : "l"(p));
    return a;
}
__device__ __forceinline__ void cp16(uint32_t s, const void* g) {
    asm volatile("cp.async.cg.shared.global [%0], [%1], 16;\n"
                 :: "r"(s), "l"(__cvta_generic_to_global(g)) : "memory");
}
__device__ __forceinline__ void ldsm_x4(uint32_t& r0, uint32_t& r1, uint32_t& r2,
                                        uint32_t& r3, uint32_t addr) {
    asm volatile("ldmatrix.sync.aligned.m8n8.x4.shared.b16 {%0,%1,%2,%3}, [%4];"
                 : "=r"(r0), "=r"(r1), "=r"(r2), "=r"(r3) : "r"(addr));
}
__device__ __forceinline__ void ldsm_x2(uint32_t& r0, uint32_t& r1, uint32_t addr) {
    asm volatile("ldmatrix.sync.aligned.m8n8.x2.shared.b16 {%0,%1}, [%2];"
                 : "=r"(r0), "=r"(r1) : "r"(addr));
}
__device__ __forceinline__ void mma16816(float* c, const uint32_t* a, const uint32_t* b) {
    asm volatile(
        "mma.sync.aligned.m16n8k16.row.col.f32.bf16.bf16.f32 "
        "{%0,%1,%2,%3}, {%4,%5,%6,%7}, {%8,%9}, {%0,%1,%2,%3};"
        : "+f"(c[0]), "+f"(c[1]), "+f"(c[2]), "+f"(c[3])
        : "r"(a[0]), "r"(a[1]), "r"(a[2]), "r"(a[3]), "r"(b[0]), "r"(b[1]));
}

// ---------------------------------------------------------------------------
// Split conversion kernels  (A'=[hi,lo,hi], B'=[hi,hi,lo] per k)
// ---------------------------------------------------------------------------
__global__ __launch_bounds__(256) void act_split(
    const float* __restrict__ X, __nv_bfloat16* __restrict__ Y, int MK, int K)
{
    int i4 = (blockIdx.x * 256 + threadIdx.x) * 4;
    if (i4 >= MK) return;
    int m = i4 / K, k = i4 % K;              // K % 4 == 0 -> same row
    float4 x = *(const float4*)(X + i4);
    __nv_bfloat16* Yo = Y + (size_t)m * (3 * K) + 3 * k;
    float xv[4] = {x.x, x.y, x.z, x.w};
    #pragma unroll
    for (int j = 0; j < 4; j++) {
        __nv_bfloat16 hi = __float2bfloat16(xv[j]);
        __nv_bfloat16 lo = __float2bfloat16(xv[j] - __bfloat162float(hi));
        Yo[3 * j] = hi; Yo[3 * j + 1] = lo; Yo[3 * j + 2] = hi;
    }
}

__global__ __launch_bounds__(256) void w_split(
    const float* __restrict__ W, __nv_bfloat16* __restrict__ Y, int K, int N)
{
    __shared__ float t[32][33];
    int k0 = blockIdx.y * 32, n0 = blockIdx.x * 32;
    int tid = threadIdx.x;
    #pragma unroll
    for (int p = 0; p < 4; p++) {
        int idx = p * 256 + tid;
        int kk = idx >> 5, nn = idx & 31;
        t[kk][nn] = W[(size_t)(k0 + kk) * N + n0 + nn];
    }
    __syncthreads();
    #pragma unroll
    for (int p = 0; p < 4; p++) {
        int idx = p * 256 + tid;
        int nn = idx >> 5, kk = idx & 31;
        float x = t[kk][nn];
        __nv_bfloat16 hi = __float2bfloat16(x);
        __nv_bfloat16 lo = __float2bfloat16(x - __bfloat162float(hi));
        size_t o = (size_t)(n0 + nn) * (3 * (size_t)K) + 3 * (size_t)(k0 + kk);
        Y[o] = hi; Y[o + 1] = hi; Y[o + 2] = lo;
    }
}

// ---------------------------------------------------------------------------
// HMMA GEMM (ROUND-10 mainloop: double-buffered, 2 syncs, regs<=128, occ 2).
// blockIdx.z = split-K section (uniform pointer offset only).
// mode: 0 +bias, 1 +bias+gelu, 2 +bias+R, 3 +bias+R & drop-sos,
//       4 raw partial -> C + z*M*N.
// ---------------------------------------------------------------------------
constexpr int TG_PITCH = 144;
constexpr int TG_STG   = 128 * TG_PITCH;      // 18432
constexpr int TG_SMEM  = 4 * TG_STG + 128;

__global__ __launch_bounds__(256, 2) void tgemm(
    const __nv_bfloat16* __restrict__ A3, const __nv_bfloat16* __restrict__ B3,
    const float* __restrict__ bias, const float* __restrict__ R,
    float* __restrict__ C, int M, int N, int K3, int mode)
{
    extern __shared__ char dynraw[];
    char* sb = (char*)(((uintptr_t)dynraw + 127) & ~(uintptr_t)127);
    const uint32_t sA0 = smem_u32(sb);
    const uint32_t sB0 = sA0 + 2 * TG_STG;

    const int tid  = threadIdx.x;
    const int wid  = tid >> 5;
    const int lane = tid & 31;
    const int g    = lane >> 2;
    const int tg   = lane & 3;
    const int wm   = wid >> 2;
    const int wn   = wid & 3;
    const int row0 = blockIdx.y * 128;
    const int col0 = blockIdx.x * 128;
    const int zsec = K3 / gridDim.z;
    const int kbase = blockIdx.z * zsec;
    const int nch  = zsec >> 6;

    uint32_t soff[4];
    const __nv_bfloat16 *Ag[4], *Bg[4];
    #pragma unroll
    for (int p = 0; p < 4; p++) {
        int idx = p * 256 + tid;
        int row = idx >> 3, seg = idx & 7;
        soff[p] = (uint32_t)(row * TG_PITCH + seg * 16);
        Ag[p] = A3 + (size_t)(row0 + row) * K3 + kbase + seg * 8;
        Bg[p] = B3 + (size_t)(col0 + row) * K3 + kbase + seg * 8;
    }

    const uint32_t aoff = (uint32_t)((wm * 64 + (lane & 15)) * TG_PITCH + (lane >> 4) * 16);
    const uint32_t boff = (uint32_t)((wn * 32 + (lane & 7)) * TG_PITCH + ((lane >> 3) & 1) * 16);

    float c[4][4][4];
    #pragma unroll
    for (int mi = 0; mi < 4; mi++)
        #pragma unroll
        for (int ni = 0; ni < 4; ni++)
            #pragma unroll
            for (int e = 0; e < 4; e++) c[mi][ni][e] = 0.f;

    #pragma unroll
    for (int p = 0; p < 4; p++) {
        cp16(sA0 + soff[p], Ag[p]);
        cp16(sB0 + soff[p], Bg[p]);
    }
    asm volatile("cp.async.commit_group;" ::: "memory");

    for (int i = 0; i < nch; i++) {
        const int st = i & 1;
        if (i + 1 < nch) {
            const int st2 = (i + 1) & 1;
            const int ko = (i + 1) * 64;
            #pragma unroll
            for (int p = 0; p < 4; p++) {
                cp16(sA0 + st2 * TG_STG + soff[p], Ag[p] + ko);
                cp16(sB0 + st2 * TG_STG + soff[p], Bg[p] + ko);
            }
            asm volatile("cp.async.commit_group;" ::: "memory");
            asm volatile("cp.async.wait_group 1;" ::: "memory");
        } else {
            asm volatile("cp.async.wait_group 0;" ::: "memory");
        }
        __syncthreads();

        const uint32_t sa = sA0 + st * TG_STG + aoff;
        const uint32_t sbb = sB0 + st * TG_STG + boff;
        #pragma unroll
        for (int ks = 0; ks < 4; ks++) {
            uint32_t a[4][4], b[4][2];
            #pragma unroll
            for (int mi = 0; mi < 4; mi++)
                ldsm_x4(a[mi][0], a[mi][1], a[mi][2], a[mi][3],
                        sa + (uint32_t)(mi * 16 * TG_PITCH + ks * 32));
            #pragma unroll
            for (int ni = 0; ni < 4; ni++)
                ldsm_x2(b[ni][0], b[ni][1],
                        sbb + (uint32_t)(ni * 8 * TG_PITCH + ks * 32));
            #pragma unroll
            for (int mi = 0; mi < 4; mi++)
                #pragma unroll
                for (int ni = 0; ni < 4; ni++)
                    mma16816(c[mi][ni], a[mi], b[ni]);
        }
        __syncthreads();
    }

    #pragma unroll
    for (int mi = 0; mi < 4; mi++) {
        #pragma unroll
        for (int half = 0; half < 2; half++) {
            int rg = row0 + wm * 64 + mi * 16 + g + half * 8;
            if (rg >= M) continue;
            if (mode == 4) {
                float* crow = C + (size_t)blockIdx.z * M * N + (size_t)rg * N;
                #pragma unroll
                for (int ni = 0; ni < 4; ni++) {
                    int cg = col0 + wn * 32 + ni * 8 + 2 * tg;
                    *(float2*)(crow + cg) =
                        make_float2(c[mi][ni][half * 2 + 0], c[mi][ni][half * 2 + 1]);
                }
                continue;
            }
            float* crow;
            if (mode == 3) {
                int t = rg % cND;
                if (t == 0) continue;
                crow = C + ((size_t)((rg / cND) * cS + (t - 1))) * N;
            } else {
                crow = C + (size_t)rg * N;
            }
            #pragma unroll
            for (int ni = 0; ni < 4; ni++) {
                int cg = col0 + wn * 32 + ni * 8 + 2 * tg;
                float v0 = c[mi][ni][half * 2 + 0] + __ldg(&bias[cg]);
                float v1 = c[mi][ni][half * 2 + 1] + __ldg(&bias[cg + 1]);
                if (mode == 1) { v0 = gelu_new(v0); v1 = gelu_new(v1); }
                else if (mode >= 2) {
                    v0 += R[(size_t)rg * N + cg];
                    v1 += R[(size_t)rg * N + cg + 1];
                }
                *(float2*)(crow + cg) = make_float2(v0, v1);
            }
        }
    }
}

// ---------------------------------------------------------------------------
// combine: C = sum_s P[s] + bias (+R / gelu / sos-drop).  float4 vectorized.
// mode: 0 bias only, 1 +gelu, 2 +R, 3 +R & drop sos row.
// ---------------------------------------------------------------------------
__global__ __launch_bounds__(256) void combine(
    const float* __restrict__ P, const float* __restrict__ bias,
    const float* __restrict__ R, float* __restrict__ C,
    int M, int N, int nsplit, int mode)
{
    int i4 = (blockIdx.x * 256 + threadIdx.x) * 4;
    if (i4 >= M * N) return;
    int r = i4 / N, cc = i4 % N;
    float4 v = *(const float4*)(P + i4);
    for (int s = 1; s < nsplit; s++) {
        float4 u = *(const float4*)(P + (size_t)s * M * N + i4);
        v.x += u.x; v.y += u.y; v.z += u.z; v.w += u.w;
    }
    float4 bb = *(const float4*)(bias + cc);
    v.x += bb.x; v.y += bb.y; v.z += bb.z; v.w += bb.w;
    if (mode == 1) {
        v.x = gelu_new(v.x); v.y = gelu_new(v.y);
        v.z = gelu_new(v.z); v.w = gelu_new(v.w);
    } else if (mode >= 2) {
        float4 rr = *(const float4*)(R + i4);
        v.x += rr.x; v.y += rr.y; v.z += rr.z; v.w += rr.w;
    }
    if (mode == 3) {
        int t = r % cND;
        if (t == 0) return;
        *(float4*)(C + ((size_t)((r / cND) * cS + (t - 1))) * N + cc) = v;
    } else {
        *(float4*)(C + i4) = v;
    }
}

// ---------------------------------------------------------------------------
// scores_mma (ROUND-10 mainloop) + early-exit for fully masked tiles.
// ---------------------------------------------------------------------------
__global__ __launch_bounds__(256, 2) void scores_mma(
    const __nv_bfloat16* __restrict__ Qs, const __nv_bfloat16* __restrict__ Ks,
    float* __restrict__ S)
{
    extern __shared__ char dynraw[];
    char* sb = (char*)(((uintptr_t)dynraw + 127) & ~(uintptr_t)127);
    const uint32_t sA0 = smem_u32(sb);
    const uint32_t sB0 = sA0 + 2 * TG_STG;

    const int tid  = threadIdx.x;
    const int wid  = tid >> 5;
    const int lane = tid & 31;
    const int g    = lane >> 2;
    const int tg   = lane & 3;
    const int wm   = wid >> 2;
    const int wn   = wid & 3;
    const int bh   = blockIdx.z;
    const int row0 = blockIdx.y * 128;
    const int col0 = blockIdx.x * 128;

    float* Sb = S + (size_t)bh * NDP * NSP;

    // Fully-masked tile: min col > max row + Sc  ->  write -1e4, skip GEMM.
    if (col0 >= row0 + 128 + cSC) {
        #pragma unroll
        for (int mi = 0; mi < 4; mi++)
            #pragma unroll
            for (int half = 0; half < 2; half++) {
                int rg = row0 + wm * 64 + mi * 16 + g + half * 8;
                float* Sr = Sb + (size_t)rg * NSP;
                #pragma unroll
                for (int ni = 0; ni < 4; ni++) {
                    int cg = col0 + wn * 32 + ni * 8 + 2 * tg;
                    *(float2*)(Sr + cg) = make_float2(-10000.0f, -10000.0f);
                }
            }
        return;
    }

    const __nv_bfloat16* A3 = Qs + (size_t)bh * NDP * K3Q;
    const __nv_bfloat16* B3 = Ks + (size_t)bh * NSP * K3Q;

    uint32_t soff[4];
    const __nv_bfloat16 *Ag[4], *Bg[4];
    #pragma unroll
    for (int p = 0; p < 4; p++) {
        int idx = p * 256 + tid;
        int row = idx >> 3, seg = idx & 7;
        soff[p] = (uint32_t)(row * TG_PITCH + seg * 16);
        Ag[p] = A3 + (size_t)(row0 + row) * K3Q + seg * 8;
        Bg[p] = B3 + (size_t)(col0 + row) * K3Q + seg * 8;
    }
    const uint32_t aoff = (uint32_t)((wm * 64 + (lane & 15)) * TG_PITCH + (lane >> 4) * 16);
    const uint32_t boff = (uint32_t)((wn * 32 + (lane & 7)) * TG_PITCH + ((lane >> 3) & 1) * 16);

    float c[4][4][4];
    #pragma unroll
    for (int mi = 0; mi < 4; mi++)
        #pragma unroll
        for (int ni = 0; ni < 4; ni++)
            #pragma unroll
            for (int e = 0; e < 4; e++) c[mi][ni][e] = 0.f;

    #pragma unroll
    for (int p = 0; p < 4; p++) {
        cp16(sA0 + soff[p], Ag[p]);
        cp16(sB0 + soff[p], Bg[p]);
    }
    asm volatile("cp.async.commit_group;" ::: "memory");

    #pragma unroll
    for (int i = 0; i < 3; i++) {
        const int st = i & 1;
        if (i + 1 < 3) {
            const int st2 = (i + 1) & 1;
            const int ko = (i + 1) * 64;
            #pragma unroll
            for (int p = 0; p < 4; p++) {
                cp16(sA0 + st2 * TG_STG + soff[p], Ag[p] + ko);
                cp16(sB0 + st2 * TG_STG + soff[p], Bg[p] + ko);
            }
            asm volatile("cp.async.commit_group;" ::: "memory");
            asm volatile("cp.async.wait_group 1;" ::: "memory");
        } else {
            asm volatile("cp.async.wait_group 0;" ::: "memory");
        }
        __syncthreads();
        const uint32_t sa = sA0 + st * TG_STG + aoff;
        const uint32_t sbb = sB0 + st * TG_STG + boff;
        #pragma unroll
        for (int ks = 0; ks < 4; ks++) {
            uint32_t a[4][4], b[4][2];
            #pragma unroll
            for (int mi = 0; mi < 4; mi++)
                ldsm_x4(a[mi][0], a[mi][1], a[mi][2], a[mi][3],
                        sa + (uint32_t)(mi * 16 * TG_PITCH + ks * 32));
            #pragma unroll
            for (int ni = 0; ni < 4; ni++)
                ldsm_x2(b[ni][0], b[ni][1],
                        sbb + (uint32_t)(ni * 8 * TG_PITCH + ks * 32));
            #pragma unroll
            for (int mi = 0; mi < 4; mi++)
                #pragma unroll
                for (int ni = 0; ni < 4; ni++)
                    mma16816(c[mi][ni], a[mi], b[ni]);
        }
        __syncthreads();
    }

    const float scale = 0.125f;   // 1/sqrt(64)
    #pragma unroll
    for (int mi = 0; mi < 4; mi++) {
        #pragma unroll
        for (int half = 0; half < 2; half++) {
            int rg = row0 + wm * 64 + mi * 16 + g + half * 8;
            float* Sr = Sb + (size_t)rg * NSP;
            #pragma unroll
            for (int ni = 0; ni < 4; ni++) {
                int cg = col0 + wn * 32 + ni * 8 + 2 * tg;
                float v0 = (cg     <= rg + cSC) ? c[mi][ni][half * 2 + 0] * scale : -10000.0f;
                float v1 = (cg + 1 <= rg + cSC) ? c[mi][ni][half * 2 + 1] * scale : -10000.0f;
                *(float2*)(Sr + cg) = make_float2(v0, v1);
            }
        }
    }
}

// ---------------------------------------------------------------------------
// av_mma (ROUND-10 version, unchanged): A_merged = P' x Vt'^T.
// ---------------------------------------------------------------------------
constexpr int AV_BSTG = 64 * TG_PITCH;                  // 9216
constexpr int AV_SMEM = 2 * TG_STG + 2 * AV_BSTG + 128;

__global__ __launch_bounds__(256, 2) void av_mma(
    const __nv_bfloat16* __restrict__ P3, const __nv_bfloat16* __restrict__ V3,
    float* __restrict__ A)
{
    extern __shared__ char dynraw[];
    char* sb = (char*)(((uintptr_t)dynraw + 127) & ~(uintptr_t)127);
    const uint32_t sA0 = smem_u32(sb);
    const uint32_t sB0 = sA0 + 2 * TG_STG;

    const int tid  = threadIdx.x;
    const int wid  = tid >> 5;
    const int lane = tid & 31;
    const int g    = lane >> 2;
    const int tg   = lane & 3;
    const int wm   = wid >> 1;
    const int wn   = wid & 1;
    const int bh   = blockIdx.y;
    const int row0 = blockIdx.x * 128;

    const __nv_bfloat16* A3 = P3 + (size_t)bh * NDP * K3AV;
    const __nv_bfloat16* B3 = V3 + (size_t)bh * cDH * K3AV;

    uint32_t soffA[4];
    const __nv_bfloat16* Ag[4];
    #pragma unroll
    for (int p = 0; p < 4; p++) {
        int idx = p * 256 + tid;
        int row = idx >> 3, seg = idx & 7;
        soffA[p] = (uint32_t)(row * TG_PITCH + seg * 16);
        Ag[p] = A3 + (size_t)(row0 + row) * K3AV + seg * 8;
    }
    uint32_t soffB[2];
    const __nv_bfloat16* Bg[2];
    #pragma unroll
    for (int p = 0; p < 2; p++) {
        int idx = p * 256 + tid;
        int row = idx >> 3, seg = idx & 7;
        soffB[p] = (uint32_t)(row * TG_PITCH + seg * 16);
        Bg[p] = B3 + (size_t)row * K3AV + seg * 8;
    }

    const uint32_t aoff = (uint32_t)((wm * 32 + (lane & 15)) * TG_PITCH + (lane >> 4) * 16);
    const uint32_t boff = (uint32_t)((wn * 32 + (lane & 7)) * TG_PITCH + ((lane >> 3) & 1) * 16);

    float c[2][4][4];
    #pragma unroll
    for (int mi = 0; mi < 2; mi++)
        #pragma unroll
        for (int ni = 0; ni < 4; ni++)
            #pragma unroll
            for (int e = 0; e < 4; e++) c[mi][ni][e] = 0.f;

    const int nch = K3AV >> 6;   // 66

    #pragma unroll
    for (int p = 0; p < 4; p++) cp16(sA0 + soffA[p], Ag[p]);
    #pragma unroll
    for (int p = 0; p < 2; p++) cp16(sB0 + soffB[p], Bg[p]);
    asm volatile("cp.async.commit_group;" ::: "memory");

    for (int i = 0; i < nch; i++) {
        const int st = i & 1;
        if (i + 1 < nch) {
            const int st2 = (i + 1) & 1;
            const int ko = (i + 1) * 64;
            #pragma unroll
            for (int p = 0; p < 4; p++) cp16(sA0 + st2 * TG_STG + soffA[p], Ag[p] + ko);
            #pragma unroll
            for (int p = 0; p < 2; p++) cp16(sB0 + st2 * AV_BSTG + soffB[p], Bg[p] + ko);
            asm volatile("cp.async.commit_group;" ::: "memory");
            asm volatile("cp.async.wait_group 1;" ::: "memory");
        } else {
            asm volatile("cp.async.wait_group 0;" ::: "memory");
        }
        __syncthreads();

        const uint32_t sa = sA0 + st * TG_STG + aoff;
        const uint32_t sbb = sB0 + st * AV_BSTG + boff;
        #pragma unroll
        for (int ks = 0; ks < 4; ks++) {
            uint32_t a[2][4], b[4][2];
            #pragma unroll
            for (int mi = 0; mi < 2; mi++)
                ldsm_x4(a[mi][0], a[mi][1], a[mi][2], a[mi][3],
                        sa + (uint32_t)(mi * 16 * TG_PITCH + ks * 32));
            #pragma unroll
            for (int ni = 0; ni < 4; ni++)
                ldsm_x2(b[ni][0], b[ni][1],
                        sbb + (uint32_t)(ni * 8 * TG_PITCH + ks * 32));
            #pragma unroll
            for (int mi = 0; mi < 2; mi++)
                #pragma unroll
                for (int ni = 0; ni < 4; ni++)
                    mma16816(c[mi][ni], a[mi], b[ni]);
        }
        __syncthreads();
    }

    const int b_ = bh / cH, h = bh % cH;
    #pragma unroll
    for (int mi = 0; mi < 2; mi++) {
        #pragma unroll
        for (int half = 0; half < 2; half++) {
            int rg = row0 + wm * 32 + mi * 16 + g + half * 8;
            if (rg >= cND) continue;
            float* Ar = A + ((size_t)(b_ * cND + rg)) * cD + h * cDH;
            #pragma unroll
            for (int ni = 0; ni < 4; ni++) {
                int cg = wn * 32 + ni * 8 + 2 * tg;
                *(float2*)(Ar + cg) =
                    make_float2(c[mi][ni][half * 2 + 0], c[mi][ni][half * 2 + 1]);
            }
        }
    }
}

// ---------------------------------------------------------------------------
// LayerNorm (optionally fused with sos-concat gather)
// ---------------------------------------------------------------------------
__global__ __launch_bounds__(256) void ln_kernel(
    const float* __restrict__ in, const float* __restrict__ sos,
    const float* __restrict__ gamma, const float* __restrict__ beta,
    float* __restrict__ Hout, float* __restrict__ HLout, int concat)
{
    int r   = blockIdx.x;
    int tid = threadIdx.x;
    const float* src;
    if (concat) {
        int b = r / cND, t = r % cND;
        src = (t == 0) ? sos : in + ((size_t)b * cS + (t - 1)) * cD;
    } else {
        src = in + (size_t)r * cD;
    }
    float v0 = src[tid], v1 = src[tid + 256], v2 = src[tid + 512];
    float s  = v0 + v1 + v2;
    float ss = v0 * v0 + v1 * v1 + v2 * v2;

    __shared__ float sb[8], sb2[8];
    #pragma unroll
    for (int o = 16; o; o >>= 1) {
        s  += __shfl_xor_sync(0xffffffffu, s,  o);
        ss += __shfl_xor_sync(0xffffffffu, ss, o);
    }
    int lane = tid & 31, w = tid >> 5;
    if (lane == 0) { sb[w] = s; sb2[w] = ss; }
    __syncthreads();
    if (tid == 0) {
        float a = 0.f, c = 0.f;
        #pragma unroll
        for (int i = 0; i < 8; i++) { a += sb[i]; c += sb2[i]; }
        sb[0] = a; sb2[0] = c;
    }
    __syncthreads();
    float mean = sb[0] * (1.0f / 768.0f);
    float var  = sb2[0] * (1.0f / 768.0f) - mean * mean;
    float inv  = rsqrtf(var + 1e-5f);

    if (concat) {
        float* hr = Hout + (size_t)r * cD;
        hr[tid] = v0; hr[tid + 256] = v1; hr[tid + 512] = v2;
    }
    float* hlr = HLout + (size_t)r * cD;
    hlr[tid      ] = (v0 - mean) * inv * gamma[tid      ] + beta[tid      ];
    hlr[tid + 256] = (v1 - mean) * inv * gamma[tid + 256] + beta[tid + 256];
    hlr[tid + 512] = (v2 - mean) * inv * gamma[tid + 512] + beta[tid + 512];
}

// ---------------------------------------------------------------------------
// Split gathers for attention
// ---------------------------------------------------------------------------
__global__ void gather_q_split(const float* __restrict__ QKV, __nv_bfloat16* __restrict__ Qs)
{
    int idx = blockIdx.x * blockDim.x + threadIdx.x;
    if (idx >= cBH * cND * cDH) return;
    int d    = idx & (cDH - 1);
    int rest = idx >> 6;
    int t    = rest % cND;
    int bh   = rest / cND;
    int b = bh / cH, h = bh % cH;
    float x = QKV[((size_t)(b * cND + t)) * (3 * cD) + h * cDH + d];
    __nv_bfloat16 hi = __float2bfloat16(x);
    __nv_bfloat16 lo = __float2bfloat16(x - __bfloat162float(hi));
    size_t o = ((size_t)bh * NDP + t) * K3Q + 3 * d;
    Qs[o] = hi; Qs[o + 1] = lo; Qs[o + 2] = hi;
}

__global__ void gather_k_split(const float* __restrict__ QKV, const float* __restrict__ CKV,
                               __nv_bfloat16* __restrict__ Ks)
{
    int idx = blockIdx.x * blockDim.x + threadIdx.x;
    if (idx >= cBH * cNS * cDH) return;
    int d    = idx & (cDH - 1);
    int rest = idx >> 6;
    int j    = rest % cNS;
    int bh   = rest / cNS;
    int b = bh / cH, h = bh % cH;
    float kv;
    if (j < cSC)
        kv = CKV[((size_t)(b * cSC + j)) * (2 * cD) + h * cDH + d];
    else
        kv = QKV[((size_t)(b * cND + (j - cSC))) * (3 * cD) + cD + h * cDH + d];
    __nv_bfloat16 hi = __float2bfloat16(kv);
    __nv_bfloat16 lo = __float2bfloat16(kv - __bfloat162float(hi));
    size_t o = ((size_t)bh * NSP + j) * K3Q + 3 * d;
    Ks[o] = hi; Ks[o + 1] = hi; Ks[o + 2] = lo;
}

__global__ void gather_vt_split(const float* __restrict__ QKV, const float* __restrict__ CKV,
                                __nv_bfloat16* __restrict__ Vts)
{
    int idx = blockIdx.x * blockDim.x + threadIdx.x;
    if (idx >= cBH * cDH * cNS) return;
    int j    = idx % cNS;
    int rest = idx / cNS;
    int d    = rest & (cDH - 1);
    int bh   = rest >> 6;
    int b = bh / cH, h = bh % cH;
    float vv;
    if (j < cSC)
        vv = CKV[((size_t)(b * cSC + j)) * (2 * cD) + cD + h * cDH + d];
    else
        vv = QKV[((size_t)(b * cND + (j - cSC))) * (3 * cD) + 2 * cD + h * cDH + d];
    __nv_bfloat16 hi = __float2bfloat16(vv);
    __nv_bfloat16 lo = __float2bfloat16(vv - __bfloat162float(hi));
    size_t o = ((size_t)bh * cDH + d) * K3AV + 3 * j;
    Vts[o] = hi; Vts[o + 1] = hi; Vts[o + 2] = lo;
}

// ---------------------------------------------------------------------------
// Softmax over padded rows; writes split-bf16 probs [hi,lo,hi] + zero padding
// ---------------------------------------------------------------------------
__global__ __launch_bounds__(256) void softmax_split(
    const float* __restrict__ S, __nv_bfloat16* __restrict__ Ps)
{
    int r  = blockIdx.x;
    int bh = r / cND, m = r % cND;
    const float* p = S + ((size_t)bh * NDP + m) * NSP;
    __nv_bfloat16* out = Ps + ((size_t)bh * NDP + m) * K3AV;
    int tid = threadIdx.x;

    float vals[6];
    float mx = -3.4e38f;
    #pragma unroll
    for (int it = 0; it < 6; it++) {
        int i = tid + it * 256;
        float v = (i < cNS) ? p[i] : -3.4e38f;
        vals[it] = v;
        mx = fmaxf(mx, v);
    }
    __shared__ float sb[8];
    #pragma unroll
    for (int o = 16; o; o >>= 1) mx = fmaxf(mx, __shfl_xor_sync(0xffffffffu, mx, o));
    if ((tid & 31) == 0) sb[tid >> 5] = mx;
    __syncthreads();
    if (tid < 32) {
        float m2 = (tid < 8) ? sb[tid] : -3.4e38f;
        #pragma unroll
        for (int o = 4; o; o >>= 1) m2 = fmaxf(m2, __shfl_xor_sync(0xffffffffu, m2, o));
        if (tid == 0) sb[0] = m2;
    }
    __syncthreads();
    float bmax = sb[0];
    __syncthreads();

    float s = 0.f;
    #pragma unroll
    for (int it = 0; it < 6; it++) {
        int i = tid + it * 256;
        if (i < cNS) {
            float e = __expf(vals[it] - bmax);
            vals[it] = e;
            s += e;
        }
    }
    #pragma unroll
    for (int o = 16; o; o >>= 1) s += __shfl_xor_sync(0xffffffffu, s, o);
    if ((tid & 31) == 0) sb[tid >> 5] = s;
    __syncthreads();
    if (tid < 32) {
        float s2 = (tid < 8) ? sb[tid] : 0.f;
        #pragma unroll
        for (int o = 4; o; o >>= 1) s2 += __shfl_xor_sync(0xffffffffu, s2, o);
        if (tid == 0) sb[0] = s2;
    }
    __syncthreads();
    float inv = 1.0f / sb[0];
    #pragma unroll
    for (int it = 0; it < 6; it++) {
        int i = tid + it * 256;
        if (i >= NSP) continue;
        float v = (i < cNS) ? vals[it] * inv : 0.f;
        __nv_bfloat16 hi = __float2bfloat16(v);
        __nv_bfloat16 lo = __float2bfloat16(v - __bfloat162float(hi));
        out[3 * i] = hi; out[3 * i + 1] = lo; out[3 * i + 2] = hi;
    }
}

// ---------------------------------------------------------------------------
// Launch sequence
// ---------------------------------------------------------------------------
extern "C" void kernel_launch(void* const* d_in, const int* in_sizes, int n_in,
                              void* d_out, int out_size)
{
    (void)in_sizes; (void)n_in; (void)out_size;
    const float* x       = (const float*)d_in[0];
    const float* ctx     = (const float*)d_in[1];
    const float* sos     = (const float*)d_in[2];
    const float* ln1_g   = (const float*)d_in[3];
    const float* ln1_b   = (const float*)d_in[4];
    const float* W_attn  = (const float*)d_in[5];
    const float* b_attn  = (const float*)d_in[6];
    const float* W_ref   = (const float*)d_in[7];
    const float* b_ref   = (const float*)d_in[8];
    const float* W_proj  = (const float*)d_in[9];
    const float* b_proj  = (const float*)d_in[10];
    const float* ln2_g   = (const float*)d_in[11];
    const float* ln2_b   = (const float*)d_in[12];
    const float* W_fc    = (const float*)d_in[13];
    const float* b_fc    = (const float*)d_in[14];
    const float* W_mproj = (const float*)d_in[15];
    const float* b_mproj = (const float*)d_in[16];
    float* out = (float*)d_out;

    float *H, *HL, *QKV, *CKV, *A, *H2, *HL2, *FC, *Sp, *Pp;
    __nv_bfloat16 *As, *Bs, *Qs, *Ks, *Vts, *Ps;
    cudaGetSymbolAddress((void**)&H,   g_H);
    cudaGetSymbolAddress((void**)&HL,  g_HL);
    cudaGetSymbolAddress((void**)&QKV, g_QKV);
    cudaGetSymbolAddress((void**)&CKV, g_CKV);
    cudaGetSymbolAddress((void**)&A,   g_A);
    cudaGetSymbolAddress((void**)&H2,  g_H2);
    cudaGetSymbolAddress((void**)&HL2, g_HL2);
    cudaGetSymbolAddress((void**)&FC,  g_FC);
    cudaGetSymbolAddress((void**)&Sp,  g_Sp);
    cudaGetSymbolAddress((void**)&Pp,  g_Pp);
    cudaGetSymbolAddress((void**)&As,  g_As);
    cudaGetSymbolAddress((void**)&Bs,  g_Bs);
    cudaGetSymbolAddress((void**)&Qs,  g_Qs);
    cudaGetSymbolAddress((void**)&Ks,  g_Ks);
    cudaGetSymbolAddress((void**)&Vts, g_Vts);
    cudaGetSymbolAddress((void**)&Ps,  g_Ps);

    cudaFuncSetAttribute(tgemm,      cudaFuncAttributeMaxDynamicSharedMemorySize, TG_SMEM);
    cudaFuncSetAttribute(scores_mma, cudaFuncAttributeMaxDynamicSharedMemorySize, TG_SMEM);
    cudaFuncSetAttribute(av_mma,     cudaFuncAttributeMaxDynamicSharedMemorySize, AV_SMEM);

    // 1. concat(sos, x) + LN1
    ln_kernel<<<cM, 256>>>(x, sos, ln1_g, ln1_b, H, HL, 1);

    // 2. qkv = ln1(h) @ W_attn + b_attn   (306 CTAs, no split)
    act_split<<<(cM * cD / 4 + 255) / 256, 256>>>(HL, As, cM * cD, cD);
    w_split<<<dim3(3 * cD / 32, cD / 32), 256>>>(W_attn, Bs, cD, 3 * cD);
    tgemm<<<dim3(3 * cD / 128, 17, 1), 256, TG_SMEM>>>(As, Bs, b_attn, nullptr, QKV,
                                                       cM, 3 * cD, 3 * cD, 0);

    // 3. ckv = context @ W_ref + b_ref    (split-K x3: 144 CTAs)
    act_split<<<(cMC * cD / 4 + 255) / 256, 256>>>(ctx, As, cMC * cD, cD);
    w_split<<<dim3(2 * cD / 32, cD / 32), 256>>>(W_ref, Bs, cD, 2 * cD);
    tgemm<<<dim3(2 * cD / 128, 4, 3), 256, TG_SMEM>>>(As, Bs, b_ref, nullptr, Pp,
                                                      cMC, 2 * cD, 3 * cD, 4);
    combine<<<(cMC * 2 * cD / 4 + 255) / 256, 256>>>(Pp, b_ref, nullptr, CKV,
                                                     cMC, 2 * cD, 3, 0);

    // 4. split gathers for attention
    gather_q_split<<<(cBH * cND * cDH + 255) / 256, 256>>>(QKV, Qs);
    gather_k_split<<<(cBH * cNS * cDH + 255) / 256, 256>>>(QKV, CKV, Ks);
    gather_vt_split<<<(cBH * cDH * cNS + 255) / 256, 256>>>(QKV, CKV, Vts);

    // 5. attention on tensor pipe
    scores_mma<<<dim3(NSP / 128, NDP / 128, cBH), 256, TG_SMEM>>>(Qs, Ks, Sp);
    softmax_split<<<cBH * cND, 256>>>(Sp, Ps);
    av_mma<<<dim3(NDP / 128, cBH), 256, AV_SMEM>>>(Ps, Vts, A);

    // 6. h2 = h + attn @ W_proj + b_proj  (split-K x2: 204 CTAs)
    act_split<<<(cM * cD / 4 + 255) / 256, 256>>>(A, As, cM * cD, cD);
    w_split<<<dim3(cD / 32, cD / 32), 256>>>(W_proj, Bs, cD, cD);
    tgemm<<<dim3(cD / 128, 17, 2), 256, TG_SMEM>>>(As, Bs, b_proj, nullptr, Pp,
                                                   cM, cD, 3 * cD, 4);
    combine<<<(cM * cD / 4 + 255) / 256, 256>>>(Pp, b_proj, H, H2, cM, cD, 2, 2);

    // 7. LN2
    ln_kernel<<<cM, 256>>>(H2, nullptr, ln2_g, ln2_b, nullptr, HL2, 0);

    // 8. fc = gelu(ln2(h2) @ W_fc + b_fc) (408 CTAs, no split)
    act_split<<<(cM * cD / 4 + 255) / 256, 256>>>(HL2, As, cM * cD, cD);
    w_split<<<dim3(4 * cD / 32, cD / 32), 256>>>(W_fc, Bs, cD, 4 * cD);
    tgemm<<<dim3(4 * cD / 128, 17, 1), 256, TG_SMEM>>>(As, Bs, b_fc, nullptr, FC,
                                                       cM, 4 * cD, 3 * cD, 1);

    // 9. out = (h2 + fc @ W_mproj + b_mproj)[:, 1:, :]  (split-K x2: 204 CTAs)
    act_split<<<(cM * 4 * cD / 4 + 255) / 256, 256>>>(FC, As, cM * 4 * cD, 4 * cD);
    w_split<<<dim3(cD / 32, 4 * cD / 32), 256>>>(W_mproj, Bs, 4 * cD, cD);
    tgemm<<<dim3(cD / 128, 17, 2), 256, TG_SMEM>>>(As, Bs, b_mproj, nullptr, Pp,
                                                   cM, cD, 12 * cD, 4);
    combine<<<(cM * cD / 4 + 255) / 256, 256>>>(Pp, b_mproj, H2, out, cM, cD, 2, 3);
}

// round 13
// speedup vs baseline: 1.2894x; 1.1530x over previous
#include <cuda_runtime.h>
#include <cuda_bf16.h>
#include <math.h>
#include <stdint.h>

// ---------------------------------------------------------------------------
// Problem constants (CoconBlock: B=2, S=1024, Sc=256, D=768, H=12, dh=64)
// ---------------------------------------------------------------------------
constexpr int cD   = 768;
constexpr int cH   = 12;
constexpr int cDH  = 64;
constexpr int cB   = 2;
constexpr int cS   = 1024;
constexpr int cSC  = 256;
constexpr int cND  = cS + 1;          // 1025 queries per batch (sos + seq)
constexpr int cNS  = cSC + cND;       // 1281 keys per batch
constexpr int cM   = cB * cND;        // 2050 rows in main activation
constexpr int cMC  = cB * cSC;        // 512 context rows
constexpr int cBH  = cB * cH;         // 24 (batch, head) pairs
constexpr int cMPAD = 2176;           // 17 * 128

// attention padded dims
constexpr int NDP  = 1152;            // 9 * 128 padded queries
constexpr int NSP  = 1408;            // 11 * 128 padded keys
constexpr int K3Q  = 192;             // 3 * dh (split, interleaved format)
constexpr int K3AV = 3 * NSP;         // 4224

// ---------------------------------------------------------------------------
// Scratch (static __device__ arrays, zero-initialized; padding regions are
// never written so they stay zero across graph replays)
// ---------------------------------------------------------------------------
__device__ float g_H  [(size_t)cM * cD];
__device__ float g_HL [(size_t)cM * cD];
__device__ float g_QKV[(size_t)cM * 3 * cD];
__device__ float g_CKV[(size_t)cMC * 2 * cD];
__device__ float g_A  [(size_t)cM * cD];
__device__ float g_H2 [(size_t)cM * cD];
__device__ float g_HL2[(size_t)cM * cD];
__device__ float g_FC [(size_t)cM * 4 * cD];
// hi/lo plane operands for the dense GEMMs (plane stride = cMPAD*K / N*K)
__device__ __nv_bfloat16 g_As[(size_t)2 * cMPAD * 3072];     // A hi|lo planes
__device__ __nv_bfloat16 g_Bs[(size_t)2 * 3072 * 768 + 2 * 768 * 2304]; // B hi|lo planes (max case)
// attention buffers (interleaved 3-slot format, unchanged from R10)
__device__ __nv_bfloat16 g_Qs [(size_t)cBH * NDP * K3Q];
__device__ __nv_bfloat16 g_Ks [(size_t)cBH * NSP * K3Q];
__device__ __nv_bfloat16 g_Vts[(size_t)cBH * cDH * K3AV];
__device__ float         g_Sp [(size_t)cBH * NDP * NSP];
__device__ __nv_bfloat16 g_Ps [(size_t)cBH * NDP * K3AV];

// ---------------------------------------------------------------------------
// Small helpers
// ---------------------------------------------------------------------------
__device__ __forceinline__ float gelu_new(float x) {
    float x3 = x * x * x;
    return 0.5f * x * (1.0f + tanhf(0.7978845608028654f * (x + 0.044715f * x3)));
}
__device__ __forceinline__ uint32_t smem_u32(const void* p) {
    uint32_t a;
    asm("{ .reg .u64 t; cvta.to.shared.u64 t, %1; cvt.u32.u64 %0, t; }" : "=r"(a) : "l"(p));
    return a;
}
__device__ __forceinline__ void cp16(uint32_t s, const void* g) {
    asm volatile("cp.async.cg.shared.global [%0], [%1], 16;\n"
                 :: "r"(s), "l"(__cvta_generic_to_global(g)) : "memory");
}
__device__ __forceinline__ void ldsm_x4(uint32_t& r0, uint32_t& r1, uint32_t& r2,
                                        uint32_t& r3, uint32_t addr) {
    asm volatile("ldmatrix.sync.aligned.m8n8.x4.shared.b16 {%0,%1,%2,%3}, [%4];"
                 : "=r"(r0), "=r"(r1), "=r"(r2), "=r"(r3) : "r"(addr));
}
__device__ __forceinline__ void ldsm_x2(uint32_t& r0, uint32_t& r1, uint32_t addr) {
    asm volatile("ldmatrix.sync.aligned.m8n8.x2.shared.b16 {%0,%1}, [%2];"
                 : "=r"(r0), "=r"(r1) : "r"(addr));
}
__device__ __forceinline__ void mma16816(float* c, const uint32_t* a, const uint32_t* b) {
    asm volatile(
        "mma.sync.aligned.m16n8k16.row.col.f32.bf16.bf16.f32 "
        "{%0,%1,%2,%3}, {%4,%5,%6,%7}, {%8,%9}, {%0,%1,%2,%3};"
        : "+f"(c[0]), "+f"(c[1]), "+f"(c[2]), "+f"(c[3])
        : "r"(a[0]), "r"(a[1]), "r"(a[2]), "r"(a[3]), "r"(b[0]), "r"(b[1]));
}

// ---------------------------------------------------------------------------
// Plane-split conversions: X fp32 -> (hi, lo) bf16 planes (lo = x - hi)
// ---------------------------------------------------------------------------
__global__ __launch_bounds__(256) void act_split2(
    const float* __restrict__ X, __nv_bfloat16* __restrict__ Yhi,
    __nv_bfloat16* __restrict__ Ylo, int MK)
{
    int i4 = (blockIdx.x * 256 + threadIdx.x) * 4;
    if (i4 >= MK) return;
    float4 x = *(const float4*)(X + i4);
    float xv[4] = {x.x, x.y, x.z, x.w};
    __nv_bfloat16 h[4], l[4];
    #pragma unroll
    for (int j = 0; j < 4; j++) {
        h[j] = __float2bfloat16(xv[j]);
        l[j] = __float2bfloat16(xv[j] - __bfloat162float(h[j]));
    }
    *(uint64_t*)(Yhi + i4) = *(uint64_t*)h;
    *(uint64_t*)(Ylo + i4) = *(uint64_t*)l;
}

// W [K,N] fp32 -> hi/lo planes [N,K] (transposed)
__global__ __launch_bounds__(256) void w_split2(
    const float* __restrict__ W, __nv_bfloat16* __restrict__ Yhi,
    __nv_bfloat16* __restrict__ Ylo, int K, int N)
{
    __shared__ float t[32][33];
    int k0 = blockIdx.y * 32, n0 = blockIdx.x * 32;
    int tid = threadIdx.x;
    #pragma unroll
    for (int p = 0; p < 4; p++) {
        int idx = p * 256 + tid;
        int kk = idx >> 5, nn = idx & 31;
        t[kk][nn] = W[(size_t)(k0 + kk) * N + n0 + nn];
    }
    __syncthreads();
    #pragma unroll
    for (int p = 0; p < 4; p++) {
        int idx = p * 256 + tid;
        int nn = idx >> 5, kk = idx & 31;
        float x = t[kk][nn];
        __nv_bfloat16 hi = __float2bfloat16(x);
        __nv_bfloat16 lo = __float2bfloat16(x - __bfloat162float(hi));
        size_t o = (size_t)(n0 + nn) * K + (k0 + kk);
        Yhi[o] = hi;
        Ylo[o] = lo;
    }
}

// ---------------------------------------------------------------------------
// Dense HMMA GEMM, hi/lo-plane operands:
//   C = Ahi*Bhi^T + Ahi*Blo^T + Alo*Bhi^T   (exact same math as the 3-slot
//   format, 2/3 the smem/gmem bytes).
// 128x128 tile, 8 warps (2x4), chunk = 32 original k, double-buffered,
// pitch 80B (conflict-free ldmatrix), occ 2 enforced by launch_bounds.
// mode: 0 +bias, 1 +bias+gelu, 2 +bias+R, 3 +bias+R & drop-sos write.
// ---------------------------------------------------------------------------
constexpr int T2_PITCH = 80;                      // 64B data + 16B pad
constexpr int T2_PLANE = 128 * T2_PITCH;          // 10240
constexpr int T2_STG   = 4 * T2_PLANE;            // 40960 (Ahi,Alo,Bhi,Blo)
constexpr int T2_SMEM  = 2 * T2_STG + 128;        // 82048

__global__ __launch_bounds__(256, 2) void tgemm2(
    const __nv_bfloat16* __restrict__ Ahi, const __nv_bfloat16* __restrict__ Alo,
    const __nv_bfloat16* __restrict__ Bhi, const __nv_bfloat16* __restrict__ Blo,
    const float* __restrict__ bias, const float* __restrict__ R,
    float* __restrict__ C, int M, int N, int K, int mode)
{
    extern __shared__ char dynraw[];
    char* sb = (char*)(((uintptr_t)dynraw + 127) & ~(uintptr_t)127);
    const uint32_t s0 = smem_u32(sb);

    const int tid  = threadIdx.x;
    const int wid  = tid >> 5;
    const int lane = tid & 31;
    const int g    = lane >> 2;
    const int tg   = lane & 3;
    const int wm   = wid >> 2;
    const int wn   = wid & 3;
    const int row0 = blockIdx.y * 128;
    const int col0 = blockIdx.x * 128;
    const int nch  = K >> 5;                       // 32 original k per chunk

    // cp.async maps: thread covers (row = tid>>2, seg = tid&3) in rows 0..63
    // of each plane, plus the +64-row sibling.
    const int crow = tid >> 2;
    const int cseg = tid & 3;
    const uint32_t so = (uint32_t)(crow * T2_PITCH + cseg * 16);
    const size_t g64 = (size_t)64 * K;
    const __nv_bfloat16* PA_hi = Ahi + (size_t)(row0 + crow) * K + cseg * 8;
    const __nv_bfloat16* PA_lo = Alo + (size_t)(row0 + crow) * K + cseg * 8;
    const __nv_bfloat16* PB_hi = Bhi + (size_t)(col0 + crow) * K + cseg * 8;
    const __nv_bfloat16* PB_lo = Blo + (size_t)(col0 + crow) * K + cseg * 8;

    const uint32_t aoff = (uint32_t)((wm * 64 + (lane & 15)) * T2_PITCH + (lane >> 4) * 16);
    const uint32_t boff = (uint32_t)((wn * 32 + (lane & 7)) * T2_PITCH + ((lane >> 3) & 1) * 16);

    float c[4][4][4];
    #pragma unroll
    for (int mi = 0; mi < 4; mi++)
        #pragma unroll
        for (int ni = 0; ni < 4; ni++)
            #pragma unroll
            for (int e = 0; e < 4; e++) c[mi][ni][e] = 0.f;

    // chunk loader
    auto load_chunk = [&](int ch, uint32_t st) {
        int k0 = ch * 32;
        cp16(st + so,                         PA_hi + k0);
        cp16(st + so + 64 * T2_PITCH,         PA_hi + k0 + g64);
        cp16(st + T2_PLANE + so,              PA_lo + k0);
        cp16(st + T2_PLANE + so + 64 * T2_PITCH, PA_lo + k0 + g64);
        cp16(st + 2 * T2_PLANE + so,          PB_hi + k0);
        cp16(st + 2 * T2_PLANE + so + 64 * T2_PITCH, PB_hi + k0 + g64);
        cp16(st + 3 * T2_PLANE + so,          PB_lo + k0);
        cp16(st + 3 * T2_PLANE + so + 64 * T2_PITCH, PB_lo + k0 + g64);
        asm volatile("cp.async.commit_group;" ::: "memory");
    };

    load_chunk(0, s0);

    for (int i = 0; i < nch; i++) {
        const int st = i & 1;
        if (i + 1 < nch) {
            load_chunk(i + 1, s0 + ((i + 1) & 1) * T2_STG);
            asm volatile("cp.async.wait_group 1;" ::: "memory");
        } else {
            asm volatile("cp.async.wait_group 0;" ::: "memory");
        }
        __syncthreads();

        const uint32_t base = s0 + st * T2_STG;
        #pragma unroll
        for (int kg = 0; kg < 2; kg++) {
            const uint32_t ko = kg * 32;
            uint32_t bhi[4][2], blo[4][2], ahi[4][4], alo[4][4];
            #pragma unroll
            for (int ni = 0; ni < 4; ni++)
                ldsm_x2(bhi[ni][0], bhi[ni][1],
                        base + 2 * T2_PLANE + boff + (uint32_t)(ni * 8 * T2_PITCH) + ko);
            #pragma unroll
            for (int mi = 0; mi < 4; mi++)
                ldsm_x4(ahi[mi][0], ahi[mi][1], ahi[mi][2], ahi[mi][3],
                        base + aoff + (uint32_t)(mi * 16 * T2_PITCH) + ko);
            #pragma unroll
            for (int mi = 0; mi < 4; mi++)
                #pragma unroll
                for (int ni = 0; ni < 4; ni++)
                    mma16816(c[mi][ni], ahi[mi], bhi[ni]);
            #pragma unroll
            for (int ni = 0; ni < 4; ni++)
                ldsm_x2(blo[ni][0], blo[ni][1],
                        base + 3 * T2_PLANE + boff + (uint32_t)(ni * 8 * T2_PITCH) + ko);
            #pragma unroll
            for (int mi = 0; mi < 4; mi++)
                #pragma unroll
                for (int ni = 0; ni < 4; ni++)
                    mma16816(c[mi][ni], ahi[mi], blo[ni]);
            #pragma unroll
            for (int mi = 0; mi < 4; mi++)
                ldsm_x4(alo[mi][0], alo[mi][1], alo[mi][2], alo[mi][3],
                        base + T2_PLANE + aoff + (uint32_t)(mi * 16 * T2_PITCH) + ko);
            #pragma unroll
            for (int mi = 0; mi < 4; mi++)
                #pragma unroll
                for (int ni = 0; ni < 4; ni++)
                    mma16816(c[mi][ni], alo[mi], bhi[ni]);
        }
        __syncthreads();
    }

    #pragma unroll
    for (int mi = 0; mi < 4; mi++) {
        #pragma unroll
        for (int half = 0; half < 2; half++) {
            int rg = row0 + wm * 64 + mi * 16 + g + half * 8;
            if (rg >= M) continue;
            float* crow2;
            if (mode == 3) {
                int t = rg % cND;
                if (t == 0) continue;
                crow2 = C + ((size_t)((rg / cND) * cS + (t - 1))) * N;
            } else {
                crow2 = C + (size_t)rg * N;
            }
            #pragma unroll
            for (int ni = 0; ni < 4; ni++) {
                int cg = col0 + wn * 32 + ni * 8 + 2 * tg;
                float v0 = c[mi][ni][half * 2 + 0] + __ldg(&bias[cg]);
                float v1 = c[mi][ni][half * 2 + 1] + __ldg(&bias[cg + 1]);
                if (mode == 1) { v0 = gelu_new(v0); v1 = gelu_new(v1); }
                else if (mode >= 2) {
                    v0 += R[(size_t)rg * N + cg];
                    v1 += R[(size_t)rg * N + cg + 1];
                }
                *(float2*)(crow2 + cg) = make_float2(v0, v1);
            }
        }
    }
}

// ---------------------------------------------------------------------------
// scores_mma (R10 mainloop, 3-slot interleaved operands) + early-exit for
// fully-masked tiles.
// ---------------------------------------------------------------------------
constexpr int TG_PITCH = 144;
constexpr int TG_STG   = 128 * TG_PITCH;      // 18432
constexpr int TG_SMEM  = 4 * TG_STG + 128;

__global__ __launch_bounds__(256, 2) void scores_mma(
    const __nv_bfloat16* __restrict__ Qs, const __nv_bfloat16* __restrict__ Ks,
    float* __restrict__ S)
{
    extern __shared__ char dynraw[];
    char* sb = (char*)(((uintptr_t)dynraw + 127) & ~(uintptr_t)127);
    const uint32_t sA0 = smem_u32(sb);
    const uint32_t sB0 = sA0 + 2 * TG_STG;

    const int tid  = threadIdx.x;
    const int wid  = tid >> 5;
    const int lane = tid & 31;
    const int g    = lane >> 2;
    const int tg   = lane & 3;
    const int wm   = wid >> 2;
    const int wn   = wid & 3;
    const int bh   = blockIdx.z;
    const int row0 = blockIdx.y * 128;
    const int col0 = blockIdx.x * 128;

    float* Sb = S + (size_t)bh * NDP * NSP;

    if (col0 >= row0 + 128 + cSC) {   // fully masked: write -1e4, skip GEMM
        #pragma unroll
        for (int mi = 0; mi < 4; mi++)
            #pragma unroll
            for (int half = 0; half < 2; half++) {
                int rg = row0 + wm * 64 + mi * 16 + g + half * 8;
                float* Sr = Sb + (size_t)rg * NSP;
                #pragma unroll
                for (int ni = 0; ni < 4; ni++) {
                    int cg = col0 + wn * 32 + ni * 8 + 2 * tg;
                    *(float2*)(Sr + cg) = make_float2(-10000.0f, -10000.0f);
                }
            }
        return;
    }

    const __nv_bfloat16* A3 = Qs + (size_t)bh * NDP * K3Q;
    const __nv_bfloat16* B3 = Ks + (size_t)bh * NSP * K3Q;

    uint32_t soff[4];
    const __nv_bfloat16 *Ag[4], *Bg[4];
    #pragma unroll
    for (int p = 0; p < 4; p++) {
        int idx = p * 256 + tid;
        int row = idx >> 3, seg = idx & 7;
        soff[p] = (uint32_t)(row * TG_PITCH + seg * 16);
        Ag[p] = A3 + (size_t)(row0 + row) * K3Q + seg * 8;
        Bg[p] = B3 + (size_t)(col0 + row) * K3Q + seg * 8;
    }
    const uint32_t aoff = (uint32_t)((wm * 64 + (lane & 15)) * TG_PITCH + (lane >> 4) * 16);
    const uint32_t boff = (uint32_t)((wn * 32 + (lane & 7)) * TG_PITCH + ((lane >> 3) & 1) * 16);

    float c[4][4][4];
    #pragma unroll
    for (int mi = 0; mi < 4; mi++)
        #pragma unroll
        for (int ni = 0; ni < 4; ni++)
            #pragma unroll
            for (int e = 0; e < 4; e++) c[mi][ni][e] = 0.f;

    #pragma unroll
    for (int p = 0; p < 4; p++) {
        cp16(sA0 + soff[p], Ag[p]);
        cp16(sB0 + soff[p], Bg[p]);
    }
    asm volatile("cp.async.commit_group;" ::: "memory");

    #pragma unroll
    for (int i = 0; i < 3; i++) {
        const int st = i & 1;
        if (i + 1 < 3) {
            const int st2 = (i + 1) & 1;
            const int ko = (i + 1) * 64;
            #pragma unroll
            for (int p = 0; p < 4; p++) {
                cp16(sA0 + st2 * TG_STG + soff[p], Ag[p] + ko);
                cp16(sB0 + st2 * TG_STG + soff[p], Bg[p] + ko);
            }
            asm volatile("cp.async.commit_group;" ::: "memory");
            asm volatile("cp.async.wait_group 1;" ::: "memory");
        } else {
            asm volatile("cp.async.wait_group 0;" ::: "memory");
        }
        __syncthreads();
        const uint32_t sa = sA0 + st * TG_STG + aoff;
        const uint32_t sbb = sB0 + st * TG_STG + boff;
        #pragma unroll
        for (int ks = 0; ks < 4; ks++) {
            uint32_t a[4][4], b[4][2];
            #pragma unroll
            for (int mi = 0; mi < 4; mi++)
                ldsm_x4(a[mi][0], a[mi][1], a[mi][2], a[mi][3],
                        sa + (uint32_t)(mi * 16 * TG_PITCH + ks * 32));
            #pragma unroll
            for (int ni = 0; ni < 4; ni++)
                ldsm_x2(b[ni][0], b[ni][1],
                        sbb + (uint32_t)(ni * 8 * TG_PITCH + ks * 32));
            #pragma unroll
            for (int mi = 0; mi < 4; mi++)
                #pragma unroll
                for (int ni = 0; ni < 4; ni++)
                    mma16816(c[mi][ni], a[mi], b[ni]);
        }
        __syncthreads();
    }

    const float scale = 0.125f;   // 1/sqrt(64)
    #pragma unroll
    for (int mi = 0; mi < 4; mi++) {
        #pragma unroll
        for (int half = 0; half < 2; half++) {
            int rg = row0 + wm * 64 + mi * 16 + g + half * 8;
            float* Sr = Sb + (size_t)rg * NSP;
            #pragma unroll
            for (int ni = 0; ni < 4; ni++) {
                int cg = col0 + wn * 32 + ni * 8 + 2 * tg;
                float v0 = (cg     <= rg + cSC) ? c[mi][ni][half * 2 + 0] * scale : -10000.0f;
                float v1 = (cg + 1 <= rg + cSC) ? c[mi][ni][half * 2 + 1] * scale : -10000.0f;
                *(float2*)(Sr + cg) = make_float2(v0, v1);
            }
        }
    }
}

// ---------------------------------------------------------------------------
// av_mma (R10 version, unchanged): A_merged = P' x Vt'^T.
// ---------------------------------------------------------------------------
constexpr int AV_BSTG = 64 * TG_PITCH;                  // 9216
constexpr int AV_SMEM = 2 * TG_STG + 2 * AV_BSTG + 128;

__global__ __launch_bounds__(256, 2) void av_mma(
    const __nv_bfloat16* __restrict__ P3, const __nv_bfloat16* __restrict__ V3,
    float* __restrict__ A)
{
    extern __shared__ char dynraw[];
    char* sb = (char*)(((uintptr_t)dynraw + 127) & ~(uintptr_t)127);
    const uint32_t sA0 = smem_u32(sb);
    const uint32_t sB0 = sA0 + 2 * TG_STG;

    const int tid  = threadIdx.x;
    const int wid  = tid >> 5;
    const int lane = tid & 31;
    const int g    = lane >> 2;
    const int tg   = lane & 3;
    const int wm   = wid >> 1;
    const int wn   = wid & 1;
    const int bh   = blockIdx.y;
    const int row0 = blockIdx.x * 128;

    const __nv_bfloat16* A3 = P3 + (size_t)bh * NDP * K3AV;
    const __nv_bfloat16* B3 = V3 + (size_t)bh * cDH * K3AV;

    uint32_t soffA[4];
    const __nv_bfloat16* Ag[4];
    #pragma unroll
    for (int p = 0; p < 4; p++) {
        int idx = p * 256 + tid;
        int row = idx >> 3, seg = idx & 7;
        soffA[p] = (uint32_t)(row * TG_PITCH + seg * 16);
        Ag[p] = A3 + (size_t)(row0 + row) * K3AV + seg * 8;
    }
    uint32_t soffB[2];
    const __nv_bfloat16* Bg[2];
    #pragma unroll
    for (int p = 0; p < 2; p++) {
        int idx = p * 256 + tid;
        int row = idx >> 3, seg = idx & 7;
        soffB[p] = (uint32_t)(row * TG_PITCH + seg * 16);
        Bg[p] = B3 + (size_t)row * K3AV + seg * 8;
    }

    const uint32_t aoff = (uint32_t)((wm * 32 + (lane & 15)) * TG_PITCH + (lane >> 4) * 16);
    const uint32_t boff = (uint32_t)((wn * 32 + (lane & 7)) * TG_PITCH + ((lane >> 3) & 1) * 16);

    float c[2][4][4];
    #pragma unroll
    for (int mi = 0; mi < 2; mi++)
        #pragma unroll
        for (int ni = 0; ni < 4; ni++)
            #pragma unroll
            for (int e = 0; e < 4; e++) c[mi][ni][e] = 0.f;

    const int nch = K3AV >> 6;   // 66

    #pragma unroll
    for (int p = 0; p < 4; p++) cp16(sA0 + soffA[p], Ag[p]);
    #pragma unroll
    for (int p = 0; p < 2; p++) cp16(sB0 + soffB[p], Bg[p]);
    asm volatile("cp.async.commit_group;" ::: "memory");

    for (int i = 0; i < nch; i++) {
        const int st = i & 1;
        if (i + 1 < nch) {
            const int st2 = (i + 1) & 1;
            const int ko = (i + 1) * 64;
            #pragma unroll
            for (int p = 0; p < 4; p++) cp16(sA0 + st2 * TG_STG + soffA[p], Ag[p] + ko);
            #pragma unroll
            for (int p = 0; p < 2; p++) cp16(sB0 + st2 * AV_BSTG + soffB[p], Bg[p] + ko);
            asm volatile("cp.async.commit_group;" ::: "memory");
            asm volatile("cp.async.wait_group 1;" ::: "memory");
        } else {
            asm volatile("cp.async.wait_group 0;" ::: "memory");
        }
        __syncthreads();

        const uint32_t sa = sA0 + st * TG_STG + aoff;
        const uint32_t sbb = sB0 + st * AV_BSTG + boff;
        #pragma unroll
        for (int ks = 0; ks < 4; ks++) {
            uint32_t a[2][4], b[4][2];
            #pragma unroll
            for (int mi = 0; mi < 2; mi++)
                ldsm_x4(a[mi][0], a[mi][1], a[mi][2], a[mi][3],
                        sa + (uint32_t)(mi * 16 * TG_PITCH + ks * 32));
            #pragma unroll
            for (int ni = 0; ni < 4; ni++)
                ldsm_x2(b[ni][0], b[ni][1],
                        sbb + (uint32_t)(ni * 8 * TG_PITCH + ks * 32));
            #pragma unroll
            for (int mi = 0; mi < 2; mi++)
                #pragma unroll
                for (int ni = 0; ni < 4; ni++)
                    mma16816(c[mi][ni], a[mi], b[ni]);
        }
        __syncthreads();
    }

    const int b_ = bh / cH, h = bh % cH;
    #pragma unroll
    for (int mi = 0; mi < 2; mi++) {
        #pragma unroll
        for (int half = 0; half < 2; half++) {
            int rg = row0 + wm * 32 + mi * 16 + g + half * 8;
            if (rg >= cND) continue;
            float* Ar = A + ((size_t)(b_ * cND + rg)) * cD + h * cDH;
            #pragma unroll
            for (int ni = 0; ni < 4; ni++) {
                int cg = wn * 32 + ni * 8 + 2 * tg;
                *(float2*)(Ar + cg) =
                    make_float2(c[mi][ni][half * 2 + 0], c[mi][ni][half * 2 + 1]);
            }
        }
    }
}

// ---------------------------------------------------------------------------
// LayerNorm (optionally fused with sos-concat gather)
// ---------------------------------------------------------------------------
__global__ __launch_bounds__(256) void ln_kernel(
    const float* __restrict__ in, const float* __restrict__ sos,
    const float* __restrict__ gamma, const float* __restrict__ beta,
    float* __restrict__ Hout, float* __restrict__ HLout, int concat)
{
    int r   = blockIdx.x;
    int tid = threadIdx.x;
    const float* src;
    if (concat) {
        int b = r / cND, t = r % cND;
        src = (t == 0) ? sos : in + ((size_t)b * cS + (t - 1)) * cD;
    } else {
        src = in + (size_t)r * cD;
    }
    float v0 = src[tid], v1 = src[tid + 256], v2 = src[tid + 512];
    float s  = v0 + v1 + v2;
    float ss = v0 * v0 + v1 * v1 + v2 * v2;

    __shared__ float sb[8], sb2[8];
    #pragma unroll
    for (int o = 16; o; o >>= 1) {
        s  += __shfl_xor_sync(0xffffffffu, s,  o);
        ss += __shfl_xor_sync(0xffffffffu, ss, o);
    }
    int lane = tid & 31, w = tid >> 5;
    if (lane == 0) { sb[w] = s; sb2[w] = ss; }
    __syncthreads();
    if (tid == 0) {
        float a = 0.f, c = 0.f;
        #pragma unroll
        for (int i = 0; i < 8; i++) { a += sb[i]; c += sb2[i]; }
        sb[0] = a; sb2[0] = c;
    }
    __syncthreads();
    float mean = sb[0] * (1.0f / 768.0f);
    float var  = sb2[0] * (1.0f / 768.0f) - mean * mean;
    float inv  = rsqrtf(var + 1e-5f);

    if (concat) {
        float* hr = Hout + (size_t)r * cD;
        hr[tid] = v0; hr[tid + 256] = v1; hr[tid + 512] = v2;
    }
    float* hlr = HLout + (size_t)r * cD;
    hlr[tid      ] = (v0 - mean) * inv * gamma[tid      ] + beta[tid      ];
    hlr[tid + 256] = (v1 - mean) * inv * gamma[tid + 256] + beta[tid + 256];
    hlr[tid + 512] = (v2 - mean) * inv * gamma[tid + 512] + beta[tid + 512];
}

// ---------------------------------------------------------------------------
// Split gathers for attention (3-slot interleaved format, as in R10)
// ---------------------------------------------------------------------------
__global__ void gather_q_split(const float* __restrict__ QKV, __nv_bfloat16* __restrict__ Qs)
{
    int idx = blockIdx.x * blockDim.x + threadIdx.x;
    if (idx >= cBH * cND * cDH) return;
    int d    = idx & (cDH - 1);
    int rest = idx >> 6;
    int t    = rest % cND;
    int bh   = rest / cND;
    int b = bh / cH, h = bh % cH;
    float x = QKV[((size_t)(b * cND + t)) * (3 * cD) + h * cDH + d];
    __nv_bfloat16 hi = __float2bfloat16(x);
    __nv_bfloat16 lo = __float2bfloat16(x - __bfloat162float(hi));
    size_t o = ((size_t)bh * NDP + t) * K3Q + 3 * d;
    Qs[o] = hi; Qs[o + 1] = lo; Qs[o + 2] = hi;
}

__global__ void gather_k_split(const float* __restrict__ QKV, const float* __restrict__ CKV,
                               __nv_bfloat16* __restrict__ Ks)
{
    int idx = blockIdx.x * blockDim.x + threadIdx.x;
    if (idx >= cBH * cNS * cDH) return;
    int d    = idx & (cDH - 1);
    int rest = idx >> 6;
    int j    = rest % cNS;
    int bh   = rest / cNS;
    int b = bh / cH, h = bh % cH;
    float kv;
    if (j < cSC)
        kv = CKV[((size_t)(b * cSC + j)) * (2 * cD) + h * cDH + d];
    else
        kv = QKV[((size_t)(b * cND + (j - cSC))) * (3 * cD) + cD + h * cDH + d];
    __nv_bfloat16 hi = __float2bfloat16(kv);
    __nv_bfloat16 lo = __float2bfloat16(kv - __bfloat162float(hi));
    size_t o = ((size_t)bh * NSP + j) * K3Q + 3 * d;
    Ks[o] = hi; Ks[o + 1] = hi; Ks[o + 2] = lo;
}

__global__ void gather_vt_split(const float* __restrict__ QKV, const float* __restrict__ CKV,
                                __nv_bfloat16* __restrict__ Vts)
{
    int idx = blockIdx.x * blockDim.x + threadIdx.x;
    if (idx >= cBH * cDH * cNS) return;
    int j    = idx % cNS;
    int rest = idx / cNS;
    int d    = rest & (cDH - 1);
    int bh   = rest >> 6;
    int b = bh / cH, h = bh % cH;
    float vv;
    if (j < cSC)
        vv = CKV[((size_t)(b * cSC + j)) * (2 * cD) + cD + h * cDH + d];
    else
        vv = QKV[((size_t)(b * cND + (j - cSC))) * (3 * cD) + 2 * cD + h * cDH + d];
    __nv_bfloat16 hi = __float2bfloat16(vv);
    __nv_bfloat16 lo = __float2bfloat16(vv - __bfloat162float(hi));
    size_t o = ((size_t)bh * cDH + d) * K3AV + 3 * j;
    Vts[o] = hi; Vts[o + 1] = hi; Vts[o + 2] = lo;
}

// ---------------------------------------------------------------------------
// Softmax over padded rows; writes split-bf16 probs [hi,lo,hi] + zero padding
// ---------------------------------------------------------------------------
__global__ __launch_bounds__(256) void softmax_split(
    const float* __restrict__ S, __nv_bfloat16* __restrict__ Ps)
{
    int r  = blockIdx.x;
    int bh = r / cND, m = r % cND;
    const float* p = S + ((size_t)bh * NDP + m) * NSP;
    __nv_bfloat16* out = Ps + ((size_t)bh * NDP + m) * K3AV;
    int tid = threadIdx.x;

    float vals[6];
    float mx = -3.4e38f;
    #pragma unroll
    for (int it = 0; it < 6; it++) {
        int i = tid + it * 256;
        float v = (i < cNS) ? p[i] : -3.4e38f;
        vals[it] = v;
        mx = fmaxf(mx, v);
    }
    __shared__ float sb[8];
    #pragma unroll
    for (int o = 16; o; o >>= 1) mx = fmaxf(mx, __shfl_xor_sync(0xffffffffu, mx, o));
    if ((tid & 31) == 0) sb[tid >> 5] = mx;
    __syncthreads();
    if (tid < 32) {
        float m2 = (tid < 8) ? sb[tid] : -3.4e38f;
        #pragma unroll
        for (int o = 4; o; o >>= 1) m2 = fmaxf(m2, __shfl_xor_sync(0xffffffffu, m2, o));
        if (tid == 0) sb[0] = m2;
    }
    __syncthreads();
    float bmax = sb[0];
    __syncthreads();

    float s = 0.f;
    #pragma unroll
    for (int it = 0; it < 6; it++) {
        int i = tid + it * 256;
        if (i < cNS) {
            float e = __expf(vals[it] - bmax);
            vals[it] = e;
            s += e;
        }
    }
    #pragma unroll
    for (int o = 16; o; o >>= 1) s += __shfl_xor_sync(0xffffffffu, s, o);
    if ((tid & 31) == 0) sb[tid >> 5] = s;
    __syncthreads();
    if (tid < 32) {
        float s2 = (tid < 8) ? sb[tid] : 0.f;
        #pragma unroll
        for (int o = 4; o; o >>= 1) s2 += __shfl_xor_sync(0xffffffffu, s2, o);
        if (tid == 0) sb[0] = s2;
    }
    __syncthreads();
    float inv = 1.0f / sb[0];
    #pragma unroll
    for (int it = 0; it < 6; it++) {
        int i = tid + it * 256;
        if (i >= NSP) continue;
        float v = (i < cNS) ? vals[it] * inv : 0.f;
        __nv_bfloat16 hi = __float2bfloat16(v);
        __nv_bfloat16 lo = __float2bfloat16(v - __bfloat162float(hi));
        out[3 * i] = hi; out[3 * i + 1] = lo; out[3 * i + 2] = hi;
    }
}

// ---------------------------------------------------------------------------
// Launch sequence
// ---------------------------------------------------------------------------
extern "C" void kernel_launch(void* const* d_in, const int* in_sizes, int n_in,
                              void* d_out, int out_size)
{
    (void)in_sizes; (void)n_in; (void)out_size;
    const float* x       = (const float*)d_in[0];
    const float* ctx     = (const float*)d_in[1];
    const float* sos     = (const float*)d_in[2];
    const float* ln1_g   = (const float*)d_in[3];
    const float* ln1_b   = (const float*)d_in[4];
    const float* W_attn  = (const float*)d_in[5];
    const float* b_attn  = (const float*)d_in[6];
    const float* W_ref   = (const float*)d_in[7];
    const float* b_ref   = (const float*)d_in[8];
    const float* W_proj  = (const float*)d_in[9];
    const float* b_proj  = (const float*)d_in[10];
    const float* ln2_g   = (const float*)d_in[11];
    const float* ln2_b   = (const float*)d_in[12];
    const float* W_fc    = (const float*)d_in[13];
    const float* b_fc    = (const float*)d_in[14];
    const float* W_mproj = (const float*)d_in[15];
    const float* b_mproj = (const float*)d_in[16];
    float* out = (float*)d_out;

    float *H, *HL, *QKV, *CKV, *A, *H2, *HL2, *FC, *Sp;
    __nv_bfloat16 *As, *Bs, *Qs, *Ks, *Vts, *Ps;
    cudaGetSymbolAddress((void**)&H,   g_H);
    cudaGetSymbolAddress((void**)&HL,  g_HL);
    cudaGetSymbolAddress((void**)&QKV, g_QKV);
    cudaGetSymbolAddress((void**)&CKV, g_CKV);
    cudaGetSymbolAddress((void**)&A,   g_A);
    cudaGetSymbolAddress((void**)&H2,  g_H2);
    cudaGetSymbolAddress((void**)&HL2, g_HL2);
    cudaGetSymbolAddress((void**)&FC,  g_FC);
    cudaGetSymbolAddress((void**)&Sp,  g_Sp);
    cudaGetSymbolAddress((void**)&As,  g_As);
    cudaGetSymbolAddress((void**)&Bs,  g_Bs);
    cudaGetSymbolAddress((void**)&Qs,  g_Qs);
    cudaGetSymbolAddress((void**)&Ks,  g_Ks);
    cudaGetSymbolAddress((void**)&Vts, g_Vts);
    cudaGetSymbolAddress((void**)&Ps,  g_Ps);

    cudaFuncSetAttribute(tgemm2,     cudaFuncAttributeMaxDynamicSharedMemorySize, T2_SMEM);
    cudaFuncSetAttribute(scores_mma, cudaFuncAttributeMaxDynamicSharedMemorySize, TG_SMEM);
    cudaFuncSetAttribute(av_mma,     cudaFuncAttributeMaxDynamicSharedMemorySize, AV_SMEM);

    // Per-GEMM plane pointers: A planes stride cMPAD*K, B planes stride N*K.
    auto Alo_of = [&](int K) { return As + (size_t)cMPAD * K; };

    // 1. concat(sos, x) + LN1
    ln_kernel<<<cM, 256>>>(x, sos, ln1_g, ln1_b, H, HL, 1);

    // 2. qkv = ln1(h) @ W_attn + b_attn   [2050x2304], K=768
    act_split2<<<(cM * cD / 4 + 255) / 256, 256>>>(HL, As, Alo_of(cD), cM * cD);
    w_split2<<<dim3(3 * cD / 32, cD / 32), 256>>>(W_attn, Bs, Bs + (size_t)3 * cD * cD,
                                                  cD, 3 * cD);
    tgemm2<<<dim3(3 * cD / 128, 17), 256, T2_SMEM>>>(
        As, Alo_of(cD), Bs, Bs + (size_t)3 * cD * cD, b_attn, nullptr, QKV,
        cM, 3 * cD, cD, 0);

    // 3. ckv = context @ W_ref + b_ref    [512x1536], K=768
    act_split2<<<(cMC * cD / 4 + 255) / 256, 256>>>(ctx, As, Alo_of(cD), cMC * cD);
    w_split2<<<dim3(2 * cD / 32, cD / 32), 256>>>(W_ref, Bs, Bs + (size_t)2 * cD * cD,
                                                  cD, 2 * cD);
    tgemm2<<<dim3(2 * cD / 128, 4), 256, T2_SMEM>>>(
        As, Alo_of(cD), Bs, Bs + (size_t)2 * cD * cD, b_ref, nullptr, CKV,
        cMC, 2 * cD, cD, 0);

    // 4. split gathers for attention
    gather_q_split<<<(cBH * cND * cDH + 255) / 256, 256>>>(QKV, Qs);
    gather_k_split<<<(cBH * cNS * cDH + 255) / 256, 256>>>(QKV, CKV, Ks);
    gather_vt_split<<<(cBH * cDH * cNS + 255) / 256, 256>>>(QKV, CKV, Vts);

    // 5. attention on tensor pipe
    scores_mma<<<dim3(NSP / 128, NDP / 128, cBH), 256, TG_SMEM>>>(Qs, Ks, Sp);
    softmax_split<<<cBH * cND, 256>>>(Sp, Ps);
    av_mma<<<dim3(NDP / 128, cBH), 256, AV_SMEM>>>(Ps, Vts, A);

    // 6. h2 = h + attn @ W_proj + b_proj  [2050x768], K=768
    act_split2<<<(cM * cD / 4 + 255) / 256, 256>>>(A, As, Alo_of(cD), cM * cD);
    w_split2<<<dim3(cD / 32, cD / 32), 256>>>(W_proj, Bs, Bs + (size_t)cD * cD,
                                              cD, cD);
    tgemm2<<<dim3(cD / 128, 17), 256, T2_SMEM>>>(
        As, Alo_of(cD), Bs, Bs + (size_t)cD * cD, b_proj, H, H2,
        cM, cD, cD, 2);

    // 7. LN2
    ln_kernel<<<cM, 256>>>(H2, nullptr, ln2_g, ln2_b, nullptr, HL2, 0);

    // 8. fc = gelu(ln2(h2) @ W_fc + b_fc) [2050x3072], K=768
    act_split2<<<(cM * cD / 4 + 255) / 256, 256>>>(HL2, As, Alo_of(cD), cM * cD);
    w_split2<<<dim3(4 * cD / 32, cD / 32), 256>>>(W_fc, Bs, Bs + (size_t)4 * cD * cD,
                                                  cD, 4 * cD);
    tgemm2<<<dim3(4 * cD / 128, 17), 256, T2_SMEM>>>(
        As, Alo_of(cD), Bs, Bs + (size_t)4 * cD * cD, b_fc, nullptr, FC,
        cM, 4 * cD, cD, 1);

    // 9. out = (h2 + fc @ W_mproj + b_mproj)[:, 1:, :]   [2050x768], K=3072
    act_split2<<<(cM * 4 * cD / 4 + 255) / 256, 256>>>(FC, As, Alo_of(4 * cD),
                                                       cM * 4 * cD);
    w_split2<<<dim3(cD / 32, 4 * cD / 32), 256>>>(W_mproj, Bs,
                                                  Bs + (size_t)cD * 4 * cD,
                                                  4 * cD, cD);
    tgemm2<<<dim3(cD / 128, 17), 256, T2_SMEM>>>(
        As, Alo_of(4 * cD), Bs, Bs + (size_t)cD * 4 * cD, b_mproj, H2, out,
        cM, cD, 4 * cD, 3);
}

// round 14
// speedup vs baseline: 1.3714x; 1.0635x over previous
#include <cuda_runtime.h>
#include <cuda_bf16.h>
#include <math.h>
#include <stdint.h>

// ---------------------------------------------------------------------------
// Problem constants (CoconBlock: B=2, S=1024, Sc=256, D=768, H=12, dh=64)
// ---------------------------------------------------------------------------
constexpr int cD   = 768;
constexpr int cH   = 12;
constexpr int cDH  = 64;
constexpr int cB   = 2;
constexpr int cS   = 1024;
constexpr int cSC  = 256;
constexpr int cND  = cS + 1;          // 1025 queries per batch (sos + seq)
constexpr int cNS  = cSC + cND;       // 1281 keys per batch
constexpr int cM   = cB * cND;        // 2050 rows in main activation
constexpr int cMC  = cB * cSC;        // 512 context rows
constexpr int cBH  = cB * cH;         // 24 (batch, head) pairs
constexpr int cMPAD = 2176;           // 17 * 128

// attention padded dims
constexpr int NDP  = 1152;            // 9 * 128 padded queries
constexpr int NSP  = 1408;            // 11 * 128 padded keys
constexpr int K3Q  = 192;             // 3 * dh (split, interleaved format)
constexpr int K3AV = 3 * NSP;         // 4224

// ---------------------------------------------------------------------------
// Scratch (static __device__ arrays, zero-initialized; padding regions are
// never written so they stay zero across graph replays)
// ---------------------------------------------------------------------------
__device__ float g_H  [(size_t)cM * cD];
__device__ float g_HL [(size_t)cM * cD];
__device__ float g_QKV[(size_t)cM * 3 * cD];
__device__ float g_CKV[(size_t)cMC * 2 * cD];
__device__ float g_A  [(size_t)cM * cD];
__device__ float g_H2 [(size_t)cM * cD];
__device__ float g_HL2[(size_t)cM * cD];
__device__ float g_FC [(size_t)cM * 4 * cD];
__device__ float g_Pp [4800000];                             // split-K partials
// hi/lo plane operands for the dense GEMMs
__device__ __nv_bfloat16 g_As[(size_t)2 * cMPAD * 3072];     // A hi|lo planes
__device__ __nv_bfloat16 g_Bs[(size_t)2 * 3072 * 768 + 2 * 768 * 2304];
// attention buffers (interleaved 3-slot format)
__device__ __nv_bfloat16 g_Qs [(size_t)cBH * NDP * K3Q];
__device__ __nv_bfloat16 g_Ks [(size_t)cBH * NSP * K3Q];
__device__ __nv_bfloat16 g_Vts[(size_t)cBH * cDH * K3AV];
__device__ float         g_Sp [(size_t)cBH * NDP * NSP];
__device__ __nv_bfloat16 g_Ps [(size_t)cBH * NDP * K3AV];

// ---------------------------------------------------------------------------
// Small helpers
// ---------------------------------------------------------------------------
__device__ __forceinline__ float gelu_new(float x) {
    float x3 = x * x * x;
    return 0.5f * x * (1.0f + tanhf(0.7978845608028654f * (x + 0.044715f * x3)));
}
__device__ __forceinline__ uint32_t smem_u32(const void* p) {
    uint32_t a;
    asm("{ .reg .u64 t; cvta.to.shared.u64 t, %1; cvt.u32.u64 %0, t; }" : "=r"(a) : "l"(p));
    return a;
}
__device__ __forceinline__ void cp16(uint32_t s, const void* g) {
    asm volatile("cp.async.cg.shared.global [%0], [%1], 16;\n"
                 :: "r"(s), "l"(__cvta_generic_to_global(g)) : "memory");
}
__device__ __forceinline__ void ldsm_x4(uint32_t& r0, uint32_t& r1, uint32_t& r2,
                                        uint32_t& r3, uint32_t addr) {
    asm volatile("ldmatrix.sync.aligned.m8n8.x4.shared.b16 {%0,%1,%2,%3}, [%4];"
                 : "=r"(r0), "=r"(r1), "=r"(r2), "=r"(r3) : "r"(addr));
}
__device__ __forceinline__ void ldsm_x2(uint32_t& r0, uint32_t& r1, uint32_t addr) {
    asm volatile("ldmatrix.sync.aligned.m8n8.x2.shared.b16 {%0,%1}, [%2];"
                 : "=r"(r0), "=r"(r1) : "r"(addr));
}
__device__ __forceinline__ void mma16816(float* c, const uint32_t* a, const uint32_t* b) {
    asm volatile(
        "mma.sync.aligned.m16n8k16.row.col.f32.bf16.bf16.f32 "
        "{%0,%1,%2,%3}, {%4,%5,%6,%7}, {%8,%9}, {%0,%1,%2,%3};"
        : "+f"(c[0]), "+f"(c[1]), "+f"(c[2]), "+f"(c[3])
        : "r"(a[0]), "r"(a[1]), "r"(a[2]), "r"(a[3]), "r"(b[0]), "r"(b[1]));
}

// ---------------------------------------------------------------------------
// Plane-split conversions: X fp32 -> (hi, lo) bf16 planes (lo = x - hi)
// ---------------------------------------------------------------------------
__global__ __launch_bounds__(256) void act_split2(
    const float* __restrict__ X, __nv_bfloat16* __restrict__ Yhi,
    __nv_bfloat16* __restrict__ Ylo, int MK)
{
    int i4 = (blockIdx.x * 256 + threadIdx.x) * 4;
    if (i4 >= MK) return;
    float4 x = *(const float4*)(X + i4);
    float xv[4] = {x.x, x.y, x.z, x.w};
    __nv_bfloat16 h[4], l[4];
    #pragma unroll
    for (int j = 0; j < 4; j++) {
        h[j] = __float2bfloat16(xv[j]);
        l[j] = __float2bfloat16(xv[j] - __bfloat162float(h[j]));
    }
    *(uint64_t*)(Yhi + i4) = *(uint64_t*)h;
    *(uint64_t*)(Ylo + i4) = *(uint64_t*)l;
}

// W [K,N] fp32 -> hi/lo planes [N,K] (transposed)
__global__ __launch_bounds__(256) void w_split2(
    const float* __restrict__ W, __nv_bfloat16* __restrict__ Yhi,
    __nv_bfloat16* __restrict__ Ylo, int K, int N)
{
    __shared__ float t[32][33];
    int k0 = blockIdx.y * 32, n0 = blockIdx.x * 32;
    int tid = threadIdx.x;
    #pragma unroll
    for (int p = 0; p < 4; p++) {
        int idx = p * 256 + tid;
        int kk = idx >> 5, nn = idx & 31;
        t[kk][nn] = W[(size_t)(k0 + kk) * N + n0 + nn];
    }
    __syncthreads();
    #pragma unroll
    for (int p = 0; p < 4; p++) {
        int idx = p * 256 + tid;
        int nn = idx >> 5, kk = idx & 31;
        float x = t[kk][nn];
        __nv_bfloat16 hi = __float2bfloat16(x);
        __nv_bfloat16 lo = __float2bfloat16(x - __bfloat162float(hi));
        size_t o = (size_t)(n0 + nn) * K + (k0 + kk);
        Yhi[o] = hi;
        Ylo[o] = lo;
    }
}

// ---------------------------------------------------------------------------
// Dense HMMA GEMM, hi/lo-plane operands:
//   C = Ahi*Bhi^T + Ahi*Blo^T + Alo*Bhi^T
// 128x128 tile, 8 warps (2x4), chunk = 32 original k, double-buffered,
// pitch 80B, occ 2 enforced by launch_bounds. blockIdx.z = split-K section.
// mode: 0 +bias, 1 +bias+gelu, 2 +bias+R, 3 +bias+R & drop-sos write,
//       4 raw partial -> C + z*M*N (no bias).
// ---------------------------------------------------------------------------
constexpr int T2_PITCH = 80;                      // 64B data + 16B pad
constexpr int T2_PLANE = 128 * T2_PITCH;          // 10240
constexpr int T2_STG   = 4 * T2_PLANE;            // 40960 (Ahi,Alo,Bhi,Blo)
constexpr int T2_SMEM  = 2 * T2_STG + 128;        // 82048

__global__ __launch_bounds__(256, 2) void tgemm2(
    const __nv_bfloat16* __restrict__ Ahi, const __nv_bfloat16* __restrict__ Alo,
    const __nv_bfloat16* __restrict__ Bhi, const __nv_bfloat16* __restrict__ Blo,
    const float* __restrict__ bias, const float* __restrict__ R,
    float* __restrict__ C, int M, int N, int K, int mode)
{
    extern __shared__ char dynraw[];
    char* sb = (char*)(((uintptr_t)dynraw + 127) & ~(uintptr_t)127);
    const uint32_t s0 = smem_u32(sb);

    const int tid  = threadIdx.x;
    const int wid  = tid >> 5;
    const int lane = tid & 31;
    const int g    = lane >> 2;
    const int tg   = lane & 3;
    const int wm   = wid >> 2;
    const int wn   = wid & 3;
    const int row0 = blockIdx.y * 128;
    const int col0 = blockIdx.x * 128;
    const int zsec = K / gridDim.z;
    const int kbase = blockIdx.z * zsec;
    const int nch  = zsec >> 5;                    // 32 original k per chunk

    const int crow = tid >> 2;
    const int cseg = tid & 3;
    const uint32_t so = (uint32_t)(crow * T2_PITCH + cseg * 16);
    const size_t g64 = (size_t)64 * K;
    const __nv_bfloat16* PA_hi = Ahi + (size_t)(row0 + crow) * K + kbase + cseg * 8;
    const __nv_bfloat16* PA_lo = Alo + (size_t)(row0 + crow) * K + kbase + cseg * 8;
    const __nv_bfloat16* PB_hi = Bhi + (size_t)(col0 + crow) * K + kbase + cseg * 8;
    const __nv_bfloat16* PB_lo = Blo + (size_t)(col0 + crow) * K + kbase + cseg * 8;

    const uint32_t aoff = (uint32_t)((wm * 64 + (lane & 15)) * T2_PITCH + (lane >> 4) * 16);
    const uint32_t boff = (uint32_t)((wn * 32 + (lane & 7)) * T2_PITCH + ((lane >> 3) & 1) * 16);

    float c[4][4][4];
    #pragma unroll
    for (int mi = 0; mi < 4; mi++)
        #pragma unroll
        for (int ni = 0; ni < 4; ni++)
            #pragma unroll
            for (int e = 0; e < 4; e++) c[mi][ni][e] = 0.f;

    auto load_chunk = [&](int ch, uint32_t st) {
        int k0 = ch * 32;
        cp16(st + so,                         PA_hi + k0);
        cp16(st + so + 64 * T2_PITCH,         PA_hi + k0 + g64);
        cp16(st + T2_PLANE + so,              PA_lo + k0);
        cp16(st + T2_PLANE + so + 64 * T2_PITCH, PA_lo + k0 + g64);
        cp16(st + 2 * T2_PLANE + so,          PB_hi + k0);
        cp16(st + 2 * T2_PLANE + so + 64 * T2_PITCH, PB_hi + k0 + g64);
        cp16(st + 3 * T2_PLANE + so,          PB_lo + k0);
        cp16(st + 3 * T2_PLANE + so + 64 * T2_PITCH, PB_lo + k0 + g64);
        asm volatile("cp.async.commit_group;" ::: "memory");
    };

    load_chunk(0, s0);

    for (int i = 0; i < nch; i++) {
        const int st = i & 1;
        if (i + 1 < nch) {
            load_chunk(i + 1, s0 + ((i + 1) & 1) * T2_STG);
            asm volatile("cp.async.wait_group 1;" ::: "memory");
        } else {
            asm volatile("cp.async.wait_group 0;" ::: "memory");
        }
        __syncthreads();

        const uint32_t base = s0 + st * T2_STG;
        #pragma unroll
        for (int kg = 0; kg < 2; kg++) {
            const uint32_t ko = kg * 32;
            uint32_t bhi[4][2], blo[4][2], ahi[4][4], alo[4][4];
            #pragma unroll
            for (int ni = 0; ni < 4; ni++)
                ldsm_x2(bhi[ni][0], bhi[ni][1],
                        base + 2 * T2_PLANE + boff + (uint32_t)(ni * 8 * T2_PITCH) + ko);
            #pragma unroll
            for (int mi = 0; mi < 4; mi++)
                ldsm_x4(ahi[mi][0], ahi[mi][1], ahi[mi][2], ahi[mi][3],
                        base + aoff + (uint32_t)(mi * 16 * T2_PITCH) + ko);
            #pragma unroll
            for (int mi = 0; mi < 4; mi++)
                #pragma unroll
                for (int ni = 0; ni < 4; ni++)
                    mma16816(c[mi][ni], ahi[mi], bhi[ni]);
            #pragma unroll
            for (int ni = 0; ni < 4; ni++)
                ldsm_x2(blo[ni][0], blo[ni][1],
                        base + 3 * T2_PLANE + boff + (uint32_t)(ni * 8 * T2_PITCH) + ko);
            #pragma unroll
            for (int mi = 0; mi < 4; mi++)
                #pragma unroll
                for (int ni = 0; ni < 4; ni++)
                    mma16816(c[mi][ni], ahi[mi], blo[ni]);
            #pragma unroll
            for (int mi = 0; mi < 4; mi++)
                ldsm_x4(alo[mi][0], alo[mi][1], alo[mi][2], alo[mi][3],
                        base + T2_PLANE + aoff + (uint32_t)(mi * 16 * T2_PITCH) + ko);
            #pragma unroll
            for (int mi = 0; mi < 4; mi++)
                #pragma unroll
                for (int ni = 0; ni < 4; ni++)
                    mma16816(c[mi][ni], alo[mi], bhi[ni]);
        }
        __syncthreads();
    }

    #pragma unroll
    for (int mi = 0; mi < 4; mi++) {
        #pragma unroll
        for (int half = 0; half < 2; half++) {
            int rg = row0 + wm * 64 + mi * 16 + g + half * 8;
            if (rg >= M) continue;
            if (mode == 4) {
                float* crow4 = C + (size_t)blockIdx.z * M * N + (size_t)rg * N;
                #pragma unroll
                for (int ni = 0; ni < 4; ni++) {
                    int cg = col0 + wn * 32 + ni * 8 + 2 * tg;
                    *(float2*)(crow4 + cg) =
                        make_float2(c[mi][ni][half * 2 + 0], c[mi][ni][half * 2 + 1]);
                }
                continue;
            }
            float* crow2;
            if (mode == 3) {
                int t = rg % cND;
                if (t == 0) continue;
                crow2 = C + ((size_t)((rg / cND) * cS + (t - 1))) * N;
            } else {
                crow2 = C + (size_t)rg * N;
            }
            #pragma unroll
            for (int ni = 0; ni < 4; ni++) {
                int cg = col0 + wn * 32 + ni * 8 + 2 * tg;
                float v0 = c[mi][ni][half * 2 + 0] + __ldg(&bias[cg]);
                float v1 = c[mi][ni][half * 2 + 1] + __ldg(&bias[cg + 1]);
                if (mode == 1) { v0 = gelu_new(v0); v1 = gelu_new(v1); }
                else if (mode >= 2) {
                    v0 += R[(size_t)rg * N + cg];
                    v1 += R[(size_t)rg * N + cg + 1];
                }
                *(float2*)(crow2 + cg) = make_float2(v0, v1);
            }
        }
    }
}

// ---------------------------------------------------------------------------
// combine: C = sum_s P[s] + bias (+R / gelu / sos-drop).  float4 vectorized.
// mode: 0 bias only, 1 +gelu, 2 +R, 3 +R & drop sos row.
// ---------------------------------------------------------------------------
__global__ __launch_bounds__(256) void combine(
    const float* __restrict__ P, const float* __restrict__ bias,
    const float* __restrict__ R, float* __restrict__ C,
    int M, int N, int nsplit, int mode)
{
    int i4 = (blockIdx.x * 256 + threadIdx.x) * 4;
    if (i4 >= M * N) return;
    int r = i4 / N, cc = i4 % N;
    float4 v = *(const float4*)(P + i4);
    for (int s = 1; s < nsplit; s++) {
        float4 u = *(const float4*)(P + (size_t)s * M * N + i4);
        v.x += u.x; v.y += u.y; v.z += u.z; v.w += u.w;
    }
    float4 bb = *(const float4*)(bias + cc);
    v.x += bb.x; v.y += bb.y; v.z += bb.z; v.w += bb.w;
    if (mode == 1) {
        v.x = gelu_new(v.x); v.y = gelu_new(v.y);
        v.z = gelu_new(v.z); v.w = gelu_new(v.w);
    } else if (mode >= 2) {
        float4 rr = *(const float4*)(R + i4);
        v.x += rr.x; v.y += rr.y; v.z += rr.z; v.w += rr.w;
    }
    if (mode == 3) {
        int t = r % cND;
        if (t == 0) return;
        *(float4*)(C + ((size_t)((r / cND) * cS + (t - 1))) * N + cc) = v;
    } else {
        *(float4*)(C + i4) = v;
    }
}

// ---------------------------------------------------------------------------
// scores_mma (R10 mainloop, 3-slot interleaved operands) + early-exit.
// ---------------------------------------------------------------------------
constexpr int TG_PITCH = 144;
constexpr int TG_STG   = 128 * TG_PITCH;      // 18432
constexpr int TG_SMEM  = 4 * TG_STG + 128;

__global__ __launch_bounds__(256, 2) void scores_mma(
    const __nv_bfloat16* __restrict__ Qs, const __nv_bfloat16* __restrict__ Ks,
    float* __restrict__ S)
{
    extern __shared__ char dynraw[];
    char* sb = (char*)(((uintptr_t)dynraw + 127) & ~(uintptr_t)127);
    const uint32_t sA0 = smem_u32(sb);
    const uint32_t sB0 = sA0 + 2 * TG_STG;

    const int tid  = threadIdx.x;
    const int wid  = tid >> 5;
    const int lane = tid & 31;
    const int g    = lane >> 2;
    const int tg   = lane & 3;
    const int wm   = wid >> 2;
    const int wn   = wid & 3;
    const int bh   = blockIdx.z;
    const int row0 = blockIdx.y * 128;
    const int col0 = blockIdx.x * 128;

    float* Sb = S + (size_t)bh * NDP * NSP;

    if (col0 >= row0 + 128 + cSC) {   // fully masked: write -1e4, skip GEMM
        #pragma unroll
        for (int mi = 0; mi < 4; mi++)
            #pragma unroll
            for (int half = 0; half < 2; half++) {
                int rg = row0 + wm * 64 + mi * 16 + g + half * 8;
                float* Sr = Sb + (size_t)rg * NSP;
                #pragma unroll
                for (int ni = 0; ni < 4; ni++) {
                    int cg = col0 + wn * 32 + ni * 8 + 2 * tg;
                    *(float2*)(Sr + cg) = make_float2(-10000.0f, -10000.0f);
                }
            }
        return;
    }

    const __nv_bfloat16* A3 = Qs + (size_t)bh * NDP * K3Q;
    const __nv_bfloat16* B3 = Ks + (size_t)bh * NSP * K3Q;

    uint32_t soff[4];
    const __nv_bfloat16 *Ag[4], *Bg[4];
    #pragma unroll
    for (int p = 0; p < 4; p++) {
        int idx = p * 256 + tid;
        int row = idx >> 3, seg = idx & 7;
        soff[p] = (uint32_t)(row * TG_PITCH + seg * 16);
        Ag[p] = A3 + (size_t)(row0 + row) * K3Q + seg * 8;
        Bg[p] = B3 + (size_t)(col0 + row) * K3Q + seg * 8;
    }
    const uint32_t aoff = (uint32_t)((wm * 64 + (lane & 15)) * TG_PITCH + (lane >> 4) * 16);
    const uint32_t boff = (uint32_t)((wn * 32 + (lane & 7)) * TG_PITCH + ((lane >> 3) & 1) * 16);

    float c[4][4][4];
    #pragma unroll
    for (int mi = 0; mi < 4; mi++)
        #pragma unroll
        for (int ni = 0; ni < 4; ni++)
            #pragma unroll
            for (int e = 0; e < 4; e++) c[mi][ni][e] = 0.f;

    #pragma unroll
    for (int p = 0; p < 4; p++) {
        cp16(sA0 + soff[p], Ag[p]);
        cp16(sB0 + soff[p], Bg[p]);
    }
    asm volatile("cp.async.commit_group;" ::: "memory");

    #pragma unroll
    for (int i = 0; i < 3; i++) {
        const int st = i & 1;
        if (i + 1 < 3) {
            const int st2 = (i + 1) & 1;
            const int ko = (i + 1) * 64;
            #pragma unroll
            for (int p = 0; p < 4; p++) {
                cp16(sA0 + st2 * TG_STG + soff[p], Ag[p] + ko);
                cp16(sB0 + st2 * TG_STG + soff[p], Bg[p] + ko);
            }
            asm volatile("cp.async.commit_group;" ::: "memory");
            asm volatile("cp.async.wait_group 1;" ::: "memory");
        } else {
            asm volatile("cp.async.wait_group 0;" ::: "memory");
        }
        __syncthreads();
        const uint32_t sa = sA0 + st * TG_STG + aoff;
        const uint32_t sbb = sB0 + st * TG_STG + boff;
        #pragma unroll
        for (int ks = 0; ks < 4; ks++) {
            uint32_t a[4][4], b[4][2];
            #pragma unroll
            for (int mi = 0; mi < 4; mi++)
                ldsm_x4(a[mi][0], a[mi][1], a[mi][2], a[mi][3],
                        sa + (uint32_t)(mi * 16 * TG_PITCH + ks * 32));
            #pragma unroll
            for (int ni = 0; ni < 4; ni++)
                ldsm_x2(b[ni][0], b[ni][1],
                        sbb + (uint32_t)(ni * 8 * TG_PITCH + ks * 32));
            #pragma unroll
            for (int mi = 0; mi < 4; mi++)
                #pragma unroll
                for (int ni = 0; ni < 4; ni++)
                    mma16816(c[mi][ni], a[mi], b[ni]);
        }
        __syncthreads();
    }

    const float scale = 0.125f;   // 1/sqrt(64)
    #pragma unroll
    for (int mi = 0; mi < 4; mi++) {
        #pragma unroll
        for (int half = 0; half < 2; half++) {
            int rg = row0 + wm * 64 + mi * 16 + g + half * 8;
            float* Sr = Sb + (size_t)rg * NSP;
            #pragma unroll
            for (int ni = 0; ni < 4; ni++) {
                int cg = col0 + wn * 32 + ni * 8 + 2 * tg;
                float v0 = (cg     <= rg + cSC) ? c[mi][ni][half * 2 + 0] * scale : -10000.0f;
                float v1 = (cg + 1 <= rg + cSC) ? c[mi][ni][half * 2 + 1] * scale : -10000.0f;
                *(float2*)(Sr + cg) = make_float2(v0, v1);
            }
        }
    }
}

// ---------------------------------------------------------------------------
// av_mma (R10 version, unchanged): A_merged = P' x Vt'^T.
// ---------------------------------------------------------------------------
constexpr int AV_BSTG = 64 * TG_PITCH;                  // 9216
constexpr int AV_SMEM = 2 * TG_STG + 2 * AV_BSTG + 128;

__global__ __launch_bounds__(256, 2) void av_mma(
    const __nv_bfloat16* __restrict__ P3, const __nv_bfloat16* __restrict__ V3,
    float* __restrict__ A)
{
    extern __shared__ char dynraw[];
    char* sb = (char*)(((uintptr_t)dynraw + 127) & ~(uintptr_t)127);
    const uint32_t sA0 = smem_u32(sb);
    const uint32_t sB0 = sA0 + 2 * TG_STG;

    const int tid  = threadIdx.x;
    const int wid  = tid >> 5;
    const int lane = tid & 31;
    const int g    = lane >> 2;
    const int tg   = lane & 3;
    const int wm   = wid >> 1;
    const int wn   = wid & 1;
    const int bh   = blockIdx.y;
    const int row0 = blockIdx.x * 128;

    const __nv_bfloat16* A3 = P3 + (size_t)bh * NDP * K3AV;
    const __nv_bfloat16* B3 = V3 + (size_t)bh * cDH * K3AV;

    uint32_t soffA[4];
    const __nv_bfloat16* Ag[4];
    #pragma unroll
    for (int p = 0; p < 4; p++) {
        int idx = p * 256 + tid;
        int row = idx >> 3, seg = idx & 7;
        soffA[p] = (uint32_t)(row * TG_PITCH + seg * 16);
        Ag[p] = A3 + (size_t)(row0 + row) * K3AV + seg * 8;
    }
    uint32_t soffB[2];
    const __nv_bfloat16* Bg[2];
    #pragma unroll
    for (int p = 0; p < 2; p++) {
        int idx = p * 256 + tid;
        int row = idx >> 3, seg = idx & 7;
        soffB[p] = (uint32_t)(row * TG_PITCH + seg * 16);
        Bg[p] = B3 + (size_t)row * K3AV + seg * 8;
    }

    const uint32_t aoff = (uint32_t)((wm * 32 + (lane & 15)) * TG_PITCH + (lane >> 4) * 16);
    const uint32_t boff = (uint32_t)((wn * 32 + (lane & 7)) * TG_PITCH + ((lane >> 3) & 1) * 16);

    float c[2][4][4];
    #pragma unroll
    for (int mi = 0; mi < 2; mi++)
        #pragma unroll
        for (int ni = 0; ni < 4; ni++)
            #pragma unroll
            for (int e = 0; e < 4; e++) c[mi][ni][e] = 0.f;

    const int nch = K3AV >> 6;   // 66

    #pragma unroll
    for (int p = 0; p < 4; p++) cp16(sA0 + soffA[p], Ag[p]);
    #pragma unroll
    for (int p = 0; p < 2; p++) cp16(sB0 + soffB[p], Bg[p]);
    asm volatile("cp.async.commit_group;" ::: "memory");

    for (int i = 0; i < nch; i++) {
        const int st = i & 1;
        if (i + 1 < nch) {
            const int st2 = (i + 1) & 1;
            const int ko = (i + 1) * 64;
            #pragma unroll
            for (int p = 0; p < 4; p++) cp16(sA0 + st2 * TG_STG + soffA[p], Ag[p] + ko);
            #pragma unroll
            for (int p = 0; p < 2; p++) cp16(sB0 + st2 * AV_BSTG + soffB[p], Bg[p] + ko);
            asm volatile("cp.async.commit_group;" ::: "memory");
            asm volatile("cp.async.wait_group 1;" ::: "memory");
        } else {
            asm volatile("cp.async.wait_group 0;" ::: "memory");
        }
        __syncthreads();

        const uint32_t sa = sA0 + st * TG_STG + aoff;
        const uint32_t sbb = sB0 + st * AV_BSTG + boff;
        #pragma unroll
        for (int ks = 0; ks < 4; ks++) {
            uint32_t a[2][4], b[4][2];
            #pragma unroll
            for (int mi = 0; mi < 2; mi++)
                ldsm_x4(a[mi][0], a[mi][1], a[mi][2], a[mi][3],
                        sa + (uint32_t)(mi * 16 * TG_PITCH + ks * 32));
            #pragma unroll
            for (int ni = 0; ni < 4; ni++)
                ldsm_x2(b[ni][0], b[ni][1],
                        sbb + (uint32_t)(ni * 8 * TG_PITCH + ks * 32));
            #pragma unroll
            for (int mi = 0; mi < 2; mi++)
                #pragma unroll
                for (int ni = 0; ni < 4; ni++)
                    mma16816(c[mi][ni], a[mi], b[ni]);
        }
        __syncthreads();
    }

    const int b_ = bh / cH, h = bh % cH;
    #pragma unroll
    for (int mi = 0; mi < 2; mi++) {
        #pragma unroll
        for (int half = 0; half < 2; half++) {
            int rg = row0 + wm * 32 + mi * 16 + g + half * 8;
            if (rg >= cND) continue;
            float* Ar = A + ((size_t)(b_ * cND + rg)) * cD + h * cDH;
            #pragma unroll
            for (int ni = 0; ni < 4; ni++) {
                int cg = wn * 32 + ni * 8 + 2 * tg;
                *(float2*)(Ar + cg) =
                    make_float2(c[mi][ni][half * 2 + 0], c[mi][ni][half * 2 + 1]);
            }
        }
    }
}

// ---------------------------------------------------------------------------
// LayerNorm (optionally fused with sos-concat gather)
// ---------------------------------------------------------------------------
__global__ __launch_bounds__(256) void ln_kernel(
    const float* __restrict__ in, const float* __restrict__ sos,
    const float* __restrict__ gamma, const float* __restrict__ beta,
    float* __restrict__ Hout, float* __restrict__ HLout, int concat)
{
    int r   = blockIdx.x;
    int tid = threadIdx.x;
    const float* src;
    if (concat) {
        int b = r / cND, t = r % cND;
        src = (t == 0) ? sos : in + ((size_t)b * cS + (t - 1)) * cD;
    } else {
        src = in + (size_t)r * cD;
    }
    float v0 = src[tid], v1 = src[tid + 256], v2 = src[tid + 512];
    float s  = v0 + v1 + v2;
    float ss = v0 * v0 + v1 * v1 + v2 * v2;

    __shared__ float sb[8], sb2[8];
    #pragma unroll
    for (int o = 16; o; o >>= 1) {
        s  += __shfl_xor_sync(0xffffffffu, s,  o);
        ss += __shfl_xor_sync(0xffffffffu, ss, o);
    }
    int lane = tid & 31, w = tid >> 5;
    if (lane == 0) { sb[w] = s; sb2[w] = ss; }
    __syncthreads();
    if (tid == 0) {
        float a = 0.f, c = 0.f;
        #pragma unroll
        for (int i = 0; i < 8; i++) { a += sb[i]; c += sb2[i]; }
        sb[0] = a; sb2[0] = c;
    }
    __syncthreads();
    float mean = sb[0] * (1.0f / 768.0f);
    float var  = sb2[0] * (1.0f / 768.0f) - mean * mean;
    float inv  = rsqrtf(var + 1e-5f);

    if (concat) {
        float* hr = Hout + (size_t)r * cD;
        hr[tid] = v0; hr[tid + 256] = v1; hr[tid + 512] = v2;
    }
    float* hlr = HLout + (size_t)r * cD;
    hlr[tid      ] = (v0 - mean) * inv * gamma[tid      ] + beta[tid      ];
    hlr[tid + 256] = (v1 - mean) * inv * gamma[tid + 256] + beta[tid + 256];
    hlr[tid + 512] = (v2 - mean) * inv * gamma[tid + 512] + beta[tid + 512];
}

// ---------------------------------------------------------------------------
// Split gathers for attention (3-slot interleaved format)
// ---------------------------------------------------------------------------
__global__ void gather_q_split(const float* __restrict__ QKV, __nv_bfloat16* __restrict__ Qs)
{
    int idx = blockIdx.x * blockDim.x + threadIdx.x;
    if (idx >= cBH * cND * cDH) return;
    int d    = idx & (cDH - 1);
    int rest = idx >> 6;
    int t    = rest % cND;
    int bh   = rest / cND;
    int b = bh / cH, h = bh % cH;
    float x = QKV[((size_t)(b * cND + t)) * (3 * cD) + h * cDH + d];
    __nv_bfloat16 hi = __float2bfloat16(x);
    __nv_bfloat16 lo = __float2bfloat16(x - __bfloat162float(hi));
    size_t o = ((size_t)bh * NDP + t) * K3Q + 3 * d;
    Qs[o] = hi; Qs[o + 1] = lo; Qs[o + 2] = hi;
}

__global__ void gather_k_split(const float* __restrict__ QKV, const float* __restrict__ CKV,
                               __nv_bfloat16* __restrict__ Ks)
{
    int idx = blockIdx.x * blockDim.x + threadIdx.x;
    if (idx >= cBH * cNS * cDH) return;
    int d    = idx & (cDH - 1);
    int rest = idx >> 6;
    int j    = rest % cNS;
    int bh   = rest / cNS;
    int b = bh / cH, h = bh % cH;
    float kv;
    if (j < cSC)
        kv = CKV[((size_t)(b * cSC + j)) * (2 * cD) + h * cDH + d];
    else
        kv = QKV[((size_t)(b * cND + (j - cSC))) * (3 * cD) + cD + h * cDH + d];
    __nv_bfloat16 hi = __float2bfloat16(kv);
    __nv_bfloat16 lo = __float2bfloat16(kv - __bfloat162float(hi));
    size_t o = ((size_t)bh * NSP + j) * K3Q + 3 * d;
    Ks[o] = hi; Ks[o + 1] = hi; Ks[o + 2] = lo;
}

__global__ void gather_vt_split(const float* __restrict__ QKV, const float* __restrict__ CKV,
                                __nv_bfloat16* __restrict__ Vts)
{
    int idx = blockIdx.x * blockDim.x + threadIdx.x;
    if (idx >= cBH * cDH * cNS) return;
    int j    = idx % cNS;
    int rest = idx / cNS;
    int d    = rest & (cDH - 1);
    int bh   = rest >> 6;
    int b = bh / cH, h = bh % cH;
    float vv;
    if (j < cSC)
        vv = CKV[((size_t)(b * cSC + j)) * (2 * cD) + cD + h * cDH + d];
    else
        vv = QKV[((size_t)(b * cND + (j - cSC))) * (3 * cD) + 2 * cD + h * cDH + d];
    __nv_bfloat16 hi = __float2bfloat16(vv);
    __nv_bfloat16 lo = __float2bfloat16(vv - __bfloat162float(hi));
    size_t o = ((size_t)bh * cDH + d) * K3AV + 3 * j;
    Vts[o] = hi; Vts[o + 1] = hi; Vts[o + 2] = lo;
}

// ---------------------------------------------------------------------------
// Softmax over padded rows; writes split-bf16 probs [hi,lo,hi] + zero padding
// ---------------------------------------------------------------------------
__global__ __launch_bounds__(256) void softmax_split(
    const float* __restrict__ S, __nv_bfloat16* __restrict__ Ps)
{
    int r  = blockIdx.x;
    int bh = r / cND, m = r % cND;
    const float* p = S + ((size_t)bh * NDP + m) * NSP;
    __nv_bfloat16* out = Ps + ((size_t)bh * NDP + m) * K3AV;
    int tid = threadIdx.x;

    float vals[6];
    float mx = -3.4e38f;
    #pragma unroll
    for (int it = 0; it < 6; it++) {
        int i = tid + it * 256;
        float v = (i < cNS) ? p[i] : -3.4e38f;
        vals[it] = v;
        mx = fmaxf(mx, v);
    }
    __shared__ float sb[8];
    #pragma unroll
    for (int o = 16; o; o >>= 1) mx = fmaxf(mx, __shfl_xor_sync(0xffffffffu, mx, o));
    if ((tid & 31) == 0) sb[tid >> 5] = mx;
    __syncthreads();
    if (tid < 32) {
        float m2 = (tid < 8) ? sb[tid] : -3.4e38f;
        #pragma unroll
        for (int o = 4; o; o >>= 1) m2 = fmaxf(m2, __shfl_xor_sync(0xffffffffu, m2, o));
        if (tid == 0) sb[0] = m2;
    }
    __syncthreads();
    float bmax = sb[0];
    __syncthreads();

    float s = 0.f;
    #pragma unroll
    for (int it = 0; it < 6; it++) {
        int i = tid + it * 256;
        if (i < cNS) {
            float e = __expf(vals[it] - bmax);
            vals[it] = e;
            s += e;
        }
    }
    #pragma unroll
    for (int o = 16; o; o >>= 1) s += __shfl_xor_sync(0xffffffffu, s, o);
    if ((tid & 31) == 0) sb[tid >> 5] = s;
    __syncthreads();
    if (tid < 32) {
        float s2 = (tid < 8) ? sb[tid] : 0.f;
        #pragma unroll
        for (int o = 4; o; o >>= 1) s2 += __shfl_xor_sync(0xffffffffu, s2, o);
        if (tid == 0) sb[0] = s2;
    }
    __syncthreads();
    float inv = 1.0f / sb[0];
    #pragma unroll
    for (int it = 0; it < 6; it++) {
        int i = tid + it * 256;
        if (i >= NSP) continue;
        float v = (i < cNS) ? vals[it] * inv : 0.f;
        __nv_bfloat16 hi = __float2bfloat16(v);
        __nv_bfloat16 lo = __float2bfloat16(v - __bfloat162float(hi));
        out[3 * i] = hi; out[3 * i + 1] = lo; out[3 * i + 2] = hi;
    }
}

// ---------------------------------------------------------------------------
// Launch sequence
// ---------------------------------------------------------------------------
extern "C" void kernel_launch(void* const* d_in, const int* in_sizes, int n_in,
                              void* d_out, int out_size)
{
    (void)in_sizes; (void)n_in; (void)out_size;
    const float* x       = (const float*)d_in[0];
    const float* ctx     = (const float*)d_in[1];
    const float* sos     = (const float*)d_in[2];
    const float* ln1_g   = (const float*)d_in[3];
    const float* ln1_b   = (const float*)d_in[4];
    const float* W_attn  = (const float*)d_in[5];
    const float* b_attn  = (const float*)d_in[6];
    const float* W_ref   = (const float*)d_in[7];
    const float* b_ref   = (const float*)d_in[8];
    const float* W_proj  = (const float*)d_in[9];
    const float* b_proj  = (const float*)d_in[10];
    const float* ln2_g   = (const float*)d_in[11];
    const float* ln2_b   = (const float*)d_in[12];
    const float* W_fc    = (const float*)d_in[13];
    const float* b_fc    = (const float*)d_in[14];
    const float* W_mproj = (const float*)d_in[15];
    const float* b_mproj = (const float*)d_in[16];
    float* out = (float*)d_out;

    float *H, *HL, *QKV, *CKV, *A, *H2, *HL2, *FC, *Sp, *Pp;
    __nv_bfloat16 *As, *Bs, *Qs, *Ks, *Vts, *Ps;
    cudaGetSymbolAddress((void**)&H,   g_H);
    cudaGetSymbolAddress((void**)&HL,  g_HL);
    cudaGetSymbolAddress((void**)&QKV, g_QKV);
    cudaGetSymbolAddress((void**)&CKV, g_CKV);
    cudaGetSymbolAddress((void**)&A,   g_A);
    cudaGetSymbolAddress((void**)&H2,  g_H2);
    cudaGetSymbolAddress((void**)&HL2, g_HL2);
    cudaGetSymbolAddress((void**)&FC,  g_FC);
    cudaGetSymbolAddress((void**)&Sp,  g_Sp);
    cudaGetSymbolAddress((void**)&Pp,  g_Pp);
    cudaGetSymbolAddress((void**)&As,  g_As);
    cudaGetSymbolAddress((void**)&Bs,  g_Bs);
    cudaGetSymbolAddress((void**)&Qs,  g_Qs);
    cudaGetSymbolAddress((void**)&Ks,  g_Ks);
    cudaGetSymbolAddress((void**)&Vts, g_Vts);
    cudaGetSymbolAddress((void**)&Ps,  g_Ps);

    cudaFuncSetAttribute(tgemm2,     cudaFuncAttributeMaxDynamicSharedMemorySize, T2_SMEM);
    cudaFuncSetAttribute(scores_mma, cudaFuncAttributeMaxDynamicSharedMemorySize, TG_SMEM);
    cudaFuncSetAttribute(av_mma,     cudaFuncAttributeMaxDynamicSharedMemorySize, AV_SMEM);

    auto Alo_of = [&](int K) { return As + (size_t)cMPAD * K; };

    // 1. concat(sos, x) + LN1
    ln_kernel<<<cM, 256>>>(x, sos, ln1_g, ln1_b, H, HL, 1);

    // 2. qkv = ln1(h) @ W_attn + b_attn   [2050x2304], K=768 (306 CTAs)
    act_split2<<<(cM * cD / 4 + 255) / 256, 256>>>(HL, As, Alo_of(cD), cM * cD);
    w_split2<<<dim3(3 * cD / 32, cD / 32), 256>>>(W_attn, Bs, Bs + (size_t)3 * cD * cD,
                                                  cD, 3 * cD);
    tgemm2<<<dim3(3 * cD / 128, 17, 1), 256, T2_SMEM>>>(
        As, Alo_of(cD), Bs, Bs + (size_t)3 * cD * cD, b_attn, nullptr, QKV,
        cM, 3 * cD, cD, 0);

    // 3. ckv = context @ W_ref + b_ref    [512x1536], K=768, split-K x3 (144 CTAs)
    act_split2<<<(cMC * cD / 4 + 255) / 256, 256>>>(ctx, As, Alo_of(cD), cMC * cD);
    w_split2<<<dim3(2 * cD / 32, cD / 32), 256>>>(W_ref, Bs, Bs + (size_t)2 * cD * cD,
                                                  cD, 2 * cD);
    tgemm2<<<dim3(2 * cD / 128, 4, 3), 256, T2_SMEM>>>(
        As, Alo_of(cD), Bs, Bs + (size_t)2 * cD * cD, b_ref, nullptr, Pp,
        cMC, 2 * cD, cD, 4);
    combine<<<(cMC * 2 * cD / 4 + 255) / 256, 256>>>(Pp, b_ref, nullptr, CKV,
                                                     cMC, 2 * cD, 3, 0);

    // 4. split gathers for attention
    gather_q_split<<<(cBH * cND * cDH + 255) / 256, 256>>>(QKV, Qs);
    gather_k_split<<<(cBH * cNS * cDH + 255) / 256, 256>>>(QKV, CKV, Ks);
    gather_vt_split<<<(cBH * cDH * cNS + 255) / 256, 256>>>(QKV, CKV, Vts);

    // 5. attention on tensor pipe
    scores_mma<<<dim3(NSP / 128, NDP / 128, cBH), 256, TG_SMEM>>>(Qs, Ks, Sp);
    softmax_split<<<cBH * cND, 256>>>(Sp, Ps);
    av_mma<<<dim3(NDP / 128, cBH), 256, AV_SMEM>>>(Ps, Vts, A);

    // 6. h2 = h + attn @ W_proj + b_proj  [2050x768], K=768 (102 CTAs, unsplit)
    act_split2<<<(cM * cD / 4 + 255) / 256, 256>>>(A, As, Alo_of(cD), cM * cD);
    w_split2<<<dim3(cD / 32, cD / 32), 256>>>(W_proj, Bs, Bs + (size_t)cD * cD,
                                              cD, cD);
    tgemm2<<<dim3(cD / 128, 17, 1), 256, T2_SMEM>>>(
        As, Alo_of(cD), Bs, Bs + (size_t)cD * cD, b_proj, H, H2,
        cM, cD, cD, 2);

    // 7. LN2
    ln_kernel<<<cM, 256>>>(H2, nullptr, ln2_g, ln2_b, nullptr, HL2, 0);

    // 8. fc = gelu(ln2(h2) @ W_fc + b_fc) [2050x3072], K=768 (408 CTAs)
    act_split2<<<(cM * cD / 4 + 255) / 256, 256>>>(HL2, As, Alo_of(cD), cM * cD);
    w_split2<<<dim3(4 * cD / 32, cD / 32), 256>>>(W_fc, Bs, Bs + (size_t)4 * cD * cD,
                                                  cD, 4 * cD);
    tgemm2<<<dim3(4 * cD / 128, 17, 1), 256, T2_SMEM>>>(
        As, Alo_of(cD), Bs, Bs + (size_t)4 * cD * cD, b_fc, nullptr, FC,
        cM, 4 * cD, cD, 1);

    // 9. out = (h2 + fc @ W_mproj + b_mproj)[:, 1:, :]  [2050x768], K=3072,
    //    split-K x3 (306 CTAs, nch 96 -> 32)
    act_split2<<<(cM * 4 * cD / 4 + 255) / 256, 256>>>(FC, As, Alo_of(4 * cD),
                                                       cM * 4 * cD);
    w_split2<<<dim3(cD / 32, 4 * cD / 32), 256>>>(W_mproj, Bs,
                                                  Bs + (size_t)cD * 4 * cD,
                                                  4 * cD, cD);
    tgemm2<<<dim3(cD / 128, 17, 3), 256, T2_SMEM>>>(
        As, Alo_of(4 * cD), Bs, Bs + (size_t)cD * 4 * cD, b_mproj, nullptr, Pp,
        cM, cD, 4 * cD, 4);
    combine<<<(cM * cD / 4 + 255) / 256, 256>>>(Pp, b_mproj, H2, out, cM, cD, 3, 3);
}

// round 15
// speedup vs baseline: 1.5066x; 1.0986x over previous
#include <cuda_runtime.h>
#include <cuda_bf16.h>
#include <math.h>
#include <stdint.h>

// ---------------------------------------------------------------------------
// Problem constants (CoconBlock: B=2, S=1024, Sc=256, D=768, H=12, dh=64)
// ---------------------------------------------------------------------------
constexpr int cD   = 768;
constexpr int cH   = 12;
constexpr int cDH  = 64;
constexpr int cB   = 2;
constexpr int cS   = 1024;
constexpr int cSC  = 256;
constexpr int cND  = cS + 1;          // 1025 queries per batch (sos + seq)
constexpr int cNS  = cSC + cND;       // 1281 keys per batch
constexpr int cM   = cB * cND;        // 2050 rows in main activation
constexpr int cMC  = cB * cSC;        // 512 context rows
constexpr int cBH  = cB * cH;         // 24 (batch, head) pairs
constexpr int cMPAD = 2176;           // 17 * 128

// attention padded dims
constexpr int NDP  = 1152;            // 9 * 128 padded queries
constexpr int NSP  = 1408;            // 11 * 128 padded keys
constexpr int K3Q  = 192;             // 3 * dh (interleaved format, scores)

// ---------------------------------------------------------------------------
// Scratch (static __device__ arrays, zero-initialized; padding regions are
// never written so they stay zero across graph replays)
// ---------------------------------------------------------------------------
__device__ float g_H  [(size_t)cM * cD];
__device__ float g_HL [(size_t)cM * cD];
__device__ float g_QKV[(size_t)cM * 3 * cD];
__device__ float g_CKV[(size_t)cMC * 2 * cD];
__device__ float g_A  [(size_t)cM * cD];
__device__ float g_H2 [(size_t)cM * cD];
__device__ float g_HL2[(size_t)cM * cD];
__device__ float g_FC [(size_t)cM * 4 * cD];
__device__ float g_Pp [4800000];                             // split-K partials
// hi/lo plane operands for the dense GEMMs
__device__ __nv_bfloat16 g_As[(size_t)2 * cMPAD * 3072];
__device__ __nv_bfloat16 g_Bs[(size_t)2 * 3072 * 768 + 2 * 768 * 2304];
// attention buffers
__device__ __nv_bfloat16 g_Qs [(size_t)cBH * NDP * K3Q];     // 3-slot (scores)
__device__ __nv_bfloat16 g_Ks [(size_t)cBH * NSP * K3Q];     // 3-slot (scores)
__device__ float         g_Sp [(size_t)cBH * NDP * NSP];
// AV hi/lo planes: P [bh,NDP,NSP] x2 planes; Vt [bh,64,NSP] x2 planes
constexpr size_t PS_PLANE = (size_t)cBH * NDP * NSP;
constexpr size_t VT_PLANE = (size_t)cBH * cDH * NSP;
__device__ __nv_bfloat16 g_Ps [2 * PS_PLANE];
__device__ __nv_bfloat16 g_Vts[2 * VT_PLANE];

// ---------------------------------------------------------------------------
// Small helpers
// ---------------------------------------------------------------------------
__device__ __forceinline__ float gelu_new(float x) {
    float x3 = x * x * x;
    return 0.5f * x * (1.0f + tanhf(0.7978845608028654f * (x + 0.044715f * x3)));
}
__device__ __forceinline__ uint32_t smem_u32(const void* p) {
    uint32_t a;
    asm("{ .reg .u64 t; cvta.to.shared.u64 t, %1; cvt.u32.u64 %0, t; }" : "=r"(a) : "l"(p));
    return a;
}
__device__ __forceinline__ void cp16(uint32_t s, const void* g) {
    asm volatile("cp.async.cg.shared.global [%0], [%1], 16;\n"
                 :: "r"(s), "l"(__cvta_generic_to_global(g)) : "memory");
}
__device__ __forceinline__ void ldsm_x4(uint32_t& r0, uint32_t& r1, uint32_t& r2,
                                        uint32_t& r3, uint32_t addr) {
    asm volatile("ldmatrix.sync.aligned.m8n8.x4.shared.b16 {%0,%1,%2,%3}, [%4];"
                 : "=r"(r0), "=r"(r1), "=r"(r2), "=r"(r3) : "r"(addr));
}
__device__ __forceinline__ void ldsm_x2(uint32_t& r0, uint32_t& r1, uint32_t addr) {
    asm volatile("ldmatrix.sync.aligned.m8n8.x2.shared.b16 {%0,%1}, [%2];"
                 : "=r"(r0), "=r"(r1) : "r"(addr));
}
__device__ __forceinline__ void mma16816(float* c, const uint32_t* a, const uint32_t* b) {
    asm volatile(
        "mma.sync.aligned.m16n8k16.row.col.f32.bf16.bf16.f32 "
        "{%0,%1,%2,%3}, {%4,%5,%6,%7}, {%8,%9}, {%0,%1,%2,%3};"
        : "+f"(c[0]), "+f"(c[1]), "+f"(c[2]), "+f"(c[3])
        : "r"(a[0]), "r"(a[1]), "r"(a[2]), "r"(a[3]), "r"(b[0]), "r"(b[1]));
}

// ---------------------------------------------------------------------------
// Plane-split conversions: X fp32 -> (hi, lo) bf16 planes (lo = x - hi)
// ---------------------------------------------------------------------------
__global__ __launch_bounds__(256) void act_split2(
    const float* __restrict__ X, __nv_bfloat16* __restrict__ Yhi,
    __nv_bfloat16* __restrict__ Ylo, int MK)
{
    int i4 = (blockIdx.x * 256 + threadIdx.x) * 4;
    if (i4 >= MK) return;
    float4 x = *(const float4*)(X + i4);
    float xv[4] = {x.x, x.y, x.z, x.w};
    __nv_bfloat16 h[4], l[4];
    #pragma unroll
    for (int j = 0; j < 4; j++) {
        h[j] = __float2bfloat16(xv[j]);
        l[j] = __float2bfloat16(xv[j] - __bfloat162float(h[j]));
    }
    *(uint64_t*)(Yhi + i4) = *(uint64_t*)h;
    *(uint64_t*)(Ylo + i4) = *(uint64_t*)l;
}

// W [K,N] fp32 -> hi/lo planes [N,K] (transposed)
__global__ __launch_bounds__(256) void w_split2(
    const float* __restrict__ W, __nv_bfloat16* __restrict__ Yhi,
    __nv_bfloat16* __restrict__ Ylo, int K, int N)
{
    __shared__ float t[32][33];
    int k0 = blockIdx.y * 32, n0 = blockIdx.x * 32;
    int tid = threadIdx.x;
    #pragma unroll
    for (int p = 0; p < 4; p++) {
        int idx = p * 256 + tid;
        int kk = idx >> 5, nn = idx & 31;
        t[kk][nn] = W[(size_t)(k0 + kk) * N + n0 + nn];
    }
    __syncthreads();
    #pragma unroll
    for (int p = 0; p < 4; p++) {
        int idx = p * 256 + tid;
        int nn = idx >> 5, kk = idx & 31;
        float x = t[kk][nn];
        __nv_bfloat16 hi = __float2bfloat16(x);
        __nv_bfloat16 lo = __float2bfloat16(x - __bfloat162float(hi));
        size_t o = (size_t)(n0 + nn) * K + (k0 + kk);
        Yhi[o] = hi;
        Ylo[o] = lo;
    }
}

// ---------------------------------------------------------------------------
// Dense HMMA GEMM, hi/lo-plane operands (R13 mainloop + split-K).
// mode: 0 +bias, 1 +bias+gelu, 2 +bias+R, 3 +bias+R & drop-sos write,
//       4 raw partial -> C + z*M*N (no bias).
// ---------------------------------------------------------------------------
constexpr int T2_PITCH = 80;
constexpr int T2_PLANE = 128 * T2_PITCH;          // 10240
constexpr int T2_STG   = 4 * T2_PLANE;            // 40960
constexpr int T2_SMEM  = 2 * T2_STG + 128;

__global__ __launch_bounds__(256, 2) void tgemm2(
    const __nv_bfloat16* __restrict__ Ahi, const __nv_bfloat16* __restrict__ Alo,
    const __nv_bfloat16* __restrict__ Bhi, const __nv_bfloat16* __restrict__ Blo,
    const float* __restrict__ bias, const float* __restrict__ R,
    float* __restrict__ C, int M, int N, int K, int mode)
{
    extern __shared__ char dynraw[];
    char* sb = (char*)(((uintptr_t)dynraw + 127) & ~(uintptr_t)127);
    const uint32_t s0 = smem_u32(sb);

    const int tid  = threadIdx.x;
    const int wid  = tid >> 5;
    const int lane = tid & 31;
    const int g    = lane >> 2;
    const int tg   = lane & 3;
    const int wm   = wid >> 2;
    const int wn   = wid & 3;
    const int row0 = blockIdx.y * 128;
    const int col0 = blockIdx.x * 128;
    const int zsec = K / gridDim.z;
    const int kbase = blockIdx.z * zsec;
    const int nch  = zsec >> 5;

    const int crow = tid >> 2;
    const int cseg = tid & 3;
    const uint32_t so = (uint32_t)(crow * T2_PITCH + cseg * 16);
    const size_t g64 = (size_t)64 * K;
    const __nv_bfloat16* PA_hi = Ahi + (size_t)(row0 + crow) * K + kbase + cseg * 8;
    const __nv_bfloat16* PA_lo = Alo + (size_t)(row0 + crow) * K + kbase + cseg * 8;
    const __nv_bfloat16* PB_hi = Bhi + (size_t)(col0 + crow) * K + kbase + cseg * 8;
    const __nv_bfloat16* PB_lo = Blo + (size_t)(col0 + crow) * K + kbase + cseg * 8;

    const uint32_t aoff = (uint32_t)((wm * 64 + (lane & 15)) * T2_PITCH + (lane >> 4) * 16);
    const uint32_t boff = (uint32_t)((wn * 32 + (lane & 7)) * T2_PITCH + ((lane >> 3) & 1) * 16);

    float c[4][4][4];
    #pragma unroll
    for (int mi = 0; mi < 4; mi++)
        #pragma unroll
        for (int ni = 0; ni < 4; ni++)
            #pragma unroll
            for (int e = 0; e < 4; e++) c[mi][ni][e] = 0.f;

    auto load_chunk = [&](int ch, uint32_t st) {
        int k0 = ch * 32;
        cp16(st + so,                         PA_hi + k0);
        cp16(st + so + 64 * T2_PITCH,         PA_hi + k0 + g64);
        cp16(st + T2_PLANE + so,              PA_lo + k0);
        cp16(st + T2_PLANE + so + 64 * T2_PITCH, PA_lo + k0 + g64);
        cp16(st + 2 * T2_PLANE + so,          PB_hi + k0);
        cp16(st + 2 * T2_PLANE + so + 64 * T2_PITCH, PB_hi + k0 + g64);
        cp16(st + 3 * T2_PLANE + so,          PB_lo + k0);
        cp16(st + 3 * T2_PLANE + so + 64 * T2_PITCH, PB_lo + k0 + g64);
        asm volatile("cp.async.commit_group;" ::: "memory");
    };

    load_chunk(0, s0);

    for (int i = 0; i < nch; i++) {
        const int st = i & 1;
        if (i + 1 < nch) {
            load_chunk(i + 1, s0 + ((i + 1) & 1) * T2_STG);
            asm volatile("cp.async.wait_group 1;" ::: "memory");
        } else {
            asm volatile("cp.async.wait_group 0;" ::: "memory");
        }
        __syncthreads();

        const uint32_t base = s0 + st * T2_STG;
        #pragma unroll
        for (int kg = 0; kg < 2; kg++) {
            const uint32_t ko = kg * 32;
            uint32_t bhi[4][2], blo[4][2], ahi[4][4], alo[4][4];
            #pragma unroll
            for (int ni = 0; ni < 4; ni++)
                ldsm_x2(bhi[ni][0], bhi[ni][1],
                        base + 2 * T2_PLANE + boff + (uint32_t)(ni * 8 * T2_PITCH) + ko);
            #pragma unroll
            for (int mi = 0; mi < 4; mi++)
                ldsm_x4(ahi[mi][0], ahi[mi][1], ahi[mi][2], ahi[mi][3],
                        base + aoff + (uint32_t)(mi * 16 * T2_PITCH) + ko);
            #pragma unroll
            for (int mi = 0; mi < 4; mi++)
                #pragma unroll
                for (int ni = 0; ni < 4; ni++)
                    mma16816(c[mi][ni], ahi[mi], bhi[ni]);
            #pragma unroll
            for (int ni = 0; ni < 4; ni++)
                ldsm_x2(blo[ni][0], blo[ni][1],
                        base + 3 * T2_PLANE + boff + (uint32_t)(ni * 8 * T2_PITCH) + ko);
            #pragma unroll
            for (int mi = 0; mi < 4; mi++)
                #pragma unroll
                for (int ni = 0; ni < 4; ni++)
                    mma16816(c[mi][ni], ahi[mi], blo[ni]);
            #pragma unroll
            for (int mi = 0; mi < 4; mi++)
                ldsm_x4(alo[mi][0], alo[mi][1], alo[mi][2], alo[mi][3],
                        base + T2_PLANE + aoff + (uint32_t)(mi * 16 * T2_PITCH) + ko);
            #pragma unroll
            for (int mi = 0; mi < 4; mi++)
                #pragma unroll
                for (int ni = 0; ni < 4; ni++)
                    mma16816(c[mi][ni], alo[mi], bhi[ni]);
        }
        __syncthreads();
    }

    #pragma unroll
    for (int mi = 0; mi < 4; mi++) {
        #pragma unroll
        for (int half = 0; half < 2; half++) {
            int rg = row0 + wm * 64 + mi * 16 + g + half * 8;
            if (rg >= M) continue;
            if (mode == 4) {
                float* crow4 = C + (size_t)blockIdx.z * M * N + (size_t)rg * N;
                #pragma unroll
                for (int ni = 0; ni < 4; ni++) {
                    int cg = col0 + wn * 32 + ni * 8 + 2 * tg;
                    *(float2*)(crow4 + cg) =
                        make_float2(c[mi][ni][half * 2 + 0], c[mi][ni][half * 2 + 1]);
                }
                continue;
            }
            float* crow2;
            if (mode == 3) {
                int t = rg % cND;
                if (t == 0) continue;
                crow2 = C + ((size_t)((rg / cND) * cS + (t - 1))) * N;
            } else {
                crow2 = C + (size_t)rg * N;
            }
            #pragma unroll
            for (int ni = 0; ni < 4; ni++) {
                int cg = col0 + wn * 32 + ni * 8 + 2 * tg;
                float v0 = c[mi][ni][half * 2 + 0] + __ldg(&bias[cg]);
                float v1 = c[mi][ni][half * 2 + 1] + __ldg(&bias[cg + 1]);
                if (mode == 1) { v0 = gelu_new(v0); v1 = gelu_new(v1); }
                else if (mode >= 2) {
                    v0 += R[(size_t)rg * N + cg];
                    v1 += R[(size_t)rg * N + cg + 1];
                }
                *(float2*)(crow2 + cg) = make_float2(v0, v1);
            }
        }
    }
}

// ---------------------------------------------------------------------------
// combine: C = sum_s P[s] + bias (+R / gelu / sos-drop).  float4 vectorized.
// mode: 0 bias only, 1 +gelu, 2 +R, 3 +R & drop sos row.
// ---------------------------------------------------------------------------
__global__ __launch_bounds__(256) void combine(
    const float* __restrict__ P, const float* __restrict__ bias,
    const float* __restrict__ R, float* __restrict__ C,
    int M, int N, int nsplit, int mode)
{
    int i4 = (blockIdx.x * 256 + threadIdx.x) * 4;
    if (i4 >= M * N) return;
    int r = i4 / N, cc = i4 % N;
    float4 v = *(const float4*)(P + i4);
    for (int s = 1; s < nsplit; s++) {
        float4 u = *(const float4*)(P + (size_t)s * M * N + i4);
        v.x += u.x; v.y += u.y; v.z += u.z; v.w += u.w;
    }
    float4 bb = *(const float4*)(bias + cc);
    v.x += bb.x; v.y += bb.y; v.z += bb.z; v.w += bb.w;
    if (mode == 1) {
        v.x = gelu_new(v.x); v.y = gelu_new(v.y);
        v.z = gelu_new(v.z); v.w = gelu_new(v.w);
    } else if (mode >= 2) {
        float4 rr = *(const float4*)(R + i4);
        v.x += rr.x; v.y += rr.y; v.z += rr.z; v.w += rr.w;
    }
    if (mode == 3) {
        int t = r % cND;
        if (t == 0) return;
        *(float4*)(C + ((size_t)((r / cND) * cS + (t - 1))) * N + cc) = v;
    } else {
        *(float4*)(C + i4) = v;
    }
}

// ---------------------------------------------------------------------------
// scores_mma (3-slot interleaved operands) + early-exit.  Unchanged from R14.
// ---------------------------------------------------------------------------
constexpr int TG_PITCH = 144;
constexpr int TG_STG   = 128 * TG_PITCH;      // 18432
constexpr int TG_SMEM  = 4 * TG_STG + 128;

__global__ __launch_bounds__(256, 2) void scores_mma(
    const __nv_bfloat16* __restrict__ Qs, const __nv_bfloat16* __restrict__ Ks,
    float* __restrict__ S)
{
    extern __shared__ char dynraw[];
    char* sb = (char*)(((uintptr_t)dynraw + 127) & ~(uintptr_t)127);
    const uint32_t sA0 = smem_u32(sb);
    const uint32_t sB0 = sA0 + 2 * TG_STG;

    const int tid  = threadIdx.x;
    const int wid  = tid >> 5;
    const int lane = tid & 31;
    const int g    = lane >> 2;
    const int tg   = lane & 3;
    const int wm   = wid >> 2;
    const int wn   = wid & 3;
    const int bh   = blockIdx.z;
    const int row0 = blockIdx.y * 128;
    const int col0 = blockIdx.x * 128;

    float* Sb = S + (size_t)bh * NDP * NSP;

    if (col0 >= row0 + 128 + cSC) {
        #pragma unroll
        for (int mi = 0; mi < 4; mi++)
            #pragma unroll
            for (int half = 0; half < 2; half++) {
                int rg = row0 + wm * 64 + mi * 16 + g + half * 8;
                float* Sr = Sb + (size_t)rg * NSP;
                #pragma unroll
                for (int ni = 0; ni < 4; ni++) {
                    int cg = col0 + wn * 32 + ni * 8 + 2 * tg;
                    *(float2*)(Sr + cg) = make_float2(-10000.0f, -10000.0f);
                }
            }
        return;
    }

    const __nv_bfloat16* A3 = Qs + (size_t)bh * NDP * K3Q;
    const __nv_bfloat16* B3 = Ks + (size_t)bh * NSP * K3Q;

    uint32_t soff[4];
    const __nv_bfloat16 *Ag[4], *Bg[4];
    #pragma unroll
    for (int p = 0; p < 4; p++) {
        int idx = p * 256 + tid;
        int row = idx >> 3, seg = idx & 7;
        soff[p] = (uint32_t)(row * TG_PITCH + seg * 16);
        Ag[p] = A3 + (size_t)(row0 + row) * K3Q + seg * 8;
        Bg[p] = B3 + (size_t)(col0 + row) * K3Q + seg * 8;
    }
    const uint32_t aoff = (uint32_t)((wm * 64 + (lane & 15)) * TG_PITCH + (lane >> 4) * 16);
    const uint32_t boff = (uint32_t)((wn * 32 + (lane & 7)) * TG_PITCH + ((lane >> 3) & 1) * 16);

    float c[4][4][4];
    #pragma unroll
    for (int mi = 0; mi < 4; mi++)
        #pragma unroll
        for (int ni = 0; ni < 4; ni++)
            #pragma unroll
            for (int e = 0; e < 4; e++) c[mi][ni][e] = 0.f;

    #pragma unroll
    for (int p = 0; p < 4; p++) {
        cp16(sA0 + soff[p], Ag[p]);
        cp16(sB0 + soff[p], Bg[p]);
    }
    asm volatile("cp.async.commit_group;" ::: "memory");

    #pragma unroll
    for (int i = 0; i < 3; i++) {
        const int st = i & 1;
        if (i + 1 < 3) {
            const int st2 = (i + 1) & 1;
            const int ko = (i + 1) * 64;
            #pragma unroll
            for (int p = 0; p < 4; p++) {
                cp16(sA0 + st2 * TG_STG + soff[p], Ag[p] + ko);
                cp16(sB0 + st2 * TG_STG + soff[p], Bg[p] + ko);
            }
            asm volatile("cp.async.commit_group;" ::: "memory");
            asm volatile("cp.async.wait_group 1;" ::: "memory");
        } else {
            asm volatile("cp.async.wait_group 0;" ::: "memory");
        }
        __syncthreads();
        const uint32_t sa = sA0 + st * TG_STG + aoff;
        const uint32_t sbb = sB0 + st * TG_STG + boff;
        #pragma unroll
        for (int ks = 0; ks < 4; ks++) {
            uint32_t a[4][4], b[4][2];
            #pragma unroll
            for (int mi = 0; mi < 4; mi++)
                ldsm_x4(a[mi][0], a[mi][1], a[mi][2], a[mi][3],
                        sa + (uint32_t)(mi * 16 * TG_PITCH + ks * 32));
            #pragma unroll
            for (int ni = 0; ni < 4; ni++)
                ldsm_x2(b[ni][0], b[ni][1],
                        sbb + (uint32_t)(ni * 8 * TG_PITCH + ks * 32));
            #pragma unroll
            for (int mi = 0; mi < 4; mi++)
                #pragma unroll
                for (int ni = 0; ni < 4; ni++)
                    mma16816(c[mi][ni], a[mi], b[ni]);
        }
        __syncthreads();
    }

    const float scale = 0.125f;   // 1/sqrt(64)
    #pragma unroll
    for (int mi = 0; mi < 4; mi++) {
        #pragma unroll
        for (int half = 0; half < 2; half++) {
            int rg = row0 + wm * 64 + mi * 16 + g + half * 8;
            float* Sr = Sb + (size_t)rg * NSP;
            #pragma unroll
            for (int ni = 0; ni < 4; ni++) {
                int cg = col0 + wn * 32 + ni * 8 + 2 * tg;
                float v0 = (cg     <= rg + cSC) ? c[mi][ni][half * 2 + 0] * scale : -10000.0f;
                float v1 = (cg + 1 <= rg + cSC) ? c[mi][ni][half * 2 + 1] * scale : -10000.0f;
                *(float2*)(Sr + cg) = make_float2(v0, v1);
            }
        }
    }
}

// ---------------------------------------------------------------------------
// av_mma2: hi/lo-plane AV.  A = P planes [NDP, NSP], B = Vt planes [64, NSP].
// 128x64 tile, 8 warps 4x2, chunk = 32 k (nch = 44), double-buffered,
// pitch 80B.  O = Phi*Vhi + Phi*Vlo + Plo*Vhi.
// ---------------------------------------------------------------------------
constexpr int AV2_APL  = 128 * T2_PITCH;          // 10240
constexpr int AV2_BPL  = 64 * T2_PITCH;           // 5120
constexpr int AV2_STG  = 2 * AV2_APL + 2 * AV2_BPL;   // 30720
constexpr int AV2_SMEM = 2 * AV2_STG + 128;           // 61568

__global__ __launch_bounds__(256, 2) void av_mma2(
    const __nv_bfloat16* __restrict__ P2, const __nv_bfloat16* __restrict__ V2,
    float* __restrict__ A)
{
    extern __shared__ char dynraw[];
    char* sb = (char*)(((uintptr_t)dynraw + 127) & ~(uintptr_t)127);
    const uint32_t s0 = smem_u32(sb);

    const int tid  = threadIdx.x;
    const int wid  = tid >> 5;
    const int lane = tid & 31;
    const int g    = lane >> 2;
    const int tg   = lane & 3;
    const int wm   = wid >> 1;          // 0..3 (32 rows each)
    const int wn   = wid & 1;           // 0..1 (32 cols each)
    const int bh   = blockIdx.y;
    const int row0 = blockIdx.x * 128;

    const __nv_bfloat16* Phi = P2 + (size_t)bh * NDP * NSP;
    const __nv_bfloat16* Plo = Phi + PS_PLANE;
    const __nv_bfloat16* Vhi = V2 + (size_t)bh * cDH * NSP;
    const __nv_bfloat16* Vlo = Vhi + VT_PLANE;

    // A planes: 128 rows x 4 segs = 512 tasks -> 2/thread/plane
    const int arow = tid >> 1;                       // 0..127
    const int aseg2 = (tid & 1) * 2;                 // seg pairs {0,1} or {2,3}
    // B planes: 64 rows x 4 segs = 256 tasks -> 1/thread/plane
    const int brow = tid >> 2;                       // 0..63
    const int bseg = tid & 3;

    const __nv_bfloat16* PAhi = Phi + (size_t)(row0 + arow) * NSP + aseg2 * 8;
    const __nv_bfloat16* PAlo = Plo + (size_t)(row0 + arow) * NSP + aseg2 * 8;
    const __nv_bfloat16* PBhi = Vhi + (size_t)brow * NSP + bseg * 8;
    const __nv_bfloat16* PBlo = Vlo + (size_t)brow * NSP + bseg * 8;
    const uint32_t soa = (uint32_t)(arow * T2_PITCH + aseg2 * 16);
    const uint32_t sob = (uint32_t)(brow * T2_PITCH + bseg * 16);

    const uint32_t aoff = (uint32_t)((wm * 32 + (lane & 15)) * T2_PITCH + (lane >> 4) * 16);
    const uint32_t boff = (uint32_t)((wn * 32 + (lane & 7)) * T2_PITCH + ((lane >> 3) & 1) * 16);

    float c[2][4][4];
    #pragma unroll
    for (int mi = 0; mi < 2; mi++)
        #pragma unroll
        for (int ni = 0; ni < 4; ni++)
            #pragma unroll
            for (int e = 0; e < 4; e++) c[mi][ni][e] = 0.f;

    const int nch = NSP >> 5;    // 44

    auto load_chunk = [&](int ch, uint32_t st) {
        int k0 = ch * 32;
        cp16(st + soa,                   PAhi + k0);
        cp16(st + soa + 16,              PAhi + k0 + 8);
        cp16(st + AV2_APL + soa,         PAlo + k0);
        cp16(st + AV2_APL + soa + 16,    PAlo + k0 + 8);
        cp16(st + 2 * AV2_APL + sob,            PBhi + k0);
        cp16(st + 2 * AV2_APL + AV2_BPL + sob,  PBlo + k0);
        asm volatile("cp.async.commit_group;" ::: "memory");
    };

    load_chunk(0, s0);

    for (int i = 0; i < nch; i++) {
        const int st = i & 1;
        if (i + 1 < nch) {
            load_chunk(i + 1, s0 + ((i + 1) & 1) * AV2_STG);
            asm volatile("cp.async.wait_group 1;" ::: "memory");
        } else {
            asm volatile("cp.async.wait_group 0;" ::: "memory");
        }
        __syncthreads();

        const uint32_t base = s0 + st * AV2_STG;
        #pragma unroll
        for (int kg = 0; kg < 2; kg++) {
            const uint32_t ko = kg * 32;
            uint32_t bhi[4][2], blo[4][2], ahi[2][4], alo[2][4];
            #pragma unroll
            for (int ni = 0; ni < 4; ni++)
                ldsm_x2(bhi[ni][0], bhi[ni][1],
                        base + 2 * AV2_APL + boff + (uint32_t)(ni * 8 * T2_PITCH) + ko);
            #pragma unroll
            for (int mi = 0; mi < 2; mi++)
                ldsm_x4(ahi[mi][0], ahi[mi][1], ahi[mi][2], ahi[mi][3],
                        base + aoff + (uint32_t)(mi * 16 * T2_PITCH) + ko);
            #pragma unroll
            for (int mi = 0; mi < 2; mi++)
                #pragma unroll
                for (int ni = 0; ni < 4; ni++)
                    mma16816(c[mi][ni], ahi[mi], bhi[ni]);
            #pragma unroll
            for (int ni = 0; ni < 4; ni++)
                ldsm_x2(blo[ni][0], blo[ni][1],
                        base + 2 * AV2_APL + AV2_BPL + boff + (uint32_t)(ni * 8 * T2_PITCH) + ko);
            #pragma unroll
            for (int mi = 0; mi < 2; mi++)
                #pragma unroll
                for (int ni = 0; ni < 4; ni++)
                    mma16816(c[mi][ni], ahi[mi], blo[ni]);
            #pragma unroll
            for (int mi = 0; mi < 2; mi++)
                ldsm_x4(alo[mi][0], alo[mi][1], alo[mi][2], alo[mi][3],
                        base + AV2_APL + aoff + (uint32_t)(mi * 16 * T2_PITCH) + ko);
            #pragma unroll
            for (int mi = 0; mi < 2; mi++)
                #pragma unroll
                for (int ni = 0; ni < 4; ni++)
                    mma16816(c[mi][ni], alo[mi], bhi[ni]);
        }
        __syncthreads();
    }

    const int b_ = bh / cH, h = bh % cH;
    #pragma unroll
    for (int mi = 0; mi < 2; mi++) {
        #pragma unroll
        for (int half = 0; half < 2; half++) {
            int rg = row0 + wm * 32 + mi * 16 + g + half * 8;
            if (rg >= cND) continue;
            float* Ar = A + ((size_t)(b_ * cND + rg)) * cD + h * cDH;
            #pragma unroll
            for (int ni = 0; ni < 4; ni++) {
                int cg = wn * 32 + ni * 8 + 2 * tg;
                *(float2*)(Ar + cg) =
                    make_float2(c[mi][ni][half * 2 + 0], c[mi][ni][half * 2 + 1]);
            }
        }
    }
}

// ---------------------------------------------------------------------------
// LayerNorm (optionally fused with sos-concat gather)
// ---------------------------------------------------------------------------
__global__ __launch_bounds__(256) void ln_kernel(
    const float* __restrict__ in, const float* __restrict__ sos,
    const float* __restrict__ gamma, const float* __restrict__ beta,
    float* __restrict__ Hout, float* __restrict__ HLout, int concat)
{
    int r   = blockIdx.x;
    int tid = threadIdx.x;
    const float* src;
    if (concat) {
        int b = r / cND, t = r % cND;
        src = (t == 0) ? sos : in + ((size_t)b * cS + (t - 1)) * cD;
    } else {
        src = in + (size_t)r * cD;
    }
    float v0 = src[tid], v1 = src[tid + 256], v2 = src[tid + 512];
    float s  = v0 + v1 + v2;
    float ss = v0 * v0 + v1 * v1 + v2 * v2;

    __shared__ float sb[8], sb2[8];
    #pragma unroll
    for (int o = 16; o; o >>= 1) {
        s  += __shfl_xor_sync(0xffffffffu, s,  o);
        ss += __shfl_xor_sync(0xffffffffu, ss, o);
    }
    int lane = tid & 31, w = tid >> 5;
    if (lane == 0) { sb[w] = s; sb2[w] = ss; }
    __syncthreads();
    if (tid == 0) {
        float a = 0.f, c = 0.f;
        #pragma unroll
        for (int i = 0; i < 8; i++) { a += sb[i]; c += sb2[i]; }
        sb[0] = a; sb2[0] = c;
    }
    __syncthreads();
    float mean = sb[0] * (1.0f / 768.0f);
    float var  = sb2[0] * (1.0f / 768.0f) - mean * mean;
    float inv  = rsqrtf(var + 1e-5f);

    if (concat) {
        float* hr = Hout + (size_t)r * cD;
        hr[tid] = v0; hr[tid + 256] = v1; hr[tid + 512] = v2;
    }
    float* hlr = HLout + (size_t)r * cD;
    hlr[tid      ] = (v0 - mean) * inv * gamma[tid      ] + beta[tid      ];
    hlr[tid + 256] = (v1 - mean) * inv * gamma[tid + 256] + beta[tid + 256];
    hlr[tid + 512] = (v2 - mean) * inv * gamma[tid + 512] + beta[tid + 512];
}

// ---------------------------------------------------------------------------
// Gathers for attention: Q/K in 3-slot interleaved (scores), Vt in hi/lo planes
// ---------------------------------------------------------------------------
__global__ void gather_q_split(const float* __restrict__ QKV, __nv_bfloat16* __restrict__ Qs)
{
    int idx = blockIdx.x * blockDim.x + threadIdx.x;
    if (idx >= cBH * cND * cDH) return;
    int d    = idx & (cDH - 1);
    int rest = idx >> 6;
    int t    = rest % cND;
    int bh   = rest / cND;
    int b = bh / cH, h = bh % cH;
    float x = QKV[((size_t)(b * cND + t)) * (3 * cD) + h * cDH + d];
    __nv_bfloat16 hi = __float2bfloat16(x);
    __nv_bfloat16 lo = __float2bfloat16(x - __bfloat162float(hi));
    size_t o = ((size_t)bh * NDP + t) * K3Q + 3 * d;
    Qs[o] = hi; Qs[o + 1] = lo; Qs[o + 2] = hi;
}

__global__ void gather_k_split(const float* __restrict__ QKV, const float* __restrict__ CKV,
                               __nv_bfloat16* __restrict__ Ks)
{
    int idx = blockIdx.x * blockDim.x + threadIdx.x;
    if (idx >= cBH * cNS * cDH) return;
    int d    = idx & (cDH - 1);
    int rest = idx >> 6;
    int j    = rest % cNS;
    int bh   = rest / cNS;
    int b = bh / cH, h = bh % cH;
    float kv;
    if (j < cSC)
        kv = CKV[((size_t)(b * cSC + j)) * (2 * cD) + h * cDH + d];
    else
        kv = QKV[((size_t)(b * cND + (j - cSC))) * (3 * cD) + cD + h * cDH + d];
    __nv_bfloat16 hi = __float2bfloat16(kv);
    __nv_bfloat16 lo = __float2bfloat16(kv - __bfloat162float(hi));
    size_t o = ((size_t)bh * NSP + j) * K3Q + 3 * d;
    Ks[o] = hi; Ks[o + 1] = hi; Ks[o + 2] = lo;
}

// V^T hi/lo planes: Vhi/Vlo[bh][d][j]
__global__ void gather_vt_split2(const float* __restrict__ QKV, const float* __restrict__ CKV,
                                 __nv_bfloat16* __restrict__ Vt)
{
    int idx = blockIdx.x * blockDim.x + threadIdx.x;
    if (idx >= cBH * cDH * cNS) return;
    int j    = idx % cNS;
    int rest = idx / cNS;
    int d    = rest & (cDH - 1);
    int bh   = rest >> 6;
    int b = bh / cH, h = bh % cH;
    float vv;
    if (j < cSC)
        vv = CKV[((size_t)(b * cSC + j)) * (2 * cD) + cD + h * cDH + d];
    else
        vv = QKV[((size_t)(b * cND + (j - cSC))) * (3 * cD) + 2 * cD + h * cDH + d];
    __nv_bfloat16 hi = __float2bfloat16(vv);
    __nv_bfloat16 lo = __float2bfloat16(vv - __bfloat162float(hi));
    size_t o = ((size_t)bh * cDH + d) * NSP + j;
    Vt[o] = hi;
    Vt[o + VT_PLANE] = lo;
}

// ---------------------------------------------------------------------------
// Softmax; writes hi/lo plane probs (+ zero key-padding)
// ---------------------------------------------------------------------------
__global__ __launch_bounds__(256) void softmax_split2(
    const float* __restrict__ S, __nv_bfloat16* __restrict__ P2)
{
    int r  = blockIdx.x;
    int bh = r / cND, m = r % cND;
    const float* p = S + ((size_t)bh * NDP + m) * NSP;
    __nv_bfloat16* ohi = P2 + ((size_t)bh * NDP + m) * NSP;
    __nv_bfloat16* olo = ohi + PS_PLANE;
    int tid = threadIdx.x;

    float vals[6];
    float mx = -3.4e38f;
    #pragma unroll
    for (int it = 0; it < 6; it++) {
        int i = tid + it * 256;
        float v = (i < cNS) ? p[i] : -3.4e38f;
        vals[it] = v;
        mx = fmaxf(mx, v);
    }
    __shared__ float sb[8];
    #pragma unroll
    for (int o = 16; o; o >>= 1) mx = fmaxf(mx, __shfl_xor_sync(0xffffffffu, mx, o));
    if ((tid & 31) == 0) sb[tid >> 5] = mx;
    __syncthreads();
    if (tid < 32) {
        float m2 = (tid < 8) ? sb[tid] : -3.4e38f;
        #pragma unroll
        for (int o = 4; o; o >>= 1) m2 = fmaxf(m2, __shfl_xor_sync(0xffffffffu, m2, o));
        if (tid == 0) sb[0] = m2;
    }
    __syncthreads();
    float bmax = sb[0];
    __syncthreads();

    float s = 0.f;
    #pragma unroll
    for (int it = 0; it < 6; it++) {
        int i = tid + it * 256;
        if (i < cNS) {
            float e = __expf(vals[it] - bmax);
            vals[it] = e;
            s += e;
        }
    }
    #pragma unroll
    for (int o = 16; o; o >>= 1) s += __shfl_xor_sync(0xffffffffu, s, o);
    if ((tid & 31) == 0) sb[tid >> 5] = s;
    __syncthreads();
    if (tid < 32) {
        float s2 = (tid < 8) ? sb[tid] : 0.f;
        #pragma unroll
        for (int o = 4; o; o >>= 1) s2 += __shfl_xor_sync(0xffffffffu, s2, o);
        if (tid == 0) sb[0] = s2;
    }
    __syncthreads();
    float inv = 1.0f / sb[0];
    #pragma unroll
    for (int it = 0; it < 6; it++) {
        int i = tid + it * 256;
        if (i >= NSP) continue;
        float v = (i < cNS) ? vals[it] * inv : 0.f;
        __nv_bfloat16 hi = __float2bfloat16(v);
        __nv_bfloat16 lo = __float2bfloat16(v - __bfloat162float(hi));
        ohi[i] = hi;
        olo[i] = lo;
    }
}

// ---------------------------------------------------------------------------
// Launch sequence
// ---------------------------------------------------------------------------
extern "C" void kernel_launch(void* const* d_in, const int* in_sizes, int n_in,
                              void* d_out, int out_size)
{
    (void)in_sizes; (void)n_in; (void)out_size;
    const float* x       = (const float*)d_in[0];
    const float* ctx     = (const float*)d_in[1];
    const float* sos     = (const float*)d_in[2];
    const float* ln1_g   = (const float*)d_in[3];
    const float* ln1_b   = (const float*)d_in[4];
    const float* W_attn  = (const float*)d_in[5];
    const float* b_attn  = (const float*)d_in[6];
    const float* W_ref   = (const float*)d_in[7];
    const float* b_ref   = (const float*)d_in[8];
    const float* W_proj  = (const float*)d_in[9];
    const float* b_proj  = (const float*)d_in[10];
    const float* ln2_g   = (const float*)d_in[11];
    const float* ln2_b   = (const float*)d_in[12];
    const float* W_fc    = (const float*)d_in[13];
    const float* b_fc    = (const float*)d_in[14];
    const float* W_mproj = (const float*)d_in[15];
    const float* b_mproj = (const float*)d_in[16];
    float* out = (float*)d_out;

    float *H, *HL, *QKV, *CKV, *A, *H2, *HL2, *FC, *Sp, *Pp;
    __nv_bfloat16 *As, *Bs, *Qs, *Ks, *Vts, *Ps;
    cudaGetSymbolAddress((void**)&H,   g_H);
    cudaGetSymbolAddress((void**)&HL,  g_HL);
    cudaGetSymbolAddress((void**)&QKV, g_QKV);
    cudaGetSymbolAddress((void**)&CKV, g_CKV);
    cudaGetSymbolAddress((void**)&A,   g_A);
    cudaGetSymbolAddress((void**)&H2,  g_H2);
    cudaGetSymbolAddress((void**)&HL2, g_HL2);
    cudaGetSymbolAddress((void**)&FC,  g_FC);
    cudaGetSymbolAddress((void**)&Sp,  g_Sp);
    cudaGetSymbolAddress((void**)&Pp,  g_Pp);
    cudaGetSymbolAddress((void**)&As,  g_As);
    cudaGetSymbolAddress((void**)&Bs,  g_Bs);
    cudaGetSymbolAddress((void**)&Qs,  g_Qs);
    cudaGetSymbolAddress((void**)&Ks,  g_Ks);
    cudaGetSymbolAddress((void**)&Vts, g_Vts);
    cudaGetSymbolAddress((void**)&Ps,  g_Ps);

    cudaFuncSetAttribute(tgemm2,     cudaFuncAttributeMaxDynamicSharedMemorySize, T2_SMEM);
    cudaFuncSetAttribute(scores_mma, cudaFuncAttributeMaxDynamicSharedMemorySize, TG_SMEM);
    cudaFuncSetAttribute(av_mma2,    cudaFuncAttributeMaxDynamicSharedMemorySize, AV2_SMEM);

    auto Alo_of = [&](int K) { return As + (size_t)cMPAD * K; };

    // 1. concat(sos, x) + LN1
    ln_kernel<<<cM, 256>>>(x, sos, ln1_g, ln1_b, H, HL, 1);

    // 2. qkv = ln1(h) @ W_attn + b_attn   [2050x2304], K=768 (306 CTAs)
    act_split2<<<(cM * cD / 4 + 255) / 256, 256>>>(HL, As, Alo_of(cD), cM * cD);
    w_split2<<<dim3(3 * cD / 32, cD / 32), 256>>>(W_attn, Bs, Bs + (size_t)3 * cD * cD,
                                                  cD, 3 * cD);
    tgemm2<<<dim3(3 * cD / 128, 17, 1), 256, T2_SMEM>>>(
        As, Alo_of(cD), Bs, Bs + (size_t)3 * cD * cD, b_attn, nullptr, QKV,
        cM, 3 * cD, cD, 0);

    // 3. ckv = context @ W_ref + b_ref    [512x1536], K=768, split-K x3 (144 CTAs)
    act_split2<<<(cMC * cD / 4 + 255) / 256, 256>>>(ctx, As, Alo_of(cD), cMC * cD);
    w_split2<<<dim3(2 * cD / 32, cD / 32), 256>>>(W_ref, Bs, Bs + (size_t)2 * cD * cD,
                                                  cD, 2 * cD);
    tgemm2<<<dim3(2 * cD / 128, 4, 3), 256, T2_SMEM>>>(
        As, Alo_of(cD), Bs, Bs + (size_t)2 * cD * cD, b_ref, nullptr, Pp,
        cMC, 2 * cD, cD, 4);
    combine<<<(cMC * 2 * cD / 4 + 255) / 256, 256>>>(Pp, b_ref, nullptr, CKV,
                                                     cMC, 2 * cD, 3, 0);

    // 4. gathers for attention
    gather_q_split<<<(cBH * cND * cDH + 255) / 256, 256>>>(QKV, Qs);
    gather_k_split<<<(cBH * cNS * cDH + 255) / 256, 256>>>(QKV, CKV, Ks);
    gather_vt_split2<<<(cBH * cDH * cNS + 255) / 256, 256>>>(QKV, CKV, Vts);

    // 5. attention on tensor pipe
    scores_mma<<<dim3(NSP / 128, NDP / 128, cBH), 256, TG_SMEM>>>(Qs, Ks, Sp);
    softmax_split2<<<cBH * cND, 256>>>(Sp, Ps);
    av_mma2<<<dim3(NDP / 128, cBH), 256, AV2_SMEM>>>(Ps, Vts, A);

    // 6. h2 = h + attn @ W_proj + b_proj  [2050x768], K=768, split-K x3 (306 CTAs)
    act_split2<<<(cM * cD / 4 + 255) / 256, 256>>>(A, As, Alo_of(cD), cM * cD);
    w_split2<<<dim3(cD / 32, cD / 32), 256>>>(W_proj, Bs, Bs + (size_t)cD * cD,
                                              cD, cD);
    tgemm2<<<dim3(cD / 128, 17, 3), 256, T2_SMEM>>>(
        As, Alo_of(cD), Bs, Bs + (size_t)cD * cD, b_proj, nullptr, Pp,
        cM, cD, cD, 4);
    combine<<<(cM * cD / 4 + 255) / 256, 256>>>(Pp, b_proj, H, H2, cM, cD, 3, 2);

    // 7. LN2
    ln_kernel<<<cM, 256>>>(H2, nullptr, ln2_g, ln2_b, nullptr, HL2, 0);

    // 8. fc = gelu(ln2(h2) @ W_fc + b_fc) [2050x3072], K=768 (408 CTAs)
    act_split2<<<(cM * cD / 4 + 255) / 256, 256>>>(HL2, As, Alo_of(cD), cM * cD);
    w_split2<<<dim3(4 * cD / 32, cD / 32), 256>>>(W_fc, Bs, Bs + (size_t)4 * cD * cD,
                                                  cD, 4 * cD);
    tgemm2<<<dim3(4 * cD / 128, 17, 1), 256, T2_SMEM>>>(
        As, Alo_of(cD), Bs, Bs + (size_t)4 * cD * cD, b_fc, nullptr, FC,
        cM, 4 * cD, cD, 1);

    // 9. out = (h2 + fc @ W_mproj + b_mproj)[:, 1:, :]  [2050x768], K=3072,
    //    split-K x3 (306 CTAs)
    act_split2<<<(cM * 4 * cD / 4 + 255) / 256, 256>>>(FC, As, Alo_of(4 * cD),
                                                       cM * 4 * cD);
    w_split2<<<dim3(cD / 32, 4 * cD / 32), 256>>>(W_mproj, Bs,
                                                  Bs + (size_t)cD * 4 * cD,
                                                  4 * cD, cD);
    tgemm2<<<dim3(cD / 128, 17, 3), 256, T2_SMEM>>>(
        As, Alo_of(4 * cD), Bs, Bs + (size_t)cD * 4 * cD, b_mproj, nullptr, Pp,
        cM, cD, 4 * cD, 4);
    combine<<<(cM * cD / 4 + 255) / 256, 256>>>(Pp, b_mproj, H2, out, cM, cD, 3, 3);
}

// round 16
// speedup vs baseline: 1.5896x; 1.0551x over previous
#include <cuda_runtime.h>
#include <cuda_bf16.h>
#include <math.h>
#include <stdint.h>

// ---------------------------------------------------------------------------
// Problem constants (CoconBlock: B=2, S=1024, Sc=256, D=768, H=12, dh=64)
// ---------------------------------------------------------------------------
constexpr int cD   = 768;
constexpr int cH   = 12;
constexpr int cDH  = 64;
constexpr int cB   = 2;
constexpr int cS   = 1024;
constexpr int cSC  = 256;
constexpr int cND  = cS + 1;          // 1025 queries per batch (sos + seq)
constexpr int cNS  = cSC + cND;       // 1281 keys per batch
constexpr int cM   = cB * cND;        // 2050 rows in main activation
constexpr int cMC  = cB * cSC;        // 512 context rows
constexpr int cBH  = cB * cH;         // 24 (batch, head) pairs
constexpr int cMPAD = 2176;           // 17 * 128

// attention padded dims
constexpr int NDP  = 1152;            // 9 * 128 padded queries
constexpr int NSP  = 1408;            // 11 * 128 padded keys
constexpr int K3Q  = 192;             // 3 * dh (interleaved format, scores)

// ---------------------------------------------------------------------------
// Scratch (static __device__ arrays, zero-initialized; padding regions are
// never written so they stay zero across graph replays)
// ---------------------------------------------------------------------------
__device__ float g_H  [(size_t)cM * cD];
__device__ float g_QKV[(size_t)cM * 3 * cD];
__device__ float g_CKV[(size_t)cMC * 2 * cD];
__device__ float g_H2 [(size_t)cM * cD];
__device__ float g_Pp [12600000];                            // split-K partials
// hi/lo plane operands for the dense GEMMs
__device__ __nv_bfloat16 g_As[(size_t)2 * cMPAD * 3072];
__device__ __nv_bfloat16 g_Bs[(size_t)2 * 3072 * 768 + 2 * 768 * 2304];
// attention buffers
__device__ __nv_bfloat16 g_Qs [(size_t)cBH * NDP * K3Q];     // 3-slot (scores)
__device__ __nv_bfloat16 g_Ks [(size_t)cBH * NSP * K3Q];     // 3-slot (scores)
__device__ float         g_Sp [(size_t)cBH * NDP * NSP];
constexpr size_t PS_PLANE = (size_t)cBH * NDP * NSP;
constexpr size_t VT_PLANE = (size_t)cBH * cDH * NSP;
__device__ __nv_bfloat16 g_Ps [2 * PS_PLANE];
__device__ __nv_bfloat16 g_Vts[2 * VT_PLANE];

// ---------------------------------------------------------------------------
// Small helpers
// ---------------------------------------------------------------------------
__device__ __forceinline__ float gelu_new(float x) {
    float x3 = x * x * x;
    return 0.5f * x * (1.0f + tanhf(0.7978845608028654f * (x + 0.044715f * x3)));
}
__device__ __forceinline__ uint32_t smem_u32(const void* p) {
    uint32_t a;
    asm("{ .reg .u64 t; cvta.to.shared.u64 t, %1; cvt.u32.u64 %0, t; }" : "=r"(a) : "l"(p));
    return a;
}
__device__ __forceinline__ void cp16(uint32_t s, const void* g) {
    asm volatile("cp.async.cg.shared.global [%0], [%1], 16;\n"
                 :: "r"(s), "l"(__cvta_generic_to_global(g)) : "memory");
}
__device__ __forceinline__ void ldsm_x4(uint32_t& r0, uint32_t& r1, uint32_t& r2,
                                        uint32_t& r3, uint32_t addr) {
    asm volatile("ldmatrix.sync.aligned.m8n8.x4.shared.b16 {%0,%1,%2,%3}, [%4];"
                 : "=r"(r0), "=r"(r1), "=r"(r2), "=r"(r3) : "r"(addr));
}
__device__ __forceinline__ void ldsm_x2(uint32_t& r0, uint32_t& r1, uint32_t addr) {
    asm volatile("ldmatrix.sync.aligned.m8n8.x2.shared.b16 {%0,%1}, [%2];"
                 : "=r"(r0), "=r"(r1) : "r"(addr));
}
__device__ __forceinline__ void mma16816(float* c, const uint32_t* a, const uint32_t* b) {
    asm volatile(
        "mma.sync.aligned.m16n8k16.row.col.f32.bf16.bf16.f32 "
        "{%0,%1,%2,%3}, {%4,%5,%6,%7}, {%8,%9}, {%0,%1,%2,%3};"
        : "+f"(c[0]), "+f"(c[1]), "+f"(c[2]), "+f"(c[3])
        : "r"(a[0]), "r"(a[1]), "r"(a[2]), "r"(a[3]), "r"(b[0]), "r"(b[1]));
}
__device__ __forceinline__ uint32_t pack_bf16x2(float a, float b) {
    __nv_bfloat16 h0 = __float2bfloat16(a), h1 = __float2bfloat16(b);
    uint16_t u0, u1;
    memcpy(&u0, &h0, 2); memcpy(&u1, &h1, 2);
    return (uint32_t)u0 | ((uint32_t)u1 << 16);
}

// ---------------------------------------------------------------------------
// Plane-split conversions
// ---------------------------------------------------------------------------
__global__ __launch_bounds__(256) void act_split2(
    const float* __restrict__ X, __nv_bfloat16* __restrict__ Yhi,
    __nv_bfloat16* __restrict__ Ylo, int MK)
{
    int i4 = (blockIdx.x * 256 + threadIdx.x) * 4;
    if (i4 >= MK) return;
    float4 x = *(const float4*)(X + i4);
    float xv[4] = {x.x, x.y, x.z, x.w};
    __nv_bfloat16 h[4], l[4];
    #pragma unroll
    for (int j = 0; j < 4; j++) {
        h[j] = __float2bfloat16(xv[j]);
        l[j] = __float2bfloat16(xv[j] - __bfloat162float(h[j]));
    }
    *(uint64_t*)(Yhi + i4) = *(uint64_t*)h;
    *(uint64_t*)(Ylo + i4) = *(uint64_t*)l;
}

// W [K,N] fp32 -> hi/lo planes [N,K] (transposed)
__global__ __launch_bounds__(256) void w_split2(
    const float* __restrict__ W, __nv_bfloat16* __restrict__ Yhi,
    __nv_bfloat16* __restrict__ Ylo, int K, int N)
{
    __shared__ float t[32][33];
    int k0 = blockIdx.y * 32, n0 = blockIdx.x * 32;
    int tid = threadIdx.x;
    #pragma unroll
    for (int p = 0; p < 4; p++) {
        int idx = p * 256 + tid;
        int kk = idx >> 5, nn = idx & 31;
        t[kk][nn] = W[(size_t)(k0 + kk) * N + n0 + nn];
    }
    __syncthreads();
    #pragma unroll
    for (int p = 0; p < 4; p++) {
        int idx = p * 256 + tid;
        int nn = idx >> 5, kk = idx & 31;
        float x = t[kk][nn];
        __nv_bfloat16 hi = __float2bfloat16(x);
        __nv_bfloat16 lo = __float2bfloat16(x - __bfloat162float(hi));
        size_t o = (size_t)(n0 + nn) * K + (k0 + kk);
        Yhi[o] = hi;
        Ylo[o] = lo;
    }
}

// ---------------------------------------------------------------------------
// Dense HMMA GEMM, hi/lo-plane operands (occ-2 mainloop + split-K).
// mode: 0 +bias, 1 +bias+gelu, 2 +bias+R, 3 +bias+R & drop-sos write,
//       4 raw partial -> C + z*M*N (no bias).
// ---------------------------------------------------------------------------
constexpr int T2_PITCH = 80;
constexpr int T2_PLANE = 128 * T2_PITCH;          // 10240
constexpr int T2_STG   = 4 * T2_PLANE;            // 40960
constexpr int T2_SMEM  = 2 * T2_STG + 128;

__global__ __launch_bounds__(256, 2) void tgemm2(
    const __nv_bfloat16* __restrict__ Ahi, const __nv_bfloat16* __restrict__ Alo,
    const __nv_bfloat16* __restrict__ Bhi, const __nv_bfloat16* __restrict__ Blo,
    const float* __restrict__ bias, const float* __restrict__ R,
    float* __restrict__ C, int M, int N, int K, int mode)
{
    extern __shared__ char dynraw[];
    char* sb = (char*)(((uintptr_t)dynraw + 127) & ~(uintptr_t)127);
    const uint32_t s0 = smem_u32(sb);

    const int tid  = threadIdx.x;
    const int wid  = tid >> 5;
    const int lane = tid & 31;
    const int g    = lane >> 2;
    const int tg   = lane & 3;
    const int wm   = wid >> 2;
    const int wn   = wid & 3;
    const int row0 = blockIdx.y * 128;
    const int col0 = blockIdx.x * 128;
    const int zsec = K / gridDim.z;
    const int kbase = blockIdx.z * zsec;
    const int nch  = zsec >> 5;

    const int crow = tid >> 2;
    const int cseg = tid & 3;
    const uint32_t so = (uint32_t)(crow * T2_PITCH + cseg * 16);
    const size_t g64 = (size_t)64 * K;
    const __nv_bfloat16* PA_hi = Ahi + (size_t)(row0 + crow) * K + kbase + cseg * 8;
    const __nv_bfloat16* PA_lo = Alo + (size_t)(row0 + crow) * K + kbase + cseg * 8;
    const __nv_bfloat16* PB_hi = Bhi + (size_t)(col0 + crow) * K + kbase + cseg * 8;
    const __nv_bfloat16* PB_lo = Blo + (size_t)(col0 + crow) * K + kbase + cseg * 8;

    const uint32_t aoff = (uint32_t)((wm * 64 + (lane & 15)) * T2_PITCH + (lane >> 4) * 16);
    const uint32_t boff = (uint32_t)((wn * 32 + (lane & 7)) * T2_PITCH + ((lane >> 3) & 1) * 16);

    float c[4][4][4];
    #pragma unroll
    for (int mi = 0; mi < 4; mi++)
        #pragma unroll
        for (int ni = 0; ni < 4; ni++)
            #pragma unroll
            for (int e = 0; e < 4; e++) c[mi][ni][e] = 0.f;

    auto load_chunk = [&](int ch, uint32_t st) {
        int k0 = ch * 32;
        cp16(st + so,                         PA_hi + k0);
        cp16(st + so + 64 * T2_PITCH,         PA_hi + k0 + g64);
        cp16(st + T2_PLANE + so,              PA_lo + k0);
        cp16(st + T2_PLANE + so + 64 * T2_PITCH, PA_lo + k0 + g64);
        cp16(st + 2 * T2_PLANE + so,          PB_hi + k0);
        cp16(st + 2 * T2_PLANE + so + 64 * T2_PITCH, PB_hi + k0 + g64);
        cp16(st + 3 * T2_PLANE + so,          PB_lo + k0);
        cp16(st + 3 * T2_PLANE + so + 64 * T2_PITCH, PB_lo + k0 + g64);
        asm volatile("cp.async.commit_group;" ::: "memory");
    };

    load_chunk(0, s0);

    for (int i = 0; i < nch; i++) {
        const int st = i & 1;
        if (i + 1 < nch) {
            load_chunk(i + 1, s0 + ((i + 1) & 1) * T2_STG);
            asm volatile("cp.async.wait_group 1;" ::: "memory");
        } else {
            asm volatile("cp.async.wait_group 0;" ::: "memory");
        }
        __syncthreads();

        const uint32_t base = s0 + st * T2_STG;
        #pragma unroll
        for (int kg = 0; kg < 2; kg++) {
            const uint32_t ko = kg * 32;
            uint32_t bhi[4][2], blo[4][2], ahi[4][4], alo[4][4];
            #pragma unroll
            for (int ni = 0; ni < 4; ni++)
                ldsm_x2(bhi[ni][0], bhi[ni][1],
                        base + 2 * T2_PLANE + boff + (uint32_t)(ni * 8 * T2_PITCH) + ko);
            #pragma unroll
            for (int mi = 0; mi < 4; mi++)
                ldsm_x4(ahi[mi][0], ahi[mi][1], ahi[mi][2], ahi[mi][3],
                        base + aoff + (uint32_t)(mi * 16 * T2_PITCH) + ko);
            #pragma unroll
            for (int mi = 0; mi < 4; mi++)
                #pragma unroll
                for (int ni = 0; ni < 4; ni++)
                    mma16816(c[mi][ni], ahi[mi], bhi[ni]);
            #pragma unroll
            for (int ni = 0; ni < 4; ni++)
                ldsm_x2(blo[ni][0], blo[ni][1],
                        base + 3 * T2_PLANE + boff + (uint32_t)(ni * 8 * T2_PITCH) + ko);
            #pragma unroll
            for (int mi = 0; mi < 4; mi++)
                #pragma unroll
                for (int ni = 0; ni < 4; ni++)
                    mma16816(c[mi][ni], ahi[mi], blo[ni]);
            #pragma unroll
            for (int mi = 0; mi < 4; mi++)
                ldsm_x4(alo[mi][0], alo[mi][1], alo[mi][2], alo[mi][3],
                        base + T2_PLANE + aoff + (uint32_t)(mi * 16 * T2_PITCH) + ko);
            #pragma unroll
            for (int mi = 0; mi < 4; mi++)
                #pragma unroll
                for (int ni = 0; ni < 4; ni++)
                    mma16816(c[mi][ni], alo[mi], bhi[ni]);
        }
        __syncthreads();
    }

    #pragma unroll
    for (int mi = 0; mi < 4; mi++) {
        #pragma unroll
        for (int half = 0; half < 2; half++) {
            int rg = row0 + wm * 64 + mi * 16 + g + half * 8;
            if (rg >= M) continue;
            if (mode == 4) {
                float* crow4 = C + (size_t)blockIdx.z * M * N + (size_t)rg * N;
                #pragma unroll
                for (int ni = 0; ni < 4; ni++) {
                    int cg = col0 + wn * 32 + ni * 8 + 2 * tg;
                    *(float2*)(crow4 + cg) =
                        make_float2(c[mi][ni][half * 2 + 0], c[mi][ni][half * 2 + 1]);
                }
                continue;
            }
            float* crow2;
            if (mode == 3) {
                int t = rg % cND;
                if (t == 0) continue;
                crow2 = C + ((size_t)((rg / cND) * cS + (t - 1))) * N;
            } else {
                crow2 = C + (size_t)rg * N;
            }
            #pragma unroll
            for (int ni = 0; ni < 4; ni++) {
                int cg = col0 + wn * 32 + ni * 8 + 2 * tg;
                float v0 = c[mi][ni][half * 2 + 0] + __ldg(&bias[cg]);
                float v1 = c[mi][ni][half * 2 + 1] + __ldg(&bias[cg + 1]);
                if (mode == 1) { v0 = gelu_new(v0); v1 = gelu_new(v1); }
                else if (mode >= 2) {
                    v0 += R[(size_t)rg * N + cg];
                    v1 += R[(size_t)rg * N + cg + 1];
                }
                *(float2*)(crow2 + cg) = make_float2(v0, v1);
            }
        }
    }
}

// ---------------------------------------------------------------------------
// combine: C = sum_s P[s] + bias (+R / sos-drop).  float4 vectorized.
// mode: 0 bias only, 2 +R, 3 +R & drop sos row.
// ---------------------------------------------------------------------------
__global__ __launch_bounds__(256) void combine(
    const float* __restrict__ P, const float* __restrict__ bias,
    const float* __restrict__ R, float* __restrict__ C,
    int M, int N, int nsplit, int mode)
{
    int i4 = (blockIdx.x * 256 + threadIdx.x) * 4;
    if (i4 >= M * N) return;
    int r = i4 / N, cc = i4 % N;
    float4 v = *(const float4*)(P + i4);
    for (int s = 1; s < nsplit; s++) {
        float4 u = *(const float4*)(P + (size_t)s * M * N + i4);
        v.x += u.x; v.y += u.y; v.z += u.z; v.w += u.w;
    }
    float4 bb = *(const float4*)(bias + cc);
    v.x += bb.x; v.y += bb.y; v.z += bb.z; v.w += bb.w;
    if (mode >= 2) {
        float4 rr = *(const float4*)(R + i4);
        v.x += rr.x; v.y += rr.y; v.z += rr.z; v.w += rr.w;
    }
    if (mode == 3) {
        int t = r % cND;
        if (t == 0) return;
        *(float4*)(C + ((size_t)((r / cND) * cS + (t - 1))) * N + cc) = v;
    } else {
        *(float4*)(C + i4) = v;
    }
}

// combine 2 partials + bias -> gelu -> hi/lo plane write (for fc)
__global__ __launch_bounds__(256) void combine_gelu_split(
    const float* __restrict__ P, const float* __restrict__ bias,
    __nv_bfloat16* __restrict__ Yhi, __nv_bfloat16* __restrict__ Ylo,
    int M, int N)
{
    int i4 = (blockIdx.x * 256 + threadIdx.x) * 4;
    if (i4 >= M * N) return;
    int cc = i4 % N;
    float4 v = *(const float4*)(P + i4);
    float4 u = *(const float4*)(P + (size_t)M * N + i4);
    float4 bb = *(const float4*)(bias + cc);
    float xv[4] = {gelu_new(v.x + u.x + bb.x), gelu_new(v.y + u.y + bb.y),
                   gelu_new(v.z + u.z + bb.z), gelu_new(v.w + u.w + bb.w)};
    __nv_bfloat16 h[4], l[4];
    #pragma unroll
    for (int j = 0; j < 4; j++) {
        h[j] = __float2bfloat16(xv[j]);
        l[j] = __float2bfloat16(xv[j] - __bfloat162float(h[j]));
    }
    *(uint64_t*)(Yhi + i4) = *(uint64_t*)h;
    *(uint64_t*)(Ylo + i4) = *(uint64_t*)l;
}

// combine 2 partials + bias + residual H -> H2, then LN -> hi/lo planes (for fc A)
__global__ __launch_bounds__(256) void combine_ln(
    const float* __restrict__ P, const float* __restrict__ bias,
    const float* __restrict__ Hres, float* __restrict__ H2,
    const float* __restrict__ gamma, const float* __restrict__ beta,
    __nv_bfloat16* __restrict__ Yhi, __nv_bfloat16* __restrict__ Ylo)
{
    int r   = blockIdx.x;
    int tid = threadIdx.x;
    const float* p0 = P + (size_t)r * cD;
    const float* p1 = P + (size_t)cM * cD + (size_t)r * cD;
    const float* hr = Hres + (size_t)r * cD;
    float v[3];
    #pragma unroll
    for (int j = 0; j < 3; j++) {
        int cc = tid + j * 256;
        v[j] = p0[cc] + p1[cc] + bias[cc] + hr[cc];
    }
    float* h2r = H2 + (size_t)r * cD;
    h2r[tid] = v[0]; h2r[tid + 256] = v[1]; h2r[tid + 512] = v[2];

    float s = v[0] + v[1] + v[2];
    float ss = v[0] * v[0] + v[1] * v[1] + v[2] * v[2];
    __shared__ float sb[8], sb2[8];
    #pragma unroll
    for (int o = 16; o; o >>= 1) {
        s  += __shfl_xor_sync(0xffffffffu, s,  o);
        ss += __shfl_xor_sync(0xffffffffu, ss, o);
    }
    int lane = tid & 31, w = tid >> 5;
    if (lane == 0) { sb[w] = s; sb2[w] = ss; }
    __syncthreads();
    if (tid == 0) {
        float a = 0.f, c2 = 0.f;
        #pragma unroll
        for (int i = 0; i < 8; i++) { a += sb[i]; c2 += sb2[i]; }
        sb[0] = a; sb2[0] = c2;
    }
    __syncthreads();
    float mean = sb[0] * (1.0f / 768.0f);
    float var  = sb2[0] * (1.0f / 768.0f) - mean * mean;
    float inv  = rsqrtf(var + 1e-5f);

    #pragma unroll
    for (int j = 0; j < 3; j++) {
        int cc = tid + j * 256;
        float y = (v[j] - mean) * inv * gamma[cc] + beta[cc];
        __nv_bfloat16 hi = __float2bfloat16(y);
        __nv_bfloat16 lo = __float2bfloat16(y - __bfloat162float(hi));
        Yhi[(size_t)r * cD + cc] = hi;
        Ylo[(size_t)r * cD + cc] = lo;
    }
}

// ---------------------------------------------------------------------------
// scores_mma (3-slot interleaved operands); fully-masked tiles are no-ops.
// ---------------------------------------------------------------------------
constexpr int TG_PITCH = 144;
constexpr int TG_STG   = 128 * TG_PITCH;      // 18432
constexpr int TG_SMEM  = 4 * TG_STG + 128;

__global__ __launch_bounds__(256, 2) void scores_mma(
    const __nv_bfloat16* __restrict__ Qs, const __nv_bfloat16* __restrict__ Ks,
    float* __restrict__ S)
{
    extern __shared__ char dynraw[];
    char* sb = (char*)(((uintptr_t)dynraw + 127) & ~(uintptr_t)127);
    const uint32_t sA0 = smem_u32(sb);
    const uint32_t sB0 = sA0 + 2 * TG_STG;

    const int tid  = threadIdx.x;
    const int wid  = tid >> 5;
    const int lane = tid & 31;
    const int g    = lane >> 2;
    const int tg   = lane & 3;
    const int wm   = wid >> 2;
    const int wn   = wid & 3;
    const int bh   = blockIdx.z;
    const int row0 = blockIdx.y * 128;
    const int col0 = blockIdx.x * 128;

    // Fully-masked tiles are never read by the truncated softmax: skip.
    if (col0 >= row0 + 128 + cSC) return;

    float* Sb = S + (size_t)bh * NDP * NSP;
    const __nv_bfloat16* A3 = Qs + (size_t)bh * NDP * K3Q;
    const __nv_bfloat16* B3 = Ks + (size_t)bh * NSP * K3Q;

    uint32_t soff[4];
    const __nv_bfloat16 *Ag[4], *Bg[4];
    #pragma unroll
    for (int p = 0; p < 4; p++) {
        int idx = p * 256 + tid;
        int row = idx >> 3, seg = idx & 7;
        soff[p] = (uint32_t)(row * TG_PITCH + seg * 16);
        Ag[p] = A3 + (size_t)(row0 + row) * K3Q + seg * 8;
        Bg[p] = B3 + (size_t)(col0 + row) * K3Q + seg * 8;
    }
    const uint32_t aoff = (uint32_t)((wm * 64 + (lane & 15)) * TG_PITCH + (lane >> 4) * 16);
    const uint32_t boff = (uint32_t)((wn * 32 + (lane & 7)) * TG_PITCH + ((lane >> 3) & 1) * 16);

    float c[4][4][4];
    #pragma unroll
    for (int mi = 0; mi < 4; mi++)
        #pragma unroll
        for (int ni = 0; ni < 4; ni++)
            #pragma unroll
            for (int e = 0; e < 4; e++) c[mi][ni][e] = 0.f;

    #pragma unroll
    for (int p = 0; p < 4; p++) {
        cp16(sA0 + soff[p], Ag[p]);
        cp16(sB0 + soff[p], Bg[p]);
    }
    asm volatile("cp.async.commit_group;" ::: "memory");

    #pragma unroll
    for (int i = 0; i < 3; i++) {
        const int st = i & 1;
        if (i + 1 < 3) {
            const int st2 = (i + 1) & 1;
            const int ko = (i + 1) * 64;
            #pragma unroll
            for (int p = 0; p < 4; p++) {
                cp16(sA0 + st2 * TG_STG + soff[p], Ag[p] + ko);
                cp16(sB0 + st2 * TG_STG + soff[p], Bg[p] + ko);
            }
            asm volatile("cp.async.commit_group;" ::: "memory");
            asm volatile("cp.async.wait_group 1;" ::: "memory");
        } else {
            asm volatile("cp.async.wait_group 0;" ::: "memory");
        }
        __syncthreads();
        const uint32_t sa = sA0 + st * TG_STG + aoff;
        const uint32_t sbb = sB0 + st * TG_STG + boff;
        #pragma unroll
        for (int ks = 0; ks < 4; ks++) {
            uint32_t a[4][4], b[4][2];
            #pragma unroll
            for (int mi = 0; mi < 4; mi++)
                ldsm_x4(a[mi][0], a[mi][1], a[mi][2], a[mi][3],
                        sa + (uint32_t)(mi * 16 * TG_PITCH + ks * 32));
            #pragma unroll
            for (int ni = 0; ni < 4; ni++)
                ldsm_x2(b[ni][0], b[ni][1],
                        sbb + (uint32_t)(ni * 8 * TG_PITCH + ks * 32));
            #pragma unroll
            for (int mi = 0; mi < 4; mi++)
                #pragma unroll
                for (int ni = 0; ni < 4; ni++)
                    mma16816(c[mi][ni], a[mi], b[ni]);
        }
        __syncthreads();
    }

    const float scale = 0.125f;   // 1/sqrt(64)
    #pragma unroll
    for (int mi = 0; mi < 4; mi++) {
        #pragma unroll
        for (int half = 0; half < 2; half++) {
            int rg = row0 + wm * 64 + mi * 16 + g + half * 8;
            float* Sr = Sb + (size_t)rg * NSP;
            #pragma unroll
            for (int ni = 0; ni < 4; ni++) {
                int cg = col0 + wn * 32 + ni * 8 + 2 * tg;
                float v0 = (cg     <= rg + cSC) ? c[mi][ni][half * 2 + 0] * scale : -10000.0f;
                float v1 = (cg + 1 <= rg + cSC) ? c[mi][ni][half * 2 + 1] * scale : -10000.0f;
                *(float2*)(Sr + cg) = make_float2(v0, v1);
            }
        }
    }
}

// ---------------------------------------------------------------------------
// av_mma2: hi/lo-plane AV with causal K truncation.
// 128x64 tile, 8 warps 4x2, chunk = 32 k, nch = min(44, bx*4 + 12).
// Writes merged-head output directly as hi/lo planes (K=768 layout).
// ---------------------------------------------------------------------------
constexpr int AV2_APL  = 128 * T2_PITCH;          // 10240
constexpr int AV2_BPL  = 64 * T2_PITCH;           // 5120
constexpr int AV2_STG  = 2 * AV2_APL + 2 * AV2_BPL;   // 30720
constexpr int AV2_SMEM = 2 * AV2_STG + 128;           // 61568

__global__ __launch_bounds__(256, 2) void av_mma2(
    const __nv_bfloat16* __restrict__ P2, const __nv_bfloat16* __restrict__ V2,
    __nv_bfloat16* __restrict__ Ahi, __nv_bfloat16* __restrict__ Alo)
{
    extern __shared__ char dynraw[];
    char* sb = (char*)(((uintptr_t)dynraw + 127) & ~(uintptr_t)127);
    const uint32_t s0 = smem_u32(sb);

    const int tid  = threadIdx.x;
    const int wid  = tid >> 5;
    const int lane = tid & 31;
    const int g    = lane >> 2;
    const int tg   = lane & 3;
    const int wm   = wid >> 1;
    const int wn   = wid & 1;
    const int bh   = blockIdx.y;
    const int row0 = blockIdx.x * 128;

    const __nv_bfloat16* Phi = P2 + (size_t)bh * NDP * NSP;
    const __nv_bfloat16* Plo = Phi + PS_PLANE;
    const __nv_bfloat16* Vhi = V2 + (size_t)bh * cDH * NSP;
    const __nv_bfloat16* Vlo = Vhi + VT_PLANE;

    const int arow = tid >> 1;
    const int aseg2 = (tid & 1) * 2;
    const int brow = tid >> 2;
    const int bseg = tid & 3;

    const __nv_bfloat16* PAhi = Phi + (size_t)(row0 + arow) * NSP + aseg2 * 8;
    const __nv_bfloat16* PAlo = Plo + (size_t)(row0 + arow) * NSP + aseg2 * 8;
    const __nv_bfloat16* PBhi = Vhi + (size_t)brow * NSP + bseg * 8;
    const __nv_bfloat16* PBlo = Vlo + (size_t)brow * NSP + bseg * 8;
    const uint32_t soa = (uint32_t)(arow * T2_PITCH + aseg2 * 16);
    const uint32_t sob = (uint32_t)(brow * T2_PITCH + bseg * 16);

    const uint32_t aoff = (uint32_t)((wm * 32 + (lane & 15)) * T2_PITCH + (lane >> 4) * 16);
    const uint32_t boff = (uint32_t)((wn * 32 + (lane & 7)) * T2_PITCH + ((lane >> 3) & 1) * 16);

    float c[2][4][4];
    #pragma unroll
    for (int mi = 0; mi < 2; mi++)
        #pragma unroll
        for (int ni = 0; ni < 4; ni++)
            #pragma unroll
            for (int e = 0; e < 4; e++) c[mi][ni][e] = 0.f;

    // Causal truncation: P rows in this block are zero beyond j = row0+383.
    const int nch_full = NSP >> 5;               // 44
    int nch = blockIdx.x * 4 + 12;
    if (nch > nch_full) nch = nch_full;

    auto load_chunk = [&](int ch, uint32_t st) {
        int k0 = ch * 32;
        cp16(st + soa,                   PAhi + k0);
        cp16(st + soa + 16,              PAhi + k0 + 8);
        cp16(st + AV2_APL + soa,         PAlo + k0);
        cp16(st + AV2_APL + soa + 16,    PAlo + k0 + 8);
        cp16(st + 2 * AV2_APL + sob,            PBhi + k0);
        cp16(st + 2 * AV2_APL + AV2_BPL + sob,  PBlo + k0);
        asm volatile("cp.async.commit_group;" ::: "memory");
    };

    load_chunk(0, s0);

    for (int i = 0; i < nch; i++) {
        const int st = i & 1;
        if (i + 1 < nch) {
            load_chunk(i + 1, s0 + ((i + 1) & 1) * AV2_STG);
            asm volatile("cp.async.wait_group 1;" ::: "memory");
        } else {
            asm volatile("cp.async.wait_group 0;" ::: "memory");
        }
        __syncthreads();

        const uint32_t base = s0 + st * AV2_STG;
        #pragma unroll
        for (int kg = 0; kg < 2; kg++) {
            const uint32_t ko = kg * 32;
            uint32_t bhi[4][2], blo[4][2], ahi[2][4], alo[2][4];
            #pragma unroll
            for (int ni = 0; ni < 4; ni++)
                ldsm_x2(bhi[ni][0], bhi[ni][1],
                        base + 2 * AV2_APL + boff + (uint32_t)(ni * 8 * T2_PITCH) + ko);
            #pragma unroll
            for (int mi = 0; mi < 2; mi++)
                ldsm_x4(ahi[mi][0], ahi[mi][1], ahi[mi][2], ahi[mi][3],
                        base + aoff + (uint32_t)(mi * 16 * T2_PITCH) + ko);
            #pragma unroll
            for (int mi = 0; mi < 2; mi++)
                #pragma unroll
                for (int ni = 0; ni < 4; ni++)
                    mma16816(c[mi][ni], ahi[mi], bhi[ni]);
            #pragma unroll
            for (int ni = 0; ni < 4; ni++)
                ldsm_x2(blo[ni][0], blo[ni][1],
                        base + 2 * AV2_APL + AV2_BPL + boff + (uint32_t)(ni * 8 * T2_PITCH) + ko);
            #pragma unroll
            for (int mi = 0; mi < 2; mi++)
                #pragma unroll
                for (int ni = 0; ni < 4; ni++)
                    mma16816(c[mi][ni], ahi[mi], blo[ni]);
            #pragma unroll
            for (int mi = 0; mi < 2; mi++)
                ldsm_x4(alo[mi][0], alo[mi][1], alo[mi][2], alo[mi][3],
                        base + AV2_APL + aoff + (uint32_t)(mi * 16 * T2_PITCH) + ko);
            #pragma unroll
            for (int mi = 0; mi < 2; mi++)
                #pragma unroll
                for (int ni = 0; ni < 4; ni++)
                    mma16816(c[mi][ni], alo[mi], bhi[ni]);
        }
        __syncthreads();
    }

    const int b_ = bh / cH, h = bh % cH;
    #pragma unroll
    for (int mi = 0; mi < 2; mi++) {
        #pragma unroll
        for (int half = 0; half < 2; half++) {
            int rg = row0 + wm * 32 + mi * 16 + g + half * 8;
            if (rg >= cND) continue;
            size_t rowoff = ((size_t)(b_ * cND + rg)) * cD + h * cDH;
            #pragma unroll
            for (int ni = 0; ni < 4; ni++) {
                int cg = wn * 32 + ni * 8 + 2 * tg;
                float v0 = c[mi][ni][half * 2 + 0];
                float v1 = c[mi][ni][half * 2 + 1];
                __nv_bfloat16 h0 = __float2bfloat16(v0);
                __nv_bfloat16 h1 = __float2bfloat16(v1);
                float l0 = v0 - __bfloat162float(h0);
                float l1 = v1 - __bfloat162float(h1);
                *(uint32_t*)(Ahi + rowoff + cg) = pack_bf16x2(v0, v1);
                *(uint32_t*)(Alo + rowoff + cg) = pack_bf16x2(l0, l1);
            }
        }
    }
}

// ---------------------------------------------------------------------------
// LayerNorm fused with sos-concat gather; writes H + hi/lo plane output.
// ---------------------------------------------------------------------------
__global__ __launch_bounds__(256) void ln_kernel(
    const float* __restrict__ in, const float* __restrict__ sos,
    const float* __restrict__ gamma, const float* __restrict__ beta,
    float* __restrict__ Hout, __nv_bfloat16* __restrict__ Yhi,
    __nv_bfloat16* __restrict__ Ylo)
{
    int r   = blockIdx.x;
    int tid = threadIdx.x;
    int b = r / cND, t = r % cND;
    const float* src = (t == 0) ? sos : in + ((size_t)b * cS + (t - 1)) * cD;

    float v0 = src[tid], v1 = src[tid + 256], v2 = src[tid + 512];
    float s  = v0 + v1 + v2;
    float ss = v0 * v0 + v1 * v1 + v2 * v2;

    __shared__ float sb[8], sb2[8];
    #pragma unroll
    for (int o = 16; o; o >>= 1) {
        s  += __shfl_xor_sync(0xffffffffu, s,  o);
        ss += __shfl_xor_sync(0xffffffffu, ss, o);
    }
    int lane = tid & 31, w = tid >> 5;
    if (lane == 0) { sb[w] = s; sb2[w] = ss; }
    __syncthreads();
    if (tid == 0) {
        float a = 0.f, c = 0.f;
        #pragma unroll
        for (int i = 0; i < 8; i++) { a += sb[i]; c += sb2[i]; }
        sb[0] = a; sb2[0] = c;
    }
    __syncthreads();
    float mean = sb[0] * (1.0f / 768.0f);
    float var  = sb2[0] * (1.0f / 768.0f) - mean * mean;
    float inv  = rsqrtf(var + 1e-5f);

    float* hr = Hout + (size_t)r * cD;
    hr[tid] = v0; hr[tid + 256] = v1; hr[tid + 512] = v2;

    float vv[3] = {v0, v1, v2};
    #pragma unroll
    for (int j = 0; j < 3; j++) {
        int cc = tid + j * 256;
        float y = (vv[j] - mean) * inv * gamma[cc] + beta[cc];
        __nv_bfloat16 hi = __float2bfloat16(y);
        __nv_bfloat16 lo = __float2bfloat16(y - __bfloat162float(hi));
        Yhi[(size_t)r * cD + cc] = hi;
        Ylo[(size_t)r * cD + cc] = lo;
    }
}

// ---------------------------------------------------------------------------
// Gathers: Q/K 3-slot interleaved (scores), Vt hi/lo planes (AV)
// ---------------------------------------------------------------------------
__global__ void gather_q_split(const float* __restrict__ QKV, __nv_bfloat16* __restrict__ Qs)
{
    int idx = blockIdx.x * blockDim.x + threadIdx.x;
    if (idx >= cBH * cND * cDH) return;
    int d    = idx & (cDH - 1);
    int rest = idx >> 6;
    int t    = rest % cND;
    int bh   = rest / cND;
    int b = bh / cH, h = bh % cH;
    float x = QKV[((size_t)(b * cND + t)) * (3 * cD) + h * cDH + d];
    __nv_bfloat16 hi = __float2bfloat16(x);
    __nv_bfloat16 lo = __float2bfloat16(x - __bfloat162float(hi));
    size_t o = ((size_t)bh * NDP + t) * K3Q + 3 * d;
    Qs[o] = hi; Qs[o + 1] = lo; Qs[o + 2] = hi;
}

__global__ void gather_k_split(const float* __restrict__ QKV, const float* __restrict__ CKV,
                               __nv_bfloat16* __restrict__ Ks)
{
    int idx = blockIdx.x * blockDim.x + threadIdx.x;
    if (idx >= cBH * cNS * cDH) return;
    int d    = idx & (cDH - 1);
    int rest = idx >> 6;
    int j    = rest % cNS;
    int bh   = rest / cNS;
    int b = bh / cH, h = bh % cH;
    float kv;
    if (j < cSC)
        kv = CKV[((size_t)(b * cSC + j)) * (2 * cD) + h * cDH + d];
    else
        kv = QKV[((size_t)(b * cND + (j - cSC))) * (3 * cD) + cD + h * cDH + d];
    __nv_bfloat16 hi = __float2bfloat16(kv);
    __nv_bfloat16 lo = __float2bfloat16(kv - __bfloat162float(hi));
    size_t o = ((size_t)bh * NSP + j) * K3Q + 3 * d;
    Ks[o] = hi; Ks[o + 1] = hi; Ks[o + 2] = lo;
}

__global__ void gather_vt_split2(const float* __restrict__ QKV, const float* __restrict__ CKV,
                                 __nv_bfloat16* __restrict__ Vt)
{
    int idx = blockIdx.x * blockDim.x + threadIdx.x;
    if (idx >= cBH * cDH * cNS) return;
    int j    = idx % cNS;
    int rest = idx / cNS;
    int d    = rest & (cDH - 1);
    int bh   = rest >> 6;
    int b = bh / cH, h = bh % cH;
    float vv;
    if (j < cSC)
        vv = CKV[((size_t)(b * cSC + j)) * (2 * cD) + cD + h * cDH + d];
    else
        vv = QKV[((size_t)(b * cND + (j - cSC))) * (3 * cD) + 2 * cD + h * cDH + d];
    __nv_bfloat16 hi = __float2bfloat16(vv);
    __nv_bfloat16 lo = __float2bfloat16(vv - __bfloat162float(hi));
    size_t o = ((size_t)bh * cDH + d) * NSP + j;
    Vt[o] = hi;
    Vt[o + VT_PLANE] = lo;
}

// ---------------------------------------------------------------------------
// Softmax truncated to the causally-valid prefix L = m + Sc + 1; writes
// hi/lo planes over [0, L) only (the rest is zero-initialized and untouched).
// ---------------------------------------------------------------------------
__global__ __launch_bounds__(256) void softmax_split2(
    const float* __restrict__ S, __nv_bfloat16* __restrict__ P2)
{
    int r  = blockIdx.x;
    int bh = r / cND, m = r % cND;
    const int L = m + cSC + 1;
    const float* p = S + ((size_t)bh * NDP + m) * NSP;
    __nv_bfloat16* ohi = P2 + ((size_t)bh * NDP + m) * NSP;
    __nv_bfloat16* olo = ohi + PS_PLANE;
    int tid = threadIdx.x;

    float vals[6];
    float mx = -3.4e38f;
    #pragma unroll
    for (int it = 0; it < 6; it++) {
        int i = tid + it * 256;
        float v = (i < L) ? p[i] : -3.4e38f;
        vals[it] = v;
        mx = fmaxf(mx, v);
    }
    __shared__ float sb[8];
    #pragma unroll
    for (int o = 16; o; o >>= 1) mx = fmaxf(mx, __shfl_xor_sync(0xffffffffu, mx, o));
    if ((tid & 31) == 0) sb[tid >> 5] = mx;
    __syncthreads();
    if (tid < 32) {
        float m2 = (tid < 8) ? sb[tid] : -3.4e38f;
        #pragma unroll
        for (int o = 4; o; o >>= 1) m2 = fmaxf(m2, __shfl_xor_sync(0xffffffffu, m2, o));
        if (tid == 0) sb[0] = m2;
    }
    __syncthreads();
    float bmax = sb[0];
    __syncthreads();

    float s = 0.f;
    #pragma unroll
    for (int it = 0; it < 6; it++) {
        int i = tid + it * 256;
        if (i < L) {
            float e = __expf(vals[it] - bmax);
            vals[it] = e;
            s += e;
        }
    }
    #pragma unroll
    for (int o = 16; o; o >>= 1) s += __shfl_xor_sync(0xffffffffu, s, o);
    if ((tid & 31) == 0) sb[tid >> 5] = s;
    __syncthreads();
    if (tid < 32) {
        float s2 = (tid < 8) ? sb[tid] : 0.f;
        #pragma unroll
        for (int o = 4; o; o >>= 1) s2 += __shfl_xor_sync(0xffffffffu, s2, o);
        if (tid == 0) sb[0] = s2;
    }
    __syncthreads();
    float inv = 1.0f / sb[0];
    #pragma unroll
    for (int it = 0; it < 6; it++) {
        int i = tid + it * 256;
        if (i >= L) continue;
        float v = vals[it] * inv;
        __nv_bfloat16 hi = __float2bfloat16(v);
        __nv_bfloat16 lo = __float2bfloat16(v - __bfloat162float(hi));
        ohi[i] = hi;
        olo[i] = lo;
    }
}

// ---------------------------------------------------------------------------
// Launch sequence
// ---------------------------------------------------------------------------
extern "C" void kernel_launch(void* const* d_in, const int* in_sizes, int n_in,
                              void* d_out, int out_size)
{
    (void)in_sizes; (void)n_in; (void)out_size;
    const float* x       = (const float*)d_in[0];
    const float* ctx     = (const float*)d_in[1];
    const float* sos     = (const float*)d_in[2];
    const float* ln1_g   = (const float*)d_in[3];
    const float* ln1_b   = (const float*)d_in[4];
    const float* W_attn  = (const float*)d_in[5];
    const float* b_attn  = (const float*)d_in[6];
    const float* W_ref   = (const float*)d_in[7];
    const float* b_ref   = (const float*)d_in[8];
    const float* W_proj  = (const float*)d_in[9];
    const float* b_proj  = (const float*)d_in[10];
    const float* ln2_g   = (const float*)d_in[11];
    const float* ln2_b   = (const float*)d_in[12];
    const float* W_fc    = (const float*)d_in[13];
    const float* b_fc    = (const float*)d_in[14];
    const float* W_mproj = (const float*)d_in[15];
    const float* b_mproj = (const float*)d_in[16];
    float* out = (float*)d_out;

    float *H, *QKV, *CKV, *H2, *Sp, *Pp;
    __nv_bfloat16 *As, *Bs, *Qs, *Ks, *Vts, *Ps;
    cudaGetSymbolAddress((void**)&H,   g_H);
    cudaGetSymbolAddress((void**)&QKV, g_QKV);
    cudaGetSymbolAddress((void**)&CKV, g_CKV);
    cudaGetSymbolAddress((void**)&H2,  g_H2);
    cudaGetSymbolAddress((void**)&Sp,  g_Sp);
    cudaGetSymbolAddress((void**)&Pp,  g_Pp);
    cudaGetSymbolAddress((void**)&As,  g_As);
    cudaGetSymbolAddress((void**)&Bs,  g_Bs);
    cudaGetSymbolAddress((void**)&Qs,  g_Qs);
    cudaGetSymbolAddress((void**)&Ks,  g_Ks);
    cudaGetSymbolAddress((void**)&Vts, g_Vts);
    cudaGetSymbolAddress((void**)&Ps,  g_Ps);

    cudaFuncSetAttribute(tgemm2,     cudaFuncAttributeMaxDynamicSharedMemorySize, T2_SMEM);
    cudaFuncSetAttribute(scores_mma, cudaFuncAttributeMaxDynamicSharedMemorySize, TG_SMEM);
    cudaFuncSetAttribute(av_mma2,    cudaFuncAttributeMaxDynamicSharedMemorySize, AV2_SMEM);

    auto Alo_of = [&](int K) { return As + (size_t)cMPAD * K; };

    // 1. concat(sos, x) + LN1 -> H + A-planes (K=768)
    ln_kernel<<<cM, 256>>>(x, sos, ln1_g, ln1_b, H, As, Alo_of(cD));

    // 2. qkv = ln1(h) @ W_attn + b_attn   [2050x2304], split-K x2 (612 CTAs)
    w_split2<<<dim3(3 * cD / 32, cD / 32), 256>>>(W_attn, Bs, Bs + (size_t)3 * cD * cD,
                                                  cD, 3 * cD);
    tgemm2<<<dim3(3 * cD / 128, 17, 2), 256, T2_SMEM>>>(
        As, Alo_of(cD), Bs, Bs + (size_t)3 * cD * cD, b_attn, nullptr, Pp,
        cM, 3 * cD, cD, 4);
    combine<<<(cM * 3 * cD / 4 + 255) / 256, 256>>>(Pp, b_attn, nullptr, QKV,
                                                    cM, 3 * cD, 2, 0);

    // 3. ckv = context @ W_ref + b_ref    [512x1536], split-K x3 (144 CTAs)
    act_split2<<<(cMC * cD / 4 + 255) / 256, 256>>>(ctx, As, Alo_of(cD), cMC * cD);
    w_split2<<<dim3(2 * cD / 32, cD / 32), 256>>>(W_ref, Bs, Bs + (size_t)2 * cD * cD,
                                                  cD, 2 * cD);
    tgemm2<<<dim3(2 * cD / 128, 4, 3), 256, T2_SMEM>>>(
        As, Alo_of(cD), Bs, Bs + (size_t)2 * cD * cD, b_ref, nullptr, Pp,
        cMC, 2 * cD, cD, 4);
    combine<<<(cMC * 2 * cD / 4 + 255) / 256, 256>>>(Pp, b_ref, nullptr, CKV,
                                                     cMC, 2 * cD, 3, 0);

    // 4. gathers for attention
    gather_q_split<<<(cBH * cND * cDH + 255) / 256, 256>>>(QKV, Qs);
    gather_k_split<<<(cBH * cNS * cDH + 255) / 256, 256>>>(QKV, CKV, Ks);
    gather_vt_split2<<<(cBH * cDH * cNS + 255) / 256, 256>>>(QKV, CKV, Vts);

    // 5. attention: scores (masked-tile no-op), truncated softmax, truncated AV
    scores_mma<<<dim3(NSP / 128, NDP / 128, cBH), 256, TG_SMEM>>>(Qs, Ks, Sp);
    softmax_split2<<<cBH * cND, 256>>>(Sp, Ps);
    av_mma2<<<dim3(NDP / 128, cBH), 256, AV2_SMEM>>>(Ps, Vts, As, Alo_of(cD));

    // 6. proj: split-K x2 (204 CTAs, 1 wave) then fused combine+LN2+split
    w_split2<<<dim3(cD / 32, cD / 32), 256>>>(W_proj, Bs, Bs + (size_t)cD * cD,
                                              cD, cD);
    tgemm2<<<dim3(cD / 128, 17, 2), 256, T2_SMEM>>>(
        As, Alo_of(cD), Bs, Bs + (size_t)cD * cD, b_proj, nullptr, Pp,
        cM, cD, cD, 4);
    combine_ln<<<cM, 256>>>(Pp, b_proj, H, H2, ln2_g, ln2_b, As, Alo_of(cD));

    // 7. fc: split-K x2 (816 CTAs) then fused combine+gelu+split (K=3072 planes)
    w_split2<<<dim3(4 * cD / 32, cD / 32), 256>>>(W_fc, Bs, Bs + (size_t)4 * cD * cD,
                                                  cD, 4 * cD);
    tgemm2<<<dim3(4 * cD / 128, 17, 2), 256, T2_SMEM>>>(
        As, Alo_of(cD), Bs, Bs + (size_t)4 * cD * cD, b_fc, nullptr, Pp,
        cM, 4 * cD, cD, 4);
    combine_gelu_split<<<(cM * 4 * cD / 4 + 255) / 256, 256>>>(
        Pp, b_fc, As, Alo_of(4 * cD), cM, 4 * cD);

    // 8. mproj: split-K x2 (204 CTAs, 1 wave, nch 48) + combine with sos-drop
    w_split2<<<dim3(cD / 32, 4 * cD / 32), 256>>>(W_mproj, Bs,
                                                  Bs + (size_t)cD * 4 * cD,
                                                  4 * cD, cD);
    tgemm2<<<dim3(cD / 128, 17, 2), 256, T2_SMEM>>>(
        As, Alo_of(4 * cD), Bs, Bs + (size_t)cD * 4 * cD, b_mproj, nullptr, Pp,
        cM, cD, 4 * cD, 4);
    combine<<<(cM * cD / 4 + 255) / 256, 256>>>(Pp, b_mproj, H2, out, cM, cD, 2, 3);
}

// round 17
// speedup vs baseline: 1.6179x; 1.0178x over previous
#include <cuda_runtime.h>
#include <cuda_bf16.h>
#include <math.h>
#include <stdint.h>

// ---------------------------------------------------------------------------
// Problem constants (CoconBlock: B=2, S=1024, Sc=256, D=768, H=12, dh=64)
// ---------------------------------------------------------------------------
constexpr int cD   = 768;
constexpr int cH   = 12;
constexpr int cDH  = 64;
constexpr int cB   = 2;
constexpr int cS   = 1024;
constexpr int cSC  = 256;
constexpr int cND  = cS + 1;          // 1025 queries per batch (sos + seq)
constexpr int cNS  = cSC + cND;       // 1281 keys per batch
constexpr int cM   = cB * cND;        // 2050 rows in main activation
constexpr int cMC  = cB * cSC;        // 512 context rows
constexpr int cBH  = cB * cH;         // 24 (batch, head) pairs
constexpr int cMPAD = 2176;           // 17 * 128

// attention padded dims
constexpr int NDP  = 1152;            // 9 * 128 padded queries
constexpr int NSP  = 1408;            // 11 * 128 padded keys
constexpr int K3Q  = 192;             // 3 * dh (interleaved format, scores)

// ---------------------------------------------------------------------------
// Scratch (zero-initialized; padding regions never written -> stay zero)
// ---------------------------------------------------------------------------
__device__ float g_H  [(size_t)cM * cD];
__device__ float g_QKV[(size_t)cM * 3 * cD];
__device__ float g_CKV[(size_t)cMC * 2 * cD];
__device__ float g_H2 [(size_t)cM * cD];
__device__ float g_Pp [12600000];                            // split-K partials
__device__ __nv_bfloat16 g_As[(size_t)2 * cMPAD * 3072];
__device__ __nv_bfloat16 g_Bs[(size_t)2 * 3072 * 768 + 2 * 768 * 2304];
__device__ __nv_bfloat16 g_Qs [(size_t)cBH * NDP * K3Q];     // 3-slot (scores)
__device__ __nv_bfloat16 g_Ks [(size_t)cBH * NSP * K3Q];     // 3-slot (scores)
__device__ float         g_Sp [(size_t)cBH * NDP * NSP];
constexpr size_t PS_PLANE = (size_t)cBH * NDP * NSP;
constexpr size_t VT_PLANE = (size_t)cBH * cDH * NSP;
__device__ __nv_bfloat16 g_Ps [2 * PS_PLANE];
__device__ __nv_bfloat16 g_Vts[2 * VT_PLANE];

// ---------------------------------------------------------------------------
// Small helpers
// ---------------------------------------------------------------------------
__device__ __forceinline__ float gelu_new(float x) {
    float x3 = x * x * x;
    return 0.5f * x * (1.0f + tanhf(0.7978845608028654f * (x + 0.044715f * x3)));
}
__device__ __forceinline__ uint32_t smem_u32(const void* p) {
    uint32_t a;
    asm("{ .reg .u64 t; cvta.to.shared.u64 t, %1; cvt.u32.u64 %0, t; }" : "=r"(a) : "l"(p));
    return a;
}
__device__ __forceinline__ void cp16(uint32_t s, const void* g) {
    asm volatile("cp.async.cg.shared.global [%0], [%1], 16;\n"
                 :: "r"(s), "l"(__cvta_generic_to_global(g)) : "memory");
}
__device__ __forceinline__ void ldsm_x4(uint32_t& r0, uint32_t& r1, uint32_t& r2,
                                        uint32_t& r3, uint32_t addr) {
    asm volatile("ldmatrix.sync.aligned.m8n8.x4.shared.b16 {%0,%1,%2,%3}, [%4];"
                 : "=r"(r0), "=r"(r1), "=r"(r2), "=r"(r3) : "r"(addr));
}
__device__ __forceinline__ void ldsm_x2(uint32_t& r0, uint32_t& r1, uint32_t addr) {
    asm volatile("ldmatrix.sync.aligned.m8n8.x2.shared.b16 {%0,%1}, [%2];"
                 : "=r"(r0), "=r"(r1) : "r"(addr));
}
__device__ __forceinline__ void mma16816(float* c, const uint32_t* a, const uint32_t* b) {
    asm volatile(
        "mma.sync.aligned.m16n8k16.row.col.f32.bf16.bf16.f32 "
        "{%0,%1,%2,%3}, {%4,%5,%6,%7}, {%8,%9}, {%0,%1,%2,%3};"
        : "+f"(c[0]), "+f"(c[1]), "+f"(c[2]), "+f"(c[3])
        : "r"(a[0]), "r"(a[1]), "r"(a[2]), "r"(a[3]), "r"(b[0]), "r"(b[1]));
}
__device__ __forceinline__ uint32_t pack_bf16x2(float a, float b) {
    __nv_bfloat16 h0 = __float2bfloat16(a), h1 = __float2bfloat16(b);
    uint16_t u0, u1;
    memcpy(&u0, &h0, 2); memcpy(&u1, &h1, 2);
    return (uint32_t)u0 | ((uint32_t)u1 << 16);
}

// ---------------------------------------------------------------------------
// Plane-split conversions
// ---------------------------------------------------------------------------
__global__ __launch_bounds__(256) void act_split2(
    const float* __restrict__ X, __nv_bfloat16* __restrict__ Yhi,
    __nv_bfloat16* __restrict__ Ylo, int MK)
{
    int i4 = (blockIdx.x * 256 + threadIdx.x) * 4;
    if (i4 >= MK) return;
    float4 x = *(const float4*)(X + i4);
    float xv[4] = {x.x, x.y, x.z, x.w};
    __nv_bfloat16 h[4], l[4];
    #pragma unroll
    for (int j = 0; j < 4; j++) {
        h[j] = __float2bfloat16(xv[j]);
        l[j] = __float2bfloat16(xv[j] - __bfloat162float(h[j]));
    }
    *(uint64_t*)(Yhi + i4) = *(uint64_t*)h;
    *(uint64_t*)(Ylo + i4) = *(uint64_t*)l;
}

// W [K,N] fp32 -> hi/lo planes [N,K] (transposed)
__global__ __launch_bounds__(256) void w_split2(
    const float* __restrict__ W, __nv_bfloat16* __restrict__ Yhi,
    __nv_bfloat16* __restrict__ Ylo, int K, int N)
{
    __shared__ float t[32][33];
    int k0 = blockIdx.y * 32, n0 = blockIdx.x * 32;
    int tid = threadIdx.x;
    #pragma unroll
    for (int p = 0; p < 4; p++) {
        int idx = p * 256 + tid;
        int kk = idx >> 5, nn = idx & 31;
        t[kk][nn] = W[(size_t)(k0 + kk) * N + n0 + nn];
    }
    __syncthreads();
    #pragma unroll
    for (int p = 0; p < 4; p++) {
        int idx = p * 256 + tid;
        int nn = idx >> 5, kk = idx & 31;
        float x = t[kk][nn];
        __nv_bfloat16 hi = __float2bfloat16(x);
        __nv_bfloat16 lo = __float2bfloat16(x - __bfloat162float(hi));
        size_t o = (size_t)(n0 + nn) * K + (k0 + kk);
        Yhi[o] = hi;
        Ylo[o] = lo;
    }
}

// ---------------------------------------------------------------------------
// Dense HMMA GEMM, hi/lo-plane operands.
// R17: 128 threads, 4 warps in 2x2, 64x64 warp tiles (A-duplication 4x -> 2x;
// smem traffic/chunk 128KB -> 96KB). 256-reg budget at 128thr x occ2.
// mode: 0 +bias, 1 +bias+gelu, 2 +bias+R, 3 +bias+R & drop-sos write,
//       4 raw partial -> C + z*M*N (no bias).
// ---------------------------------------------------------------------------
constexpr int T2_PITCH = 80;
constexpr int T2_PLANE = 128 * T2_PITCH;          // 10240
constexpr int T2_STG   = 4 * T2_PLANE;            // 40960
constexpr int T2_SMEM  = 2 * T2_STG + 128;

__global__ __launch_bounds__(128, 2) void tgemm2(
    const __nv_bfloat16* __restrict__ Ahi, const __nv_bfloat16* __restrict__ Alo,
    const __nv_bfloat16* __restrict__ Bhi, const __nv_bfloat16* __restrict__ Blo,
    const float* __restrict__ bias, const float* __restrict__ R,
    float* __restrict__ C, int M, int N, int K, int mode)
{
    extern __shared__ char dynraw[];
    char* sb = (char*)(((uintptr_t)dynraw + 127) & ~(uintptr_t)127);
    const uint32_t s0 = smem_u32(sb);

    const int tid  = threadIdx.x;
    const int wid  = tid >> 5;
    const int lane = tid & 31;
    const int g    = lane >> 2;
    const int tg   = lane & 3;
    const int wm   = wid >> 1;          // 0..1 (64 rows each)
    const int wn   = wid & 1;           // 0..1 (64 cols each)
    const int row0 = blockIdx.y * 128;
    const int col0 = blockIdx.x * 128;
    const int zsec = K / gridDim.z;
    const int kbase = blockIdx.z * zsec;
    const int nch  = zsec >> 5;

    const __nv_bfloat16* baseAhi = Ahi + (size_t)row0 * K + kbase;
    const __nv_bfloat16* baseAlo = Alo + (size_t)row0 * K + kbase;
    const __nv_bfloat16* baseBhi = Bhi + (size_t)col0 * K + kbase;
    const __nv_bfloat16* baseBlo = Blo + (size_t)col0 * K + kbase;

    // ldmatrix lane maps (pitch 80: conflict-free per 8-lane phase)
    const uint32_t aoff = (uint32_t)((wm * 64 + (lane & 15)) * T2_PITCH + (lane >> 4) * 16);
    const uint32_t boff = (uint32_t)((wn * 64 + (lane & 7) + ((lane >> 4) & 1) * 8) * T2_PITCH
                                     + ((lane >> 3) & 1) * 16);

    float c[4][8][4];
    #pragma unroll
    for (int mi = 0; mi < 4; mi++)
        #pragma unroll
        for (int ni = 0; ni < 8; ni++)
            #pragma unroll
            for (int e = 0; e < 4; e++) c[mi][ni][e] = 0.f;

    auto load_chunk = [&](int ch, uint32_t st) {
        int k0 = ch * 32;
        #pragma unroll
        for (int q = 0; q < 4; q++) {
            int idx = q * 128 + tid;                  // 0..511
            int row = idx >> 2;
            int seg = (idx & 3) * 8;                  // elem offset
            uint32_t so = (uint32_t)(row * T2_PITCH + seg * 2);
            size_t go = (size_t)row * K + seg + k0;
            cp16(st + so,                baseAhi + go);
            cp16(st + T2_PLANE + so,     baseAlo + go);
            cp16(st + 2 * T2_PLANE + so, baseBhi + go);
            cp16(st + 3 * T2_PLANE + so, baseBlo + go);
        }
        asm volatile("cp.async.commit_group;" ::: "memory");
    };

    load_chunk(0, s0);

    for (int i = 0; i < nch; i++) {
        const int st = i & 1;
        if (i + 1 < nch) {
            load_chunk(i + 1, s0 + ((i + 1) & 1) * T2_STG);
            asm volatile("cp.async.wait_group 1;" ::: "memory");
        } else {
            asm volatile("cp.async.wait_group 0;" ::: "memory");
        }
        __syncthreads();

        const uint32_t base = s0 + st * T2_STG;
        #pragma unroll
        for (int kg = 0; kg < 2; kg++) {
            const uint32_t ko = kg * 32;
            uint32_t bhi[8][2], blo[8][2], ahi[4][4], alo[4][4];
            #pragma unroll
            for (int nj = 0; nj < 4; nj++)
                ldsm_x4(bhi[2 * nj][0], bhi[2 * nj][1], bhi[2 * nj + 1][0], bhi[2 * nj + 1][1],
                        base + 2 * T2_PLANE + boff + (uint32_t)(nj * 16 * T2_PITCH) + ko);
            #pragma unroll
            for (int mi = 0; mi < 4; mi++)
                ldsm_x4(ahi[mi][0], ahi[mi][1], ahi[mi][2], ahi[mi][3],
                        base + aoff + (uint32_t)(mi * 16 * T2_PITCH) + ko);
            #pragma unroll
            for (int mi = 0; mi < 4; mi++)
                #pragma unroll
                for (int ni = 0; ni < 8; ni++)
                    mma16816(c[mi][ni], ahi[mi], bhi[ni]);
            #pragma unroll
            for (int nj = 0; nj < 4; nj++)
                ldsm_x4(blo[2 * nj][0], blo[2 * nj][1], blo[2 * nj + 1][0], blo[2 * nj + 1][1],
                        base + 3 * T2_PLANE + boff + (uint32_t)(nj * 16 * T2_PITCH) + ko);
            #pragma unroll
            for (int mi = 0; mi < 4; mi++)
                #pragma unroll
                for (int ni = 0; ni < 8; ni++)
                    mma16816(c[mi][ni], ahi[mi], blo[ni]);
            #pragma unroll
            for (int mi = 0; mi < 4; mi++)
                ldsm_x4(alo[mi][0], alo[mi][1], alo[mi][2], alo[mi][3],
                        base + T2_PLANE + aoff + (uint32_t)(mi * 16 * T2_PITCH) + ko);
            #pragma unroll
            for (int mi = 0; mi < 4; mi++)
                #pragma unroll
                for (int ni = 0; ni < 8; ni++)
                    mma16816(c[mi][ni], alo[mi], bhi[ni]);
        }
        __syncthreads();
    }

    #pragma unroll
    for (int mi = 0; mi < 4; mi++) {
        #pragma unroll
        for (int half = 0; half < 2; half++) {
            int rg = row0 + wm * 64 + mi * 16 + g + half * 8;
            if (rg >= M) continue;
            if (mode == 4) {
                float* crow4 = C + (size_t)blockIdx.z * M * N + (size_t)rg * N;
                #pragma unroll
                for (int ni = 0; ni < 8; ni++) {
                    int cg = col0 + wn * 64 + ni * 8 + 2 * tg;
                    *(float2*)(crow4 + cg) =
                        make_float2(c[mi][ni][half * 2 + 0], c[mi][ni][half * 2 + 1]);
                }
                continue;
            }
            float* crow2;
            if (mode == 3) {
                int t = rg % cND;
                if (t == 0) continue;
                crow2 = C + ((size_t)((rg / cND) * cS + (t - 1))) * N;
            } else {
                crow2 = C + (size_t)rg * N;
            }
            #pragma unroll
            for (int ni = 0; ni < 8; ni++) {
                int cg = col0 + wn * 64 + ni * 8 + 2 * tg;
                float v0 = c[mi][ni][half * 2 + 0] + __ldg(&bias[cg]);
                float v1 = c[mi][ni][half * 2 + 1] + __ldg(&bias[cg + 1]);
                if (mode == 1) { v0 = gelu_new(v0); v1 = gelu_new(v1); }
                else if (mode >= 2) {
                    v0 += R[(size_t)rg * N + cg];
                    v1 += R[(size_t)rg * N + cg + 1];
                }
                *(float2*)(crow2 + cg) = make_float2(v0, v1);
            }
        }
    }
}

// ---------------------------------------------------------------------------
// combine: C = sum_s P[s] + bias (+R / sos-drop).  float4 vectorized.
// mode: 0 bias only, 2 +R, 3 +R & drop sos row.
// ---------------------------------------------------------------------------
__global__ __launch_bounds__(256) void combine(
    const float* __restrict__ P, const float* __restrict__ bias,
    const float* __restrict__ R, float* __restrict__ C,
    int M, int N, int nsplit, int mode)
{
    int i4 = (blockIdx.x * 256 + threadIdx.x) * 4;
    if (i4 >= M * N) return;
    int r = i4 / N, cc = i4 % N;
    float4 v = *(const float4*)(P + i4);
    for (int s = 1; s < nsplit; s++) {
        float4 u = *(const float4*)(P + (size_t)s * M * N + i4);
        v.x += u.x; v.y += u.y; v.z += u.z; v.w += u.w;
    }
    float4 bb = *(const float4*)(bias + cc);
    v.x += bb.x; v.y += bb.y; v.z += bb.z; v.w += bb.w;
    if (mode >= 2) {
        float4 rr = *(const float4*)(R + i4);
        v.x += rr.x; v.y += rr.y; v.z += rr.z; v.w += rr.w;
    }
    if (mode == 3) {
        int t = r % cND;
        if (t == 0) return;
        *(float4*)(C + ((size_t)((r / cND) * cS + (t - 1))) * N + cc) = v;
    } else {
        *(float4*)(C + i4) = v;
    }
}

// combine 2 partials + bias -> gelu -> hi/lo plane write (for fc)
__global__ __launch_bounds__(256) void combine_gelu_split(
    const float* __restrict__ P, const float* __restrict__ bias,
    __nv_bfloat16* __restrict__ Yhi, __nv_bfloat16* __restrict__ Ylo,
    int M, int N)
{
    int i4 = (blockIdx.x * 256 + threadIdx.x) * 4;
    if (i4 >= M * N) return;
    int cc = i4 % N;
    float4 v = *(const float4*)(P + i4);
    float4 u = *(const float4*)(P + (size_t)M * N + i4);
    float4 bb = *(const float4*)(bias + cc);
    float xv[4] = {gelu_new(v.x + u.x + bb.x), gelu_new(v.y + u.y + bb.y),
                   gelu_new(v.z + u.z + bb.z), gelu_new(v.w + u.w + bb.w)};
    __nv_bfloat16 h[4], l[4];
    #pragma unroll
    for (int j = 0; j < 4; j++) {
        h[j] = __float2bfloat16(xv[j]);
        l[j] = __float2bfloat16(xv[j] - __bfloat162float(h[j]));
    }
    *(uint64_t*)(Yhi + i4) = *(uint64_t*)h;
    *(uint64_t*)(Ylo + i4) = *(uint64_t*)l;
}

// combine 2 partials + bias + residual H -> H2, then LN -> hi/lo planes
__global__ __launch_bounds__(256) void combine_ln(
    const float* __restrict__ P, const float* __restrict__ bias,
    const float* __restrict__ Hres, float* __restrict__ H2,
    const float* __restrict__ gamma, const float* __restrict__ beta,
    __nv_bfloat16* __restrict__ Yhi, __nv_bfloat16* __restrict__ Ylo)
{
    int r   = blockIdx.x;
    int tid = threadIdx.x;
    const float* p0 = P + (size_t)r * cD;
    const float* p1 = P + (size_t)cM * cD + (size_t)r * cD;
    const float* hr = Hres + (size_t)r * cD;
    float v[3];
    #pragma unroll
    for (int j = 0; j < 3; j++) {
        int cc = tid + j * 256;
        v[j] = p0[cc] + p1[cc] + bias[cc] + hr[cc];
    }
    float* h2r = H2 + (size_t)r * cD;
    h2r[tid] = v[0]; h2r[tid + 256] = v[1]; h2r[tid + 512] = v[2];

    float s = v[0] + v[1] + v[2];
    float ss = v[0] * v[0] + v[1] * v[1] + v[2] * v[2];
    __shared__ float sb[8], sb2[8];
    #pragma unroll
    for (int o = 16; o; o >>= 1) {
        s  += __shfl_xor_sync(0xffffffffu, s,  o);
        ss += __shfl_xor_sync(0xffffffffu, ss, o);
    }
    int lane = tid & 31, w = tid >> 5;
    if (lane == 0) { sb[w] = s; sb2[w] = ss; }
    __syncthreads();
    if (tid == 0) {
        float a = 0.f, c2 = 0.f;
        #pragma unroll
        for (int i = 0; i < 8; i++) { a += sb[i]; c2 += sb2[i]; }
        sb[0] = a; sb2[0] = c2;
    }
    __syncthreads();
    float mean = sb[0] * (1.0f / 768.0f);
    float var  = sb2[0] * (1.0f / 768.0f) - mean * mean;
    float inv  = rsqrtf(var + 1e-5f);

    #pragma unroll
    for (int j = 0; j < 3; j++) {
        int cc = tid + j * 256;
        float y = (v[j] - mean) * inv * gamma[cc] + beta[cc];
        __nv_bfloat16 hi = __float2bfloat16(y);
        __nv_bfloat16 lo = __float2bfloat16(y - __bfloat162float(hi));
        Yhi[(size_t)r * cD + cc] = hi;
        Ylo[(size_t)r * cD + cc] = lo;
    }
}

// ---------------------------------------------------------------------------
// scores_mma (3-slot interleaved operands); fully-masked tiles are no-ops.
// ---------------------------------------------------------------------------
constexpr int TG_PITCH = 144;
constexpr int TG_STG   = 128 * TG_PITCH;      // 18432
constexpr int TG_SMEM  = 4 * TG_STG + 128;

__global__ __launch_bounds__(256, 2) void scores_mma(
    const __nv_bfloat16* __restrict__ Qs, const __nv_bfloat16* __restrict__ Ks,
    float* __restrict__ S)
{
    extern __shared__ char dynraw[];
    char* sb = (char*)(((uintptr_t)dynraw + 127) & ~(uintptr_t)127);
    const uint32_t sA0 = smem_u32(sb);
    const uint32_t sB0 = sA0 + 2 * TG_STG;

    const int tid  = threadIdx.x;
    const int wid  = tid >> 5;
    const int lane = tid & 31;
    const int g    = lane >> 2;
    const int tg   = lane & 3;
    const int wm   = wid >> 2;
    const int wn   = wid & 3;
    const int bh   = blockIdx.z;
    const int row0 = blockIdx.y * 128;
    const int col0 = blockIdx.x * 128;

    if (col0 >= row0 + 128 + cSC) return;   // never read downstream

    float* Sb = S + (size_t)bh * NDP * NSP;
    const __nv_bfloat16* A3 = Qs + (size_t)bh * NDP * K3Q;
    const __nv_bfloat16* B3 = Ks + (size_t)bh * NSP * K3Q;

    uint32_t soff[4];
    const __nv_bfloat16 *Ag[4], *Bg[4];
    #pragma unroll
    for (int p = 0; p < 4; p++) {
        int idx = p * 256 + tid;
        int row = idx >> 3, seg = idx & 7;
        soff[p] = (uint32_t)(row * TG_PITCH + seg * 16);
        Ag[p] = A3 + (size_t)(row0 + row) * K3Q + seg * 8;
        Bg[p] = B3 + (size_t)(col0 + row) * K3Q + seg * 8;
    }
    const uint32_t aoff = (uint32_t)((wm * 64 + (lane & 15)) * TG_PITCH + (lane >> 4) * 16);
    const uint32_t boff = (uint32_t)((wn * 32 + (lane & 7)) * TG_PITCH + ((lane >> 3) & 1) * 16);

    float c[4][4][4];
    #pragma unroll
    for (int mi = 0; mi < 4; mi++)
        #pragma unroll
        for (int ni = 0; ni < 4; ni++)
            #pragma unroll
            for (int e = 0; e < 4; e++) c[mi][ni][e] = 0.f;

    #pragma unroll
    for (int p = 0; p < 4; p++) {
        cp16(sA0 + soff[p], Ag[p]);
        cp16(sB0 + soff[p], Bg[p]);
    }
    asm volatile("cp.async.commit_group;" ::: "memory");

    #pragma unroll
    for (int i = 0; i < 3; i++) {
        const int st = i & 1;
        if (i + 1 < 3) {
            const int st2 = (i + 1) & 1;
            const int ko = (i + 1) * 64;
            #pragma unroll
            for (int p = 0; p < 4; p++) {
                cp16(sA0 + st2 * TG_STG + soff[p], Ag[p] + ko);
                cp16(sB0 + st2 * TG_STG + soff[p], Bg[p] + ko);
            }
            asm volatile("cp.async.commit_group;" ::: "memory");
            asm volatile("cp.async.wait_group 1;" ::: "memory");
        } else {
            asm volatile("cp.async.wait_group 0;" ::: "memory");
        }
        __syncthreads();
        const uint32_t sa = sA0 + st * TG_STG + aoff;
        const uint32_t sbb = sB0 + st * TG_STG + boff;
        #pragma unroll
        for (int ks = 0; ks < 4; ks++) {
            uint32_t a[4][4], b[4][2];
            #pragma unroll
            for (int mi = 0; mi < 4; mi++)
                ldsm_x4(a[mi][0], a[mi][1], a[mi][2], a[mi][3],
                        sa + (uint32_t)(mi * 16 * TG_PITCH + ks * 32));
            #pragma unroll
            for (int ni = 0; ni < 4; ni++)
                ldsm_x2(b[ni][0], b[ni][1],
                        sbb + (uint32_t)(ni * 8 * TG_PITCH + ks * 32));
            #pragma unroll
            for (int mi = 0; mi < 4; mi++)
                #pragma unroll
                for (int ni = 0; ni < 4; ni++)
                    mma16816(c[mi][ni], a[mi], b[ni]);
        }
        __syncthreads();
    }

    const float scale = 0.125f;   // 1/sqrt(64)
    #pragma unroll
    for (int mi = 0; mi < 4; mi++) {
        #pragma unroll
        for (int half = 0; half < 2; half++) {
            int rg = row0 + wm * 64 + mi * 16 + g + half * 8;
            float* Sr = Sb + (size_t)rg * NSP;
            #pragma unroll
            for (int ni = 0; ni < 4; ni++) {
                int cg = col0 + wn * 32 + ni * 8 + 2 * tg;
                float v0 = (cg     <= rg + cSC) ? c[mi][ni][half * 2 + 0] * scale : -10000.0f;
                float v1 = (cg + 1 <= rg + cSC) ? c[mi][ni][half * 2 + 1] * scale : -10000.0f;
                *(float2*)(Sr + cg) = make_float2(v0, v1);
            }
        }
    }
}

// ---------------------------------------------------------------------------
// av_mma2: hi/lo-plane AV with causal K truncation (unchanged from R16).
// ---------------------------------------------------------------------------
constexpr int AV2_APL  = 128 * T2_PITCH;          // 10240
constexpr int AV2_BPL  = 64 * T2_PITCH;           // 5120
constexpr int AV2_STG  = 2 * AV2_APL + 2 * AV2_BPL;   // 30720
constexpr int AV2_SMEM = 2 * AV2_STG + 128;           // 61568

__global__ __launch_bounds__(256, 2) void av_mma2(
    const __nv_bfloat16* __restrict__ P2, const __nv_bfloat16* __restrict__ V2,
    __nv_bfloat16* __restrict__ Ahi, __nv_bfloat16* __restrict__ Alo)
{
    extern __shared__ char dynraw[];
    char* sb = (char*)(((uintptr_t)dynraw + 127) & ~(uintptr_t)127);
    const uint32_t s0 = smem_u32(sb);

    const int tid  = threadIdx.x;
    const int wid  = tid >> 5;
    const int lane = tid & 31;
    const int g    = lane >> 2;
    const int tg   = lane & 3;
    const int wm   = wid >> 1;
    const int wn   = wid & 1;
    const int bh   = blockIdx.y;
    const int row0 = blockIdx.x * 128;

    const __nv_bfloat16* Phi = P2 + (size_t)bh * NDP * NSP;
    const __nv_bfloat16* Plo = Phi + PS_PLANE;
    const __nv_bfloat16* Vhi = V2 + (size_t)bh * cDH * NSP;
    const __nv_bfloat16* Vlo = Vhi + VT_PLANE;

    const int arow = tid >> 1;
    const int aseg2 = (tid & 1) * 2;
    const int brow = tid >> 2;
    const int bseg = tid & 3;

    const __nv_bfloat16* PAhi = Phi + (size_t)(row0 + arow) * NSP + aseg2 * 8;
    const __nv_bfloat16* PAlo = Plo + (size_t)(row0 + arow) * NSP + aseg2 * 8;
    const __nv_bfloat16* PBhi = Vhi + (size_t)brow * NSP + bseg * 8;
    const __nv_bfloat16* PBlo = Vlo + (size_t)brow * NSP + bseg * 8;
    const uint32_t soa = (uint32_t)(arow * T2_PITCH + aseg2 * 16);
    const uint32_t sob = (uint32_t)(brow * T2_PITCH + bseg * 16);

    const uint32_t aoff = (uint32_t)((wm * 32 + (lane & 15)) * T2_PITCH + (lane >> 4) * 16);
    const uint32_t boff = (uint32_t)((wn * 32 + (lane & 7)) * T2_PITCH + ((lane >> 3) & 1) * 16);

    float c[2][4][4];
    #pragma unroll
    for (int mi = 0; mi < 2; mi++)
        #pragma unroll
        for (int ni = 0; ni < 4; ni++)
            #pragma unroll
            for (int e = 0; e < 4; e++) c[mi][ni][e] = 0.f;

    const int nch_full = NSP >> 5;               // 44
    int nch = blockIdx.x * 4 + 12;
    if (nch > nch_full) nch = nch_full;

    auto load_chunk = [&](int ch, uint32_t st) {
        int k0 = ch * 32;
        cp16(st + soa,                   PAhi + k0);
        cp16(st + soa + 16,              PAhi + k0 + 8);
        cp16(st + AV2_APL + soa,         PAlo + k0);
        cp16(st + AV2_APL + soa + 16,    PAlo + k0 + 8);
        cp16(st + 2 * AV2_APL + sob,            PBhi + k0);
        cp16(st + 2 * AV2_APL + AV2_BPL + sob,  PBlo + k0);
        asm volatile("cp.async.commit_group;" ::: "memory");
    };

    load_chunk(0, s0);

    for (int i = 0; i < nch; i++) {
        const int st = i & 1;
        if (i + 1 < nch) {
            load_chunk(i + 1, s0 + ((i + 1) & 1) * AV2_STG);
            asm volatile("cp.async.wait_group 1;" ::: "memory");
        } else {
            asm volatile("cp.async.wait_group 0;" ::: "memory");
        }
        __syncthreads();

        const uint32_t base = s0 + st * AV2_STG;
        #pragma unroll
        for (int kg = 0; kg < 2; kg++) {
            const uint32_t ko = kg * 32;
            uint32_t bhi[4][2], blo[4][2], ahi[2][4], alo[2][4];
            #pragma unroll
            for (int ni = 0; ni < 4; ni++)
                ldsm_x2(bhi[ni][0], bhi[ni][1],
                        base + 2 * AV2_APL + boff + (uint32_t)(ni * 8 * T2_PITCH) + ko);
            #pragma unroll
            for (int mi = 0; mi < 2; mi++)
                ldsm_x4(ahi[mi][0], ahi[mi][1], ahi[mi][2], ahi[mi][3],
                        base + aoff + (uint32_t)(mi * 16 * T2_PITCH) + ko);
            #pragma unroll
            for (int mi = 0; mi < 2; mi++)
                #pragma unroll
                for (int ni = 0; ni < 4; ni++)
                    mma16816(c[mi][ni], ahi[mi], bhi[ni]);
            #pragma unroll
            for (int ni = 0; ni < 4; ni++)
                ldsm_x2(blo[ni][0], blo[ni][1],
                        base + 2 * AV2_APL + AV2_BPL + boff + (uint32_t)(ni * 8 * T2_PITCH) + ko);
            #pragma unroll
            for (int mi = 0; mi < 2; mi++)
                #pragma unroll
                for (int ni = 0; ni < 4; ni++)
                    mma16816(c[mi][ni], ahi[mi], blo[ni]);
            #pragma unroll
            for (int mi = 0; mi < 2; mi++)
                ldsm_x4(alo[mi][0], alo[mi][1], alo[mi][2], alo[mi][3],
                        base + AV2_APL + aoff + (uint32_t)(mi * 16 * T2_PITCH) + ko);
            #pragma unroll
            for (int mi = 0; mi < 2; mi++)
                #pragma unroll
                for (int ni = 0; ni < 4; ni++)
                    mma16816(c[mi][ni], alo[mi], bhi[ni]);
        }
        __syncthreads();
    }

    const int b_ = bh / cH, h = bh % cH;
    #pragma unroll
    for (int mi = 0; mi < 2; mi++) {
        #pragma unroll
        for (int half = 0; half < 2; half++) {
            int rg = row0 + wm * 32 + mi * 16 + g + half * 8;
            if (rg >= cND) continue;
            size_t rowoff = ((size_t)(b_ * cND + rg)) * cD + h * cDH;
            #pragma unroll
            for (int ni = 0; ni < 4; ni++) {
                int cg = wn * 32 + ni * 8 + 2 * tg;
                float v0 = c[mi][ni][half * 2 + 0];
                float v1 = c[mi][ni][half * 2 + 1];
                __nv_bfloat16 h0 = __float2bfloat16(v0);
                __nv_bfloat16 h1 = __float2bfloat16(v1);
                float l0 = v0 - __bfloat162float(h0);
                float l1 = v1 - __bfloat162float(h1);
                *(uint32_t*)(Ahi + rowoff + cg) = pack_bf16x2(v0, v1);
                *(uint32_t*)(Alo + rowoff + cg) = pack_bf16x2(l0, l1);
            }
        }
    }
}

// ---------------------------------------------------------------------------
// LayerNorm fused with sos-concat gather; writes H + hi/lo plane output.
// ---------------------------------------------------------------------------
__global__ __launch_bounds__(256) void ln_kernel(
    const float* __restrict__ in, const float* __restrict__ sos,
    const float* __restrict__ gamma, const float* __restrict__ beta,
    float* __restrict__ Hout, __nv_bfloat16* __restrict__ Yhi,
    __nv_bfloat16* __restrict__ Ylo)
{
    int r   = blockIdx.x;
    int tid = threadIdx.x;
    int b = r / cND, t = r % cND;
    const float* src = (t == 0) ? sos : in + ((size_t)b * cS + (t - 1)) * cD;

    float v0 = src[tid], v1 = src[tid + 256], v2 = src[tid + 512];
    float s  = v0 + v1 + v2;
    float ss = v0 * v0 + v1 * v1 + v2 * v2;

    __shared__ float sb[8], sb2[8];
    #pragma unroll
    for (int o = 16; o; o >>= 1) {
        s  += __shfl_xor_sync(0xffffffffu, s,  o);
        ss += __shfl_xor_sync(0xffffffffu, ss, o);
    }
    int lane = tid & 31, w = tid >> 5;
    if (lane == 0) { sb[w] = s; sb2[w] = ss; }
    __syncthreads();
    if (tid == 0) {
        float a = 0.f, c = 0.f;
        #pragma unroll
        for (int i = 0; i < 8; i++) { a += sb[i]; c += sb2[i]; }
        sb[0] = a; sb2[0] = c;
    }
    __syncthreads();
    float mean = sb[0] * (1.0f / 768.0f);
    float var  = sb2[0] * (1.0f / 768.0f) - mean * mean;
    float inv  = rsqrtf(var + 1e-5f);

    float* hr = Hout + (size_t)r * cD;
    hr[tid] = v0; hr[tid + 256] = v1; hr[tid + 512] = v2;

    float vv[3] = {v0, v1, v2};
    #pragma unroll
    for (int j = 0; j < 3; j++) {
        int cc = tid + j * 256;
        float y = (vv[j] - mean) * inv * gamma[cc] + beta[cc];
        __nv_bfloat16 hi = __float2bfloat16(y);
        __nv_bfloat16 lo = __float2bfloat16(y - __bfloat162float(hi));
        Yhi[(size_t)r * cD + cc] = hi;
        Ylo[(size_t)r * cD + cc] = lo;
    }
}

// ---------------------------------------------------------------------------
// Gathers: Q/K 3-slot interleaved (scores), Vt hi/lo planes (AV)
// ---------------------------------------------------------------------------
__global__ void gather_q_split(const float* __restrict__ QKV, __nv_bfloat16* __restrict__ Qs)
{
    int idx = blockIdx.x * blockDim.x + threadIdx.x;
    if (idx >= cBH * cND * cDH) return;
    int d    = idx & (cDH - 1);
    int rest = idx >> 6;
    int t    = rest % cND;
    int bh   = rest / cND;
    int b = bh / cH, h = bh % cH;
    float x = QKV[((size_t)(b * cND + t)) * (3 * cD) + h * cDH + d];
    __nv_bfloat16 hi = __float2bfloat16(x);
    __nv_bfloat16 lo = __float2bfloat16(x - __bfloat162float(hi));
    size_t o = ((size_t)bh * NDP + t) * K3Q + 3 * d;
    Qs[o] = hi; Qs[o + 1] = lo; Qs[o + 2] = hi;
}

__global__ void gather_k_split(const float* __restrict__ QKV, const float* __restrict__ CKV,
                               __nv_bfloat16* __restrict__ Ks)
{
    int idx = blockIdx.x * blockDim.x + threadIdx.x;
    if (idx >= cBH * cNS * cDH) return;
    int d    = idx & (cDH - 1);
    int rest = idx >> 6;
    int j    = rest % cNS;
    int bh   = rest / cNS;
    int b = bh / cH, h = bh % cH;
    float kv;
    if (j < cSC)
        kv = CKV[((size_t)(b * cSC + j)) * (2 * cD) + h * cDH + d];
    else
        kv = QKV[((size_t)(b * cND + (j - cSC))) * (3 * cD) + cD + h * cDH + d];
    __nv_bfloat16 hi = __float2bfloat16(kv);
    __nv_bfloat16 lo = __float2bfloat16(kv - __bfloat162float(hi));
    size_t o = ((size_t)bh * NSP + j) * K3Q + 3 * d;
    Ks[o] = hi; Ks[o + 1] = hi; Ks[o + 2] = lo;
}

__global__ void gather_vt_split2(const float* __restrict__ QKV, const float* __restrict__ CKV,
                                 __nv_bfloat16* __restrict__ Vt)
{
    int idx = blockIdx.x * blockDim.x + threadIdx.x;
    if (idx >= cBH * cDH * cNS) return;
    int j    = idx % cNS;
    int rest = idx / cNS;
    int d    = rest & (cDH - 1);
    int bh   = rest >> 6;
    int b = bh / cH, h = bh % cH;
    float vv;
    if (j < cSC)
        vv = CKV[((size_t)(b * cSC + j)) * (2 * cD) + cD + h * cDH + d];
    else
        vv = QKV[((size_t)(b * cND + (j - cSC))) * (3 * cD) + 2 * cD + h * cDH + d];
    __nv_bfloat16 hi = __float2bfloat16(vv);
    __nv_bfloat16 lo = __float2bfloat16(vv - __bfloat162float(hi));
    size_t o = ((size_t)bh * cDH + d) * NSP + j;
    Vt[o] = hi;
    Vt[o + VT_PLANE] = lo;
}

// ---------------------------------------------------------------------------
// Softmax truncated to L = m + Sc + 1; writes hi/lo planes over [0, L).
// ---------------------------------------------------------------------------
__global__ __launch_bounds__(256) void softmax_split2(
    const float* __restrict__ S, __nv_bfloat16* __restrict__ P2)
{
    int r  = blockIdx.x;
    int bh = r / cND, m = r % cND;
    const int L = m + cSC + 1;
    const float* p = S + ((size_t)bh * NDP + m) * NSP;
    __nv_bfloat16* ohi = P2 + ((size_t)bh * NDP + m) * NSP;
    __nv_bfloat16* olo = ohi + PS_PLANE;
    int tid = threadIdx.x;

    float vals[6];
    float mx = -3.4e38f;
    #pragma unroll
    for (int it = 0; it < 6; it++) {
        int i = tid + it * 256;
        float v = (i < L) ? p[i] : -3.4e38f;
        vals[it] = v;
        mx = fmaxf(mx, v);
    }
    __shared__ float sb[8];
    #pragma unroll
    for (int o = 16; o; o >>= 1) mx = fmaxf(mx, __shfl_xor_sync(0xffffffffu, mx, o));
    if ((tid & 31) == 0) sb[tid >> 5] = mx;
    __syncthreads();
    if (tid < 32) {
        float m2 = (tid < 8) ? sb[tid] : -3.4e38f;
        #pragma unroll
        for (int o = 4; o; o >>= 1) m2 = fmaxf(m2, __shfl_xor_sync(0xffffffffu, m2, o));
        if (tid == 0) sb[0] = m2;
    }
    __syncthreads();
    float bmax = sb[0];
    __syncthreads();

    float s = 0.f;
    #pragma unroll
    for (int it = 0; it < 6; it++) {
        int i = tid + it * 256;
        if (i < L) {
            float e = __expf(vals[it] - bmax);
            vals[it] = e;
            s += e;
        }
    }
    #pragma unroll
    for (int o = 16; o; o >>= 1) s += __shfl_xor_sync(0xffffffffu, s, o);
    if ((tid & 31) == 0) sb[tid >> 5] = s;
    __syncthreads();
    if (tid < 32) {
        float s2 = (tid < 8) ? sb[tid] : 0.f;
        #pragma unroll
        for (int o = 4; o; o >>= 1) s2 += __shfl_xor_sync(0xffffffffu, s2, o);
        if (tid == 0) sb[0] = s2;
    }
    __syncthreads();
    float inv = 1.0f / sb[0];
    #pragma unroll
    for (int it = 0; it < 6; it++) {
        int i = tid + it * 256;
        if (i >= L) continue;
        float v = vals[it] * inv;
        __nv_bfloat16 hi = __float2bfloat16(v);
        __nv_bfloat16 lo = __float2bfloat16(v - __bfloat162float(hi));
        ohi[i] = hi;
        olo[i] = lo;
    }
}

// ---------------------------------------------------------------------------
// Launch sequence
// ---------------------------------------------------------------------------
extern "C" void kernel_launch(void* const* d_in, const int* in_sizes, int n_in,
                              void* d_out, int out_size)
{
    (void)in_sizes; (void)n_in; (void)out_size;
    const float* x       = (const float*)d_in[0];
    const float* ctx     = (const float*)d_in[1];
    const float* sos     = (const float*)d_in[2];
    const float* ln1_g   = (const float*)d_in[3];
    const float* ln1_b   = (const float*)d_in[4];
    const float* W_attn  = (const float*)d_in[5];
    const float* b_attn  = (const float*)d_in[6];
    const float* W_ref   = (const float*)d_in[7];
    const float* b_ref   = (const float*)d_in[8];
    const float* W_proj  = (const float*)d_in[9];
    const float* b_proj  = (const float*)d_in[10];
    const float* ln2_g   = (const float*)d_in[11];
    const float* ln2_b   = (const float*)d_in[12];
    const float* W_fc    = (const float*)d_in[13];
    const float* b_fc    = (const float*)d_in[14];
    const float* W_mproj = (const float*)d_in[15];
    const float* b_mproj = (const float*)d_in[16];
    float* out = (float*)d_out;

    float *H, *QKV, *CKV, *H2, *Sp, *Pp;
    __nv_bfloat16 *As, *Bs, *Qs, *Ks, *Vts, *Ps;
    cudaGetSymbolAddress((void**)&H,   g_H);
    cudaGetSymbolAddress((void**)&QKV, g_QKV);
    cudaGetSymbolAddress((void**)&CKV, g_CKV);
    cudaGetSymbolAddress((void**)&H2,  g_H2);
    cudaGetSymbolAddress((void**)&Sp,  g_Sp);
    cudaGetSymbolAddress((void**)&Pp,  g_Pp);
    cudaGetSymbolAddress((void**)&As,  g_As);
    cudaGetSymbolAddress((void**)&Bs,  g_Bs);
    cudaGetSymbolAddress((void**)&Qs,  g_Qs);
    cudaGetSymbolAddress((void**)&Ks,  g_Ks);
    cudaGetSymbolAddress((void**)&Vts, g_Vts);
    cudaGetSymbolAddress((void**)&Ps,  g_Ps);

    cudaFuncSetAttribute(tgemm2,     cudaFuncAttributeMaxDynamicSharedMemorySize, T2_SMEM);
    cudaFuncSetAttribute(scores_mma, cudaFuncAttributeMaxDynamicSharedMemorySize, TG_SMEM);
    cudaFuncSetAttribute(av_mma2,    cudaFuncAttributeMaxDynamicSharedMemorySize, AV2_SMEM);

    auto Alo_of = [&](int K) { return As + (size_t)cMPAD * K; };

    // 1. concat(sos, x) + LN1 -> H + A-planes (K=768)
    ln_kernel<<<cM, 256>>>(x, sos, ln1_g, ln1_b, H, As, Alo_of(cD));

    // 2. qkv = ln1(h) @ W_attn + b_attn   [2050x2304], split-K x2 (612 CTAs)
    w_split2<<<dim3(3 * cD / 32, cD / 32), 256>>>(W_attn, Bs, Bs + (size_t)3 * cD * cD,
                                                  cD, 3 * cD);
    tgemm2<<<dim3(3 * cD / 128, 17, 2), 128, T2_SMEM>>>(
        As, Alo_of(cD), Bs, Bs + (size_t)3 * cD * cD, b_attn, nullptr, Pp,
        cM, 3 * cD, cD, 4);
    combine<<<(cM * 3 * cD / 4 + 255) / 256, 256>>>(Pp, b_attn, nullptr, QKV,
                                                    cM, 3 * cD, 2, 0);

    // 3. ckv = context @ W_ref + b_ref    [512x1536], split-K x3 (144 CTAs)
    act_split2<<<(cMC * cD / 4 + 255) / 256, 256>>>(ctx, As, Alo_of(cD), cMC * cD);
    w_split2<<<dim3(2 * cD / 32, cD / 32), 256>>>(W_ref, Bs, Bs + (size_t)2 * cD * cD,
                                                  cD, 2 * cD);
    tgemm2<<<dim3(2 * cD / 128, 4, 3), 128, T2_SMEM>>>(
        As, Alo_of(cD), Bs, Bs + (size_t)2 * cD * cD, b_ref, nullptr, Pp,
        cMC, 2 * cD, cD, 4);
    combine<<<(cMC * 2 * cD / 4 + 255) / 256, 256>>>(Pp, b_ref, nullptr, CKV,
                                                     cMC, 2 * cD, 3, 0);

    // 4. gathers for attention
    gather_q_split<<<(cBH * cND * cDH + 255) / 256, 256>>>(QKV, Qs);
    gather_k_split<<<(cBH * cNS * cDH + 255) / 256, 256>>>(QKV, CKV, Ks);
    gather_vt_split2<<<(cBH * cDH * cNS + 255) / 256, 256>>>(QKV, CKV, Vts);

    // 5. attention: scores (masked-tile no-op), truncated softmax, truncated AV
    scores_mma<<<dim3(NSP / 128, NDP / 128, cBH), 256, TG_SMEM>>>(Qs, Ks, Sp);
    softmax_split2<<<cBH * cND, 256>>>(Sp, Ps);
    av_mma2<<<dim3(NDP / 128, cBH), 256, AV2_SMEM>>>(Ps, Vts, As, Alo_of(cD));

    // 6. proj: split-K x2 (204 CTAs, 1 wave) then fused combine+LN2+split
    w_split2<<<dim3(cD / 32, cD / 32), 256>>>(W_proj, Bs, Bs + (size_t)cD * cD,
                                              cD, cD);
    tgemm2<<<dim3(cD / 128, 17, 2), 128, T2_SMEM>>>(
        As, Alo_of(cD), Bs, Bs + (size_t)cD * cD, b_proj, nullptr, Pp,
        cM, cD, cD, 4);
    combine_ln<<<cM, 256>>>(Pp, b_proj, H, H2, ln2_g, ln2_b, As, Alo_of(cD));

    // 7. fc: split-K x2 (816 CTAs) then fused combine+gelu+split (K=3072 planes)
    w_split2<<<dim3(4 * cD / 32, cD / 32), 256>>>(W_fc, Bs, Bs + (size_t)4 * cD * cD,
                                                  cD, 4 * cD);
    tgemm2<<<dim3(4 * cD / 128, 17, 2), 128, T2_SMEM>>>(
        As, Alo_of(cD), Bs, Bs + (size_t)4 * cD * cD, b_fc, nullptr, Pp,
        cM, 4 * cD, cD, 4);
    combine_gelu_split<<<(cM * 4 * cD / 4 + 255) / 256, 256>>>(
        Pp, b_fc, As, Alo_of(4 * cD), cM, 4 * cD);

    // 8. mproj: split-K x2 (204 CTAs, 1 wave, nch 48) + combine with sos-drop
    w_split2<<<dim3(cD / 32, 4 * cD / 32), 256>>>(W_mproj, Bs,
                                                  Bs + (size_t)cD * 4 * cD,
                                                  4 * cD, cD);
    tgemm2<<<dim3(cD / 128, 17, 2), 128, T2_SMEM>>>(
        As, Alo_of(4 * cD), Bs, Bs + (size_t)cD * 4 * cD, b_mproj, nullptr, Pp,
        cM, cD, 4 * cD, 4);
    combine<<<(cM * cD / 4 + 255) / 256, 256>>>(Pp, b_mproj, H2, out, cM, cD, 2, 3);
}